// round 4
// baseline (speedup 1.0000x reference)
#include <cuda_runtime.h>
#include <math.h>
#include <stdint.h>

#define BB 4
#define LL 8192
#define DDIM 256
#define HH 4
#define NLAYER 4
#define FFD 1024
#define WW 512
#define VV 14
#define DH 64
#define BL (BB*LL)     /* 32768 rows */
#define NBLK (LL/WW)   /* 16 windows per sequence */

// ---------------- scratch (static device globals; no allocations) ----------------
__device__ float g_X [BL*DDIM];
__device__ float g_Hb[BL*DDIM];
__device__ float g_Q [BL*DDIM];
__device__ float g_K [BL*DDIM];
__device__ float g_V [BL*DDIM];
__device__ float g_O [BL*DDIM];
__device__ float g_F [BL*FFD];

__device__ __forceinline__ uint32_t f2tf32(float x) {
    uint32_t r;
    asm("cvt.rna.tf32.f32 %0, %1;" : "=r"(r) : "f"(x));
    return r;
}
__device__ __forceinline__ void mma_tf32(float* c, const uint32_t* a, const uint32_t* b) {
    asm volatile(
        "mma.sync.aligned.m16n8k8.row.col.f32.tf32.tf32.f32 "
        "{%0,%1,%2,%3}, {%4,%5,%6,%7}, {%8,%9}, {%0,%1,%2,%3};"
        : "+f"(c[0]), "+f"(c[1]), "+f"(c[2]), "+f"(c[3])
        : "r"(a[0]), "r"(a[1]), "r"(a[2]), "r"(a[3]), "r"(b[0]), "r"(b[1]));
}

// ---------------- embedding gather ----------------
__global__ void embed_kernel(const int* __restrict__ ids, const float* __restrict__ emb,
                             float* __restrict__ x) {
    int i = blockIdx.x * blockDim.x + threadIdx.x;
    int row = i >> 6;
    int d4  = i & 63;
    int id  = ids[row];
    ((float4*)x)[i] = ((const float4*)emb)[id * 64 + d4];
}

// ---------------- LayerNorm ----------------
__global__ void ln_kernel(const float* __restrict__ x, const float* __restrict__ g,
                          const float* __restrict__ b, float* __restrict__ out) {
    int row  = blockIdx.x * 8 + (threadIdx.x >> 5);
    int lane = threadIdx.x & 31;
    const float4* xr = (const float4*)(x + (size_t)row * DDIM);
    float4 v0 = xr[lane];
    float4 v1 = xr[lane + 32];
    float s  = v0.x + v0.y + v0.z + v0.w + v1.x + v1.y + v1.z + v1.w;
    float ss = v0.x*v0.x + v0.y*v0.y + v0.z*v0.z + v0.w*v0.w
             + v1.x*v1.x + v1.y*v1.y + v1.z*v1.z + v1.w*v1.w;
    #pragma unroll
    for (int off = 16; off; off >>= 1) {
        s  += __shfl_xor_sync(0xffffffffu, s,  off);
        ss += __shfl_xor_sync(0xffffffffu, ss, off);
    }
    float mean = s * (1.0f / DDIM);
    float var  = ss * (1.0f / DDIM) - mean * mean;
    float rstd = rsqrtf(var + 1e-5f);
    const float4* gp = (const float4*)g;
    const float4* bp = (const float4*)b;
    float4* op = (float4*)(out + (size_t)row * DDIM);
    float4 g0 = gp[lane], g1 = gp[lane + 32];
    float4 b0 = bp[lane], b1 = bp[lane + 32];
    float4 o0, o1;
    o0.x = (v0.x - mean) * rstd * g0.x + b0.x;
    o0.y = (v0.y - mean) * rstd * g0.y + b0.y;
    o0.z = (v0.z - mean) * rstd * g0.z + b0.z;
    o0.w = (v0.w - mean) * rstd * g0.w + b0.w;
    o1.x = (v1.x - mean) * rstd * g1.x + b1.x;
    o1.y = (v1.y - mean) * rstd * g1.y + b1.y;
    o1.z = (v1.z - mean) * rstd * g1.z + b1.z;
    o1.w = (v1.w - mean) * rstd * g1.w + b1.w;
    op[lane] = o0;
    op[lane + 32] = o1;
}

__device__ __forceinline__ float gelu_tanh(float x) {
    float t = tanhf(0.7978845608028654f * (x + 0.044715f * x * x * x));
    return 0.5f * x * (1.0f + t);
}

// ================= tf32 mma.sync GEMM, double-buffered pipeline =================
// BM=128, BN=128, BK=32; 256 threads = 8 warps (4x2); warp tile 32x64 (2x8 m16n8k8).
#define AS_STRIDE 36
#define BS_STRIDE 136
#define GSM_A (128*AS_STRIDE)          /* u32 per buffer */
#define GSM_B (32*BS_STRIDE)
#define GSM_BYTES ((2*GSM_A + 2*GSM_B) * 4)

template<bool GELU, bool RES>
__global__ void __launch_bounds__(256) gemm_mma(
        const float* __restrict__ A, const float* __restrict__ W,
        const float* __restrict__ bias, const float* __restrict__ Res,
        float* __restrict__ C, int M, int N, int K) {
    extern __shared__ uint32_t smu[];
    uint32_t* Asu[2] = { smu, smu + GSM_A };
    uint32_t* Bsu[2] = { smu + 2*GSM_A, smu + 2*GSM_A + GSM_B };
    int tid = threadIdx.x, lane = tid & 31, wid = tid >> 5;
    int wm = wid & 3, wn = wid >> 2;
    int gid = lane >> 2, tig = lane & 3;
    int m0 = blockIdx.y * 128, n0 = blockIdx.x * 128;

    // per-thread load coordinates
    int amm[4], akq[4], bkk[4], bnq[4];
    #pragma unroll
    for (int i = 0; i < 4; i++) {
        int idx = tid + i * 256;
        amm[i] = idx >> 3; akq[i] = idx & 7;
        bkk[i] = idx >> 5; bnq[i] = idx & 31;
    }

    float acc[2][8][4];
    #pragma unroll
    for (int i = 0; i < 2; i++)
        #pragma unroll
        for (int j = 0; j < 8; j++)
            #pragma unroll
            for (int u = 0; u < 4; u++) acc[i][j][u] = 0.0f;

    float4 ra[4], rb[4];
    // prologue: load chunk 0
    #pragma unroll
    for (int i = 0; i < 4; i++) {
        ra[i] = *(const float4*)&A[(size_t)(m0 + amm[i]) * K + akq[i] * 4];
        rb[i] = *(const float4*)&W[(size_t)bkk[i] * N + n0 + bnq[i] * 4];
    }
    #pragma unroll
    for (int i = 0; i < 4; i++) {
        uint32_t* p = &Asu[0][amm[i] * AS_STRIDE + akq[i] * 4];
        p[0] = f2tf32(ra[i].x); p[1] = f2tf32(ra[i].y);
        p[2] = f2tf32(ra[i].z); p[3] = f2tf32(ra[i].w);
        uint4 t = {f2tf32(rb[i].x), f2tf32(rb[i].y), f2tf32(rb[i].z), f2tf32(rb[i].w)};
        *(uint4*)&Bsu[0][bkk[i] * BS_STRIDE + bnq[i] * 4] = t;
    }
    __syncthreads();

    int nch = K >> 5;
    for (int kc = 0; kc < nch; kc++) {
        bool more = (kc + 1 < nch);
        if (more) {
            int k0 = (kc + 1) << 5;
            #pragma unroll
            for (int i = 0; i < 4; i++) {
                ra[i] = *(const float4*)&A[(size_t)(m0 + amm[i]) * K + k0 + akq[i] * 4];
                rb[i] = *(const float4*)&W[(size_t)(k0 + bkk[i]) * N + n0 + bnq[i] * 4];
            }
        }
        const uint32_t* As = Asu[kc & 1];
        const uint32_t* Bs = Bsu[kc & 1];
        #pragma unroll
        for (int ks = 0; ks < 4; ks++) {
            int kb = ks * 8;
            uint32_t afr[2][4];
            #pragma unroll
            for (int tm = 0; tm < 2; tm++) {
                int row = wm * 32 + tm * 16 + gid;
                afr[tm][0] = As[row * AS_STRIDE + kb + tig];
                afr[tm][1] = As[(row + 8) * AS_STRIDE + kb + tig];
                afr[tm][2] = As[row * AS_STRIDE + kb + tig + 4];
                afr[tm][3] = As[(row + 8) * AS_STRIDE + kb + tig + 4];
            }
            uint32_t bfr[8][2];
            #pragma unroll
            for (int tn = 0; tn < 8; tn++) {
                int col = wn * 64 + tn * 8 + gid;
                bfr[tn][0] = Bs[(kb + tig) * BS_STRIDE + col];
                bfr[tn][1] = Bs[(kb + tig + 4) * BS_STRIDE + col];
            }
            #pragma unroll
            for (int tm = 0; tm < 2; tm++)
                #pragma unroll
                for (int tn = 0; tn < 8; tn++)
                    mma_tf32(acc[tm][tn], afr[tm], bfr[tn]);
        }
        if (more) {
            int nb2 = (kc + 1) & 1;
            #pragma unroll
            for (int i = 0; i < 4; i++) {
                uint32_t* p = &Asu[nb2][amm[i] * AS_STRIDE + akq[i] * 4];
                p[0] = f2tf32(ra[i].x); p[1] = f2tf32(ra[i].y);
                p[2] = f2tf32(ra[i].z); p[3] = f2tf32(ra[i].w);
                uint4 t = {f2tf32(rb[i].x), f2tf32(rb[i].y), f2tf32(rb[i].z), f2tf32(rb[i].w)};
                *(uint4*)&Bsu[nb2][bkk[i] * BS_STRIDE + bnq[i] * 4] = t;
            }
        }
        __syncthreads();
    }

    // epilogue
    #pragma unroll
    for (int tm = 0; tm < 2; tm++) {
        int row = m0 + wm * 32 + tm * 16 + gid;
        #pragma unroll
        for (int tn = 0; tn < 8; tn++) {
            int col = n0 + wn * 64 + tn * 8 + tig * 2;
            float b0 = bias[col], b1 = bias[col + 1];
            #pragma unroll
            for (int half = 0; half < 2; half++) {
                int r = row + half * 8;
                float v0 = acc[tm][tn][half * 2 + 0] + b0;
                float v1 = acc[tm][tn][half * 2 + 1] + b1;
                if (GELU) { v0 = gelu_tanh(v0); v1 = gelu_tanh(v1); }
                size_t off = (size_t)r * N + col;
                if (RES) {
                    float2 rr = *(const float2*)&Res[off];
                    v0 += rr.x; v1 += rr.y;
                }
                float2 o = {v0, v1};
                *(float2*)&C[off] = o;
            }
        }
    }
}

// ---------------- fused attention: QK^T via tf32 MMA, fp32 softmax/PV ----------------
// Block 256 thr / 8 warps. S-phase: warp = (wq4 = w&3 -> 16 q rows, wk2 = w>>2 -> 32 k cols).
// softmax/PV-phase: warp owns queries [8w, 8w+8), lane owns dims (lane, lane+32).
#define QK_ST 68
#define SS_ST 68
#define ATSM_U32 (64*QK_ST*2 + 64*64 + 64*SS_ST)
#define ATSM_BYTES (ATSM_U32 * 4)

__global__ void attn_kernel(const float* __restrict__ Q, const float* __restrict__ K,
                            const float* __restrict__ V, float* __restrict__ O) {
    extern __shared__ uint32_t smu[];
    uint32_t* qsm = smu;                       // [64][68] tf32
    uint32_t* ksm = qsm + 64 * QK_ST;          // [64][68] tf32
    float*    vsm = (float*)(ksm + 64 * QK_ST);// [64][64]
    float*    ssm = vsm + 64 * 64;             // [64][68] scores then P

    int qt   = blockIdx.x;
    int head = blockIdx.y;
    int bn   = blockIdx.z;
    int b    = bn / NBLK;
    int nb   = bn % NBLK;
    int q0   = qt * 64;
    int tid  = threadIdx.x;
    int lane = tid & 31;
    int warp = tid >> 5;
    int wq4 = warp & 3, wk2 = warp >> 2;
    int gid = lane >> 2, tig = lane & 3;

    const float* Qbase = Q + ((size_t)(b * LL + nb * WW + q0)) * DDIM + head * DH;
    #pragma unroll
    for (int i = 0; i < 4; i++) {
        int idx = tid + i * 256;
        int qi = idx >> 4, d4 = idx & 15;
        float4 v = *(const float4*)&Qbase[(size_t)qi * DDIM + d4 * 4];
        uint32_t* p = &qsm[qi * QK_ST + d4 * 4];
        p[0] = f2tf32(v.x); p[1] = f2tf32(v.y);
        p[2] = f2tf32(v.z); p[3] = f2tf32(v.w);
    }

    float m[8], l[8], o0[8], o1[8];
    #pragma unroll
    for (int i = 0; i < 8; i++) { m[i] = -1e30f; l[i] = 0.0f; o0[i] = 0.0f; o1[i] = 0.0f; }

    int lo = q0;
    if (nb == 0) lo = (lo > WW) ? lo : WW;
    int hi = q0 + 63 + WW;
    int cmin = lo >> 6, cmax = hi >> 6;

    float slope = exp2f(-2.0f * (float)(head + 1));
    const float scale = 0.125f;
    int kvbase = b * LL + nb * WW - WW;

    for (int c = cmin; c <= cmax; c++) {
        int kc0 = c * 64;
        __syncthreads();
        // load K (tf32, row-major stride 68) and V (fp32)
        #pragma unroll
        for (int i = 0; i < 4; i++) {
            int idx = tid + i * 256;
            int kk = idx >> 4, d4 = idx & 15;
            size_t gro = ((size_t)(kvbase + kc0 + kk)) * DDIM + head * DH + d4 * 4;
            float4 kv = *(const float4*)&K[gro];
            uint32_t* p = &ksm[kk * QK_ST + d4 * 4];
            p[0] = f2tf32(kv.x); p[1] = f2tf32(kv.y);
            p[2] = f2tf32(kv.z); p[3] = f2tf32(kv.w);
            *(float4*)&vsm[kk * 64 + d4 * 4] = *(const float4*)&V[gro];
        }
        __syncthreads();

        // S = Q @ K^T via MMA: warp computes 16q x 32k
        float cfr[4][4];
        #pragma unroll
        for (int t = 0; t < 4; t++)
            #pragma unroll
            for (int u = 0; u < 4; u++) cfr[t][u] = 0.0f;
        #pragma unroll
        for (int ks = 0; ks < 8; ks++) {
            int kb = ks * 8;
            int r0 = (wq4 * 16 + gid) * QK_ST + kb + tig;
            uint32_t af[4];
            af[0] = qsm[r0];
            af[1] = qsm[r0 + 8 * QK_ST];
            af[2] = qsm[r0 + 4];
            af[3] = qsm[r0 + 8 * QK_ST + 4];
            #pragma unroll
            for (int t = 0; t < 4; t++) {
                int col = wk2 * 32 + t * 8 + gid;
                uint32_t bf[2];
                bf[0] = ksm[col * QK_ST + kb + tig];
                bf[1] = ksm[col * QK_ST + kb + tig + 4];
                mma_tf32(cfr[t], af, bf);
            }
        }
        // mask + scale + ALiBi, store to ssm
        #pragma unroll
        for (int t = 0; t < 4; t++) {
            int klocal = wk2 * 32 + t * 8 + 2 * tig;   // within-chunk col
            int ka = kc0 + klocal, kb2 = ka + 1;       // combined key idx
            #pragma unroll
            for (int half = 0; half < 2; half++) {
                int rloc = wq4 * 16 + gid + half * 8;
                int qg = q0 + rloc;
                bool oka = (ka >= qg) && (ka <= qg + WW) && (nb > 0 || ka >= WW);
                bool okb = (kb2 >= qg) && (kb2 <= qg + WW) && (nb > 0 || kb2 >= WW);
                float da = (float)(WW + qg - ka);
                float db = (float)(WW + qg - kb2);
                float sa = cfr[t][half * 2 + 0];
                float sb = cfr[t][half * 2 + 1];
                sa = oka ? (sa * scale - slope * da) : -1e30f;
                sb = okb ? (sb * scale - slope * db) : -1e30f;
                float2 st = {sa, sb};
                *(float2*)&ssm[rloc * SS_ST + klocal] = st;
            }
        }
        __syncthreads();

        // online softmax per warp's 8 queries; write P in place
        #pragma unroll
        for (int qi = 0; qi < 8; qi++) {
            int q = warp * 8 + qi;
            float s0 = ssm[q * SS_ST + lane];
            float s1 = ssm[q * SS_ST + lane + 32];
            float mx = fmaxf(s0, s1);
            #pragma unroll
            for (int off = 16; off; off >>= 1)
                mx = fmaxf(mx, __shfl_xor_sync(0xffffffffu, mx, off));
            float mn = fmaxf(m[qi], mx);
            float fac = (m[qi] > -1e29f) ? __expf(m[qi] - mn) : 0.0f;
            float p0 = (s0 > -1e29f) ? __expf(s0 - mn) : 0.0f;
            float p1 = (s1 > -1e29f) ? __expf(s1 - mn) : 0.0f;
            float ps = p0 + p1;
            #pragma unroll
            for (int off = 16; off; off >>= 1)
                ps += __shfl_xor_sync(0xffffffffu, ps, off);
            l[qi] = l[qi] * fac + ps;
            m[qi] = mn;
            o0[qi] *= fac;
            o1[qi] *= fac;
            ssm[q * SS_ST + lane] = p0;
            ssm[q * SS_ST + lane + 32] = p1;
        }
        __syncwarp();

        // o += P @ V (lane owns dims lane, lane+32)
        #pragma unroll
        for (int kk = 0; kk < 64; kk += 4) {
            float v0[4], v1[4];
            #pragma unroll
            for (int u = 0; u < 4; u++) {
                v0[u] = vsm[(kk + u) * 64 + lane];
                v1[u] = vsm[(kk + u) * 64 + 32 + lane];
            }
            #pragma unroll
            for (int qi = 0; qi < 8; qi++) {
                float4 pv = *(const float4*)&ssm[(warp * 8 + qi) * SS_ST + kk];
                o0[qi] = fmaf(pv.x, v0[0], fmaf(pv.y, v0[1], fmaf(pv.z, v0[2], fmaf(pv.w, v0[3], o0[qi]))));
                o1[qi] = fmaf(pv.x, v1[0], fmaf(pv.y, v1[1], fmaf(pv.z, v1[2], fmaf(pv.w, v1[3], o1[qi]))));
            }
        }
        __syncwarp();
    }

    float* Ob = O + ((size_t)(b * LL + nb * WW + q0 + warp * 8)) * DDIM + head * DH;
    #pragma unroll
    for (int qi = 0; qi < 8; qi++) {
        float inv = 1.0f / l[qi];
        Ob[(size_t)qi * DDIM + lane]      = o0[qi] * inv;
        Ob[(size_t)qi * DDIM + lane + 32] = o1[qi] * inv;
    }
}

// ---------------- head: warp per row, N=14 ----------------
__global__ void head_kernel(const float* __restrict__ h, const float* __restrict__ w,
                            float* __restrict__ out) {
    int row  = blockIdx.x * 8 + (threadIdx.x >> 5);
    int lane = threadIdx.x & 31;
    float acc[VV];
    #pragma unroll
    for (int c = 0; c < VV; c++) acc[c] = 0.0f;
    for (int d = lane; d < DDIM; d += 32) {
        float xv = h[(size_t)row * DDIM + d];
        const float* wr = w + d * VV;
        #pragma unroll
        for (int c = 0; c < VV; c++) acc[c] = fmaf(xv, wr[c], acc[c]);
    }
    #pragma unroll
    for (int c = 0; c < VV; c++)
        #pragma unroll
        for (int off = 16; off; off >>= 1)
            acc[c] += __shfl_xor_sync(0xffffffffu, acc[c], off);
    if (lane < VV) out[(size_t)row * VV + lane] = acc[lane];
}

// ---------------- launch ----------------
extern "C" void kernel_launch(void* const* d_in, const int* in_sizes, int n_in,
                              void* d_out, int out_size) {
    const int*   byte_ids = (const int*)  d_in[0];
    const float* embed    = (const float*)d_in[1];
    const float* wq   = (const float*)d_in[2];
    const float* bq   = (const float*)d_in[3];
    const float* wk   = (const float*)d_in[4];
    const float* bk   = (const float*)d_in[5];
    const float* wv   = (const float*)d_in[6];
    const float* bv   = (const float*)d_in[7];
    const float* wo   = (const float*)d_in[8];
    const float* bo   = (const float*)d_in[9];
    const float* ln1g = (const float*)d_in[10];
    const float* ln1b = (const float*)d_in[11];
    const float* ln2g = (const float*)d_in[12];
    const float* ln2b = (const float*)d_in[13];
    const float* w1   = (const float*)d_in[14];
    const float* b1   = (const float*)d_in[15];
    const float* w2   = (const float*)d_in[16];
    const float* b2   = (const float*)d_in[17];
    const float* lnfg = (const float*)d_in[18];
    const float* lnfb = (const float*)d_in[19];
    const float* headw= (const float*)d_in[20];
    float* out = (float*)d_out;

    float *X, *Hb, *Q, *K, *V, *O, *F;
    cudaGetSymbolAddress((void**)&X,  g_X);
    cudaGetSymbolAddress((void**)&Hb, g_Hb);
    cudaGetSymbolAddress((void**)&Q,  g_Q);
    cudaGetSymbolAddress((void**)&K,  g_K);
    cudaGetSymbolAddress((void**)&V,  g_V);
    cudaGetSymbolAddress((void**)&O,  g_O);
    cudaGetSymbolAddress((void**)&F,  g_F);

    cudaFuncSetAttribute(attn_kernel, cudaFuncAttributeMaxDynamicSharedMemorySize, ATSM_BYTES);
    cudaFuncSetAttribute(gemm_mma<false,false>, cudaFuncAttributeMaxDynamicSharedMemorySize, GSM_BYTES);
    cudaFuncSetAttribute(gemm_mma<false,true >, cudaFuncAttributeMaxDynamicSharedMemorySize, GSM_BYTES);
    cudaFuncSetAttribute(gemm_mma<true ,false>, cudaFuncAttributeMaxDynamicSharedMemorySize, GSM_BYTES);

    embed_kernel<<<BL * 64 / 256, 256>>>(byte_ids, embed, X);

    dim3 gD(DDIM / 128, BL / 128);   // (2, 256)
    dim3 gF(FFD / 128,  BL / 128);   // (8, 256)
    dim3 gA(8, HH, BB * NBLK);
    const size_t SMB = GSM_BYTES;

    for (int l = 0; l < NLAYER; l++) {
        ln_kernel<<<BL / 8, 256>>>(X, ln1g + l * DDIM, ln1b + l * DDIM, Hb);
        gemm_mma<false, false><<<gD, 256, SMB>>>(Hb, wq + (size_t)l * DDIM * DDIM, bq + l * DDIM, nullptr, Q, BL, DDIM, DDIM);
        gemm_mma<false, false><<<gD, 256, SMB>>>(Hb, wk + (size_t)l * DDIM * DDIM, bk + l * DDIM, nullptr, K, BL, DDIM, DDIM);
        gemm_mma<false, false><<<gD, 256, SMB>>>(Hb, wv + (size_t)l * DDIM * DDIM, bv + l * DDIM, nullptr, V, BL, DDIM, DDIM);
        attn_kernel<<<gA, 256, ATSM_BYTES>>>(Q, K, V, O);
        gemm_mma<false, true ><<<gD, 256, SMB>>>(O, wo + (size_t)l * DDIM * DDIM, bo + l * DDIM, X, X, BL, DDIM, DDIM);
        ln_kernel<<<BL / 8, 256>>>(X, ln2g + l * DDIM, ln2b + l * DDIM, Hb);
        gemm_mma<true,  false><<<gF, 256, SMB>>>(Hb, w1 + (size_t)l * DDIM * FFD, b1 + l * FFD, nullptr, F, BL, FFD, DDIM);
        gemm_mma<false, true ><<<gD, 256, SMB>>>(F, w2 + (size_t)l * FFD * DDIM, b2 + l * DDIM, X, X, BL, DDIM, FFD);
    }
    ln_kernel<<<BL / 8, 256>>>(X, lnfg, lnfb, Hb);
    head_kernel<<<BL / 8, 256>>>(Hb, headw, out);
}

// round 5
// speedup vs baseline: 1.3074x; 1.3074x over previous
#include <cuda_runtime.h>
#include <math.h>
#include <stdint.h>

#define BB 4
#define LL 8192
#define DDIM 256
#define HH 4
#define NLAYER 4
#define FFD 1024
#define WW 512
#define VV 14
#define DH 64
#define BL (BB*LL)     /* 32768 rows */
#define NBLK (LL/WW)   /* 16 windows per sequence */

// ---------------- scratch (static device globals; no allocations) ----------------
__device__ float g_X [BL*DDIM];
__device__ float g_Hb[BL*DDIM];
__device__ float g_Q [BL*DDIM];
__device__ float g_K [BL*DDIM];
__device__ float g_V [BL*DDIM];
__device__ float g_O [BL*DDIM];
__device__ float g_F [BL*FFD];

__device__ __forceinline__ uint32_t f2tf32(float x) {
    uint32_t r;
    asm("cvt.rna.tf32.f32 %0, %1;" : "=r"(r) : "f"(x));
    return r;
}
__device__ __forceinline__ void mma_tf32(float* c, const uint32_t* a, const uint32_t* b) {
    asm volatile(
        "mma.sync.aligned.m16n8k8.row.col.f32.tf32.tf32.f32 "
        "{%0,%1,%2,%3}, {%4,%5,%6,%7}, {%8,%9}, {%0,%1,%2,%3};"
        : "+f"(c[0]), "+f"(c[1]), "+f"(c[2]), "+f"(c[3])
        : "r"(a[0]), "r"(a[1]), "r"(a[2]), "r"(a[3]), "r"(b[0]), "r"(b[1]));
}

// ---------------- embedding gather ----------------
__global__ void embed_kernel(const int* __restrict__ ids, const float* __restrict__ emb,
                             float* __restrict__ x) {
    int i = blockIdx.x * blockDim.x + threadIdx.x;
    int row = i >> 6;
    int d4  = i & 63;
    int id  = ids[row];
    ((float4*)x)[i] = ((const float4*)emb)[id * 64 + d4];
}

// ---------------- LayerNorm ----------------
__global__ void ln_kernel(const float* __restrict__ x, const float* __restrict__ g,
                          const float* __restrict__ b, float* __restrict__ out) {
    int row  = blockIdx.x * 8 + (threadIdx.x >> 5);
    int lane = threadIdx.x & 31;
    const float4* xr = (const float4*)(x + (size_t)row * DDIM);
    float4 v0 = xr[lane];
    float4 v1 = xr[lane + 32];
    float s  = v0.x + v0.y + v0.z + v0.w + v1.x + v1.y + v1.z + v1.w;
    float ss = v0.x*v0.x + v0.y*v0.y + v0.z*v0.z + v0.w*v0.w
             + v1.x*v1.x + v1.y*v1.y + v1.z*v1.z + v1.w*v1.w;
    #pragma unroll
    for (int off = 16; off; off >>= 1) {
        s  += __shfl_xor_sync(0xffffffffu, s,  off);
        ss += __shfl_xor_sync(0xffffffffu, ss, off);
    }
    float mean = s * (1.0f / DDIM);
    float var  = ss * (1.0f / DDIM) - mean * mean;
    float rstd = rsqrtf(var + 1e-5f);
    const float4* gp = (const float4*)g;
    const float4* bp = (const float4*)b;
    float4* op = (float4*)(out + (size_t)row * DDIM);
    float4 g0 = gp[lane], g1 = gp[lane + 32];
    float4 b0 = bp[lane], b1 = bp[lane + 32];
    float4 o0, o1;
    o0.x = (v0.x - mean) * rstd * g0.x + b0.x;
    o0.y = (v0.y - mean) * rstd * g0.y + b0.y;
    o0.z = (v0.z - mean) * rstd * g0.z + b0.z;
    o0.w = (v0.w - mean) * rstd * g0.w + b0.w;
    o1.x = (v1.x - mean) * rstd * g1.x + b1.x;
    o1.y = (v1.y - mean) * rstd * g1.y + b1.y;
    o1.z = (v1.z - mean) * rstd * g1.z + b1.z;
    o1.w = (v1.w - mean) * rstd * g1.w + b1.w;
    op[lane] = o0;
    op[lane + 32] = o1;
}

__device__ __forceinline__ float gelu_tanh(float x) {
    float t = tanhf(0.7978845608028654f * (x + 0.044715f * x * x * x));
    return 0.5f * x * (1.0f + t);
}

// ================= tf32 mma.sync GEMM (single-buffer, 2 CTA/SM) =================
// BM=128, BN=128, BK=32; 256 threads = 8 warps (4x2); warp tile 32x64 (2x8 m16n8k8).
#define AS_STRIDE 36
#define BS_STRIDE 136
#define GSM_A (128*AS_STRIDE)          /* u32 */
#define GSM_B (32*BS_STRIDE)
#define GSM_BYTES ((GSM_A + GSM_B) * 4)

template<bool GELU, bool RES>
__global__ void __launch_bounds__(256, 2) gemm_mma(
        const float* __restrict__ A, const float* __restrict__ W,
        const float* __restrict__ bias, const float* __restrict__ Res,
        float* __restrict__ C, int M, int N, int K) {
    extern __shared__ uint32_t smu[];
    uint32_t* Asu = smu;                 // [128][36] tf32 bits
    uint32_t* Bsu = smu + GSM_A;         // [32][136]
    int tid = threadIdx.x, lane = tid & 31, wid = tid >> 5;
    int wm = wid & 3, wn = wid >> 2;
    int gid = lane >> 2, tig = lane & 3;
    int m0 = blockIdx.y * 128, n0 = blockIdx.x * 128;

    float acc[2][8][4];
    #pragma unroll
    for (int i = 0; i < 2; i++)
        #pragma unroll
        for (int j = 0; j < 8; j++)
            #pragma unroll
            for (int u = 0; u < 4; u++) acc[i][j][u] = 0.0f;

    for (int k0 = 0; k0 < K; k0 += 32) {
        #pragma unroll
        for (int i = 0; i < 4; i++) {
            int idx = tid + i * 256;
            int mm = idx >> 3, kq = idx & 7;
            float4 v = *(const float4*)&A[(size_t)(m0 + mm) * K + k0 + kq * 4];
            uint32_t* p = &Asu[mm * AS_STRIDE + kq * 4];
            p[0] = f2tf32(v.x); p[1] = f2tf32(v.y);
            p[2] = f2tf32(v.z); p[3] = f2tf32(v.w);
        }
        #pragma unroll
        for (int i = 0; i < 4; i++) {
            int idx = tid + i * 256;
            int kk = idx >> 5, nq = idx & 31;
            float4 v = *(const float4*)&W[(size_t)(k0 + kk) * N + n0 + nq * 4];
            uint4 t = {f2tf32(v.x), f2tf32(v.y), f2tf32(v.z), f2tf32(v.w)};
            *(uint4*)&Bsu[kk * BS_STRIDE + nq * 4] = t;
        }
        __syncthreads();

        #pragma unroll
        for (int ks = 0; ks < 4; ks++) {
            int kb = ks * 8;
            uint32_t afr[2][4];
            #pragma unroll
            for (int tm = 0; tm < 2; tm++) {
                int row = wm * 32 + tm * 16 + gid;
                afr[tm][0] = Asu[row * AS_STRIDE + kb + tig];
                afr[tm][1] = Asu[(row + 8) * AS_STRIDE + kb + tig];
                afr[tm][2] = Asu[row * AS_STRIDE + kb + tig + 4];
                afr[tm][3] = Asu[(row + 8) * AS_STRIDE + kb + tig + 4];
            }
            uint32_t bfr[8][2];
            #pragma unroll
            for (int tn = 0; tn < 8; tn++) {
                int col = wn * 64 + tn * 8 + gid;
                bfr[tn][0] = Bsu[(kb + tig) * BS_STRIDE + col];
                bfr[tn][1] = Bsu[(kb + tig + 4) * BS_STRIDE + col];
            }
            #pragma unroll
            for (int tm = 0; tm < 2; tm++)
                #pragma unroll
                for (int tn = 0; tn < 8; tn++)
                    mma_tf32(acc[tm][tn], afr[tm], bfr[tn]);
        }
        __syncthreads();
    }

    // epilogue
    #pragma unroll
    for (int tm = 0; tm < 2; tm++) {
        int row = m0 + wm * 32 + tm * 16 + gid;
        #pragma unroll
        for (int tn = 0; tn < 8; tn++) {
            int col = n0 + wn * 64 + tn * 8 + tig * 2;
            float b0 = bias[col], b1 = bias[col + 1];
            #pragma unroll
            for (int half = 0; half < 2; half++) {
                int r = row + half * 8;
                float v0 = acc[tm][tn][half * 2 + 0] + b0;
                float v1 = acc[tm][tn][half * 2 + 1] + b1;
                if (GELU) { v0 = gelu_tanh(v0); v1 = gelu_tanh(v1); }
                size_t off = (size_t)r * N + col;
                if (RES) {
                    float2 rr = *(const float2*)&Res[off];
                    v0 += rr.x; v1 += rr.y;
                }
                float2 o = {v0, v1};
                *(float2*)&C[off] = o;
            }
        }
    }
}

// ---------------- fused attention: QK^T via tf32 MMA, fp32 softmax/PV ----------------
#define QK_ST 68
#define SS_ST 68
#define ATSM_U32 (64*QK_ST*2 + 64*64 + 64*SS_ST)
#define ATSM_BYTES (ATSM_U32 * 4)

__global__ void attn_kernel(const float* __restrict__ Q, const float* __restrict__ K,
                            const float* __restrict__ V, float* __restrict__ O) {
    extern __shared__ uint32_t smu[];
    uint32_t* qsm = smu;                       // [64][68] tf32
    uint32_t* ksm = qsm + 64 * QK_ST;          // [64][68] tf32
    float*    vsm = (float*)(ksm + 64 * QK_ST);// [64][64]
    float*    ssm = vsm + 64 * 64;             // [64][68] scores then P

    int qt   = blockIdx.x;
    int head = blockIdx.y;
    int bn   = blockIdx.z;
    int b    = bn / NBLK;
    int nb   = bn % NBLK;
    int q0   = qt * 64;
    int tid  = threadIdx.x;
    int lane = tid & 31;
    int warp = tid >> 5;
    int wq4 = warp & 3, wk2 = warp >> 2;
    int gid = lane >> 2, tig = lane & 3;

    const float* Qbase = Q + ((size_t)(b * LL + nb * WW + q0)) * DDIM + head * DH;
    #pragma unroll
    for (int i = 0; i < 4; i++) {
        int idx = tid + i * 256;
        int qi = idx >> 4, d4 = idx & 15;
        float4 v = *(const float4*)&Qbase[(size_t)qi * DDIM + d4 * 4];
        uint32_t* p = &qsm[qi * QK_ST + d4 * 4];
        p[0] = f2tf32(v.x); p[1] = f2tf32(v.y);
        p[2] = f2tf32(v.z); p[3] = f2tf32(v.w);
    }

    float m[8], l[8], o0[8], o1[8];
    #pragma unroll
    for (int i = 0; i < 8; i++) { m[i] = -1e30f; l[i] = 0.0f; o0[i] = 0.0f; o1[i] = 0.0f; }

    int lo = q0;
    if (nb == 0) lo = (lo > WW) ? lo : WW;
    int hi = q0 + 63 + WW;
    int cmin = lo >> 6, cmax = hi >> 6;

    float slope = exp2f(-2.0f * (float)(head + 1));
    const float scale = 0.125f;
    int kvbase = b * LL + nb * WW - WW;

    for (int c = cmin; c <= cmax; c++) {
        int kc0 = c * 64;
        __syncthreads();
        #pragma unroll
        for (int i = 0; i < 4; i++) {
            int idx = tid + i * 256;
            int kk = idx >> 4, d4 = idx & 15;
            size_t gro = ((size_t)(kvbase + kc0 + kk)) * DDIM + head * DH + d4 * 4;
            float4 kv = *(const float4*)&K[gro];
            uint32_t* p = &ksm[kk * QK_ST + d4 * 4];
            p[0] = f2tf32(kv.x); p[1] = f2tf32(kv.y);
            p[2] = f2tf32(kv.z); p[3] = f2tf32(kv.w);
            *(float4*)&vsm[kk * 64 + d4 * 4] = *(const float4*)&V[gro];
        }
        __syncthreads();

        // S = Q @ K^T via MMA: warp computes 16q x 32k
        float cfr[4][4];
        #pragma unroll
        for (int t = 0; t < 4; t++)
            #pragma unroll
            for (int u = 0; u < 4; u++) cfr[t][u] = 0.0f;
        #pragma unroll
        for (int ks = 0; ks < 8; ks++) {
            int kb = ks * 8;
            int r0 = (wq4 * 16 + gid) * QK_ST + kb + tig;
            uint32_t af[4];
            af[0] = qsm[r0];
            af[1] = qsm[r0 + 8 * QK_ST];
            af[2] = qsm[r0 + 4];
            af[3] = qsm[r0 + 8 * QK_ST + 4];
            #pragma unroll
            for (int t = 0; t < 4; t++) {
                int col = wk2 * 32 + t * 8 + gid;
                uint32_t bf[2];
                bf[0] = ksm[col * QK_ST + kb + tig];
                bf[1] = ksm[col * QK_ST + kb + tig + 4];
                mma_tf32(cfr[t], af, bf);
            }
        }
        #pragma unroll
        for (int t = 0; t < 4; t++) {
            int klocal = wk2 * 32 + t * 8 + 2 * tig;
            int ka = kc0 + klocal, kb2 = ka + 1;
            #pragma unroll
            for (int half = 0; half < 2; half++) {
                int rloc = wq4 * 16 + gid + half * 8;
                int qg = q0 + rloc;
                bool oka = (ka >= qg) && (ka <= qg + WW) && (nb > 0 || ka >= WW);
                bool okb = (kb2 >= qg) && (kb2 <= qg + WW) && (nb > 0 || kb2 >= WW);
                float da = (float)(WW + qg - ka);
                float db = (float)(WW + qg - kb2);
                float sa = cfr[t][half * 2 + 0];
                float sb = cfr[t][half * 2 + 1];
                sa = oka ? (sa * scale - slope * da) : -1e30f;
                sb = okb ? (sb * scale - slope * db) : -1e30f;
                float2 st = {sa, sb};
                *(float2*)&ssm[rloc * SS_ST + klocal] = st;
            }
        }
        __syncthreads();

        #pragma unroll
        for (int qi = 0; qi < 8; qi++) {
            int q = warp * 8 + qi;
            float s0 = ssm[q * SS_ST + lane];
            float s1 = ssm[q * SS_ST + lane + 32];
            float mx = fmaxf(s0, s1);
            #pragma unroll
            for (int off = 16; off; off >>= 1)
                mx = fmaxf(mx, __shfl_xor_sync(0xffffffffu, mx, off));
            float mn = fmaxf(m[qi], mx);
            float fac = (m[qi] > -1e29f) ? __expf(m[qi] - mn) : 0.0f;
            float p0 = (s0 > -1e29f) ? __expf(s0 - mn) : 0.0f;
            float p1 = (s1 > -1e29f) ? __expf(s1 - mn) : 0.0f;
            float ps = p0 + p1;
            #pragma unroll
            for (int off = 16; off; off >>= 1)
                ps += __shfl_xor_sync(0xffffffffu, ps, off);
            l[qi] = l[qi] * fac + ps;
            m[qi] = mn;
            o0[qi] *= fac;
            o1[qi] *= fac;
            ssm[q * SS_ST + lane] = p0;
            ssm[q * SS_ST + lane + 32] = p1;
        }
        __syncwarp();

        #pragma unroll
        for (int kk = 0; kk < 64; kk += 4) {
            float v0[4], v1[4];
            #pragma unroll
            for (int u = 0; u < 4; u++) {
                v0[u] = vsm[(kk + u) * 64 + lane];
                v1[u] = vsm[(kk + u) * 64 + 32 + lane];
            }
            #pragma unroll
            for (int qi = 0; qi < 8; qi++) {
                float4 pv = *(const float4*)&ssm[(warp * 8 + qi) * SS_ST + kk];
                o0[qi] = fmaf(pv.x, v0[0], fmaf(pv.y, v0[1], fmaf(pv.z, v0[2], fmaf(pv.w, v0[3], o0[qi]))));
                o1[qi] = fmaf(pv.x, v1[0], fmaf(pv.y, v1[1], fmaf(pv.z, v1[2], fmaf(pv.w, v1[3], o1[qi]))));
            }
        }
        __syncwarp();
    }

    float* Ob = O + ((size_t)(b * LL + nb * WW + q0 + warp * 8)) * DDIM + head * DH;
    #pragma unroll
    for (int qi = 0; qi < 8; qi++) {
        float inv = 1.0f / l[qi];
        Ob[(size_t)qi * DDIM + lane]      = o0[qi] * inv;
        Ob[(size_t)qi * DDIM + lane + 32] = o1[qi] * inv;
    }
}

// ---------------- head: warp per row, N=14 ----------------
__global__ void head_kernel(const float* __restrict__ h, const float* __restrict__ w,
                            float* __restrict__ out) {
    int row  = blockIdx.x * 8 + (threadIdx.x >> 5);
    int lane = threadIdx.x & 31;
    float acc[VV];
    #pragma unroll
    for (int c = 0; c < VV; c++) acc[c] = 0.0f;
    for (int d = lane; d < DDIM; d += 32) {
        float xv = h[(size_t)row * DDIM + d];
        const float* wr = w + d * VV;
        #pragma unroll
        for (int c = 0; c < VV; c++) acc[c] = fmaf(xv, wr[c], acc[c]);
    }
    #pragma unroll
    for (int c = 0; c < VV; c++)
        #pragma unroll
        for (int off = 16; off; off >>= 1)
            acc[c] += __shfl_xor_sync(0xffffffffu, acc[c], off);
    if (lane < VV) out[(size_t)row * VV + lane] = acc[lane];
}

// ---------------- launch ----------------
extern "C" void kernel_launch(void* const* d_in, const int* in_sizes, int n_in,
                              void* d_out, int out_size) {
    const int*   byte_ids = (const int*)  d_in[0];
    const float* embed    = (const float*)d_in[1];
    const float* wq   = (const float*)d_in[2];
    const float* bq   = (const float*)d_in[3];
    const float* wk   = (const float*)d_in[4];
    const float* bk   = (const float*)d_in[5];
    const float* wv   = (const float*)d_in[6];
    const float* bv   = (const float*)d_in[7];
    const float* wo   = (const float*)d_in[8];
    const float* bo   = (const float*)d_in[9];
    const float* ln1g = (const float*)d_in[10];
    const float* ln1b = (const float*)d_in[11];
    const float* ln2g = (const float*)d_in[12];
    const float* ln2b = (const float*)d_in[13];
    const float* w1   = (const float*)d_in[14];
    const float* b1   = (const float*)d_in[15];
    const float* w2   = (const float*)d_in[16];
    const float* b2   = (const float*)d_in[17];
    const float* lnfg = (const float*)d_in[18];
    const float* lnfb = (const float*)d_in[19];
    const float* headw= (const float*)d_in[20];
    float* out = (float*)d_out;

    float *X, *Hb, *Q, *K, *V, *O, *F;
    cudaGetSymbolAddress((void**)&X,  g_X);
    cudaGetSymbolAddress((void**)&Hb, g_Hb);
    cudaGetSymbolAddress((void**)&Q,  g_Q);
    cudaGetSymbolAddress((void**)&K,  g_K);
    cudaGetSymbolAddress((void**)&V,  g_V);
    cudaGetSymbolAddress((void**)&O,  g_O);
    cudaGetSymbolAddress((void**)&F,  g_F);

    cudaFuncSetAttribute(attn_kernel, cudaFuncAttributeMaxDynamicSharedMemorySize, ATSM_BYTES);

    embed_kernel<<<BL * 64 / 256, 256>>>(byte_ids, embed, X);

    dim3 gD(DDIM / 128, BL / 128);   // (2, 256)
    dim3 gF(FFD / 128,  BL / 128);   // (8, 256)
    dim3 gA(8, HH, BB * NBLK);
    const size_t SMB = GSM_BYTES;

    for (int l = 0; l < NLAYER; l++) {
        ln_kernel<<<BL / 8, 256>>>(X, ln1g + l * DDIM, ln1b + l * DDIM, Hb);
        gemm_mma<false, false><<<gD, 256, SMB>>>(Hb, wq + (size_t)l * DDIM * DDIM, bq + l * DDIM, nullptr, Q, BL, DDIM, DDIM);
        gemm_mma<false, false><<<gD, 256, SMB>>>(Hb, wk + (size_t)l * DDIM * DDIM, bk + l * DDIM, nullptr, K, BL, DDIM, DDIM);
        gemm_mma<false, false><<<gD, 256, SMB>>>(Hb, wv + (size_t)l * DDIM * DDIM, bv + l * DDIM, nullptr, V, BL, DDIM, DDIM);
        attn_kernel<<<gA, 256, ATSM_BYTES>>>(Q, K, V, O);
        gemm_mma<false, true ><<<gD, 256, SMB>>>(O, wo + (size_t)l * DDIM * DDIM, bo + l * DDIM, X, X, BL, DDIM, DDIM);
        ln_kernel<<<BL / 8, 256>>>(X, ln2g + l * DDIM, ln2b + l * DDIM, Hb);
        gemm_mma<true,  false><<<gF, 256, SMB>>>(Hb, w1 + (size_t)l * DDIM * FFD, b1 + l * FFD, nullptr, F, BL, FFD, DDIM);
        gemm_mma<false, true ><<<gD, 256, SMB>>>(F, w2 + (size_t)l * FFD * DDIM, b2 + l * DDIM, X, X, BL, DDIM, FFD);
    }
    ln_kernel<<<BL / 8, 256>>>(X, lnfg, lnfb, Hb);
    head_kernel<<<BL / 8, 256>>>(Hb, headw, out);
}

// round 6
// speedup vs baseline: 1.3922x; 1.0649x over previous
#include <cuda_runtime.h>
#include <math.h>
#include <stdint.h>

#define BB 4
#define LL 8192
#define DDIM 256
#define HH 4
#define NLAYER 4
#define FFD 1024
#define WW 512
#define VV 14
#define DH 64
#define BL (BB*LL)     /* 32768 rows */
#define NBLK (LL/WW)   /* 16 windows per sequence */

// ---------------- scratch (static device globals; no allocations) ----------------
__device__ float    g_X [BL*DDIM];     // residual (fp32)
__device__ uint32_t g_Hb[BL*DDIM];     // LN output (tf32 bits)
__device__ uint32_t g_Q [BL*DDIM];     // tf32 bits
__device__ uint32_t g_K [BL*DDIM];     // tf32 bits
__device__ float    g_V [BL*DDIM];     // fp32 (also reused as final-LN buffer)
__device__ uint32_t g_O [BL*DDIM];     // attention out (tf32 bits)
__device__ uint32_t g_F [BL*FFD];      // FFN hidden (tf32 bits)
// converted weights (tf32 bits)
__device__ uint32_t g_Wq[NLAYER*DDIM*DDIM];
__device__ uint32_t g_Wk[NLAYER*DDIM*DDIM];
__device__ uint32_t g_Wv[NLAYER*DDIM*DDIM];
__device__ uint32_t g_Wo[NLAYER*DDIM*DDIM];
__device__ uint32_t g_W1[NLAYER*DDIM*FFD];
__device__ uint32_t g_W2[NLAYER*FFD*DDIM];

__device__ __forceinline__ uint32_t f2tf32(float x) {
    uint32_t r;
    asm("cvt.rna.tf32.f32 %0, %1;" : "=r"(r) : "f"(x));
    return r;
}
__device__ __forceinline__ void mma_tf32(float* c, const uint32_t* a, const uint32_t* b) {
    asm volatile(
        "mma.sync.aligned.m16n8k8.row.col.f32.tf32.tf32.f32 "
        "{%0,%1,%2,%3}, {%4,%5,%6,%7}, {%8,%9}, {%0,%1,%2,%3};"
        : "+f"(c[0]), "+f"(c[1]), "+f"(c[2]), "+f"(c[3])
        : "r"(a[0]), "r"(a[1]), "r"(a[2]), "r"(a[3]), "r"(b[0]), "r"(b[1]));
}
__device__ __forceinline__ uint32_t smem_u32(const void* p) {
    uint32_t a;
    asm("{ .reg .u64 t; cvta.to.shared.u64 t, %1; cvt.u32.u64 %0, t; }" : "=r"(a) : "l"(p));
    return a;
}
__device__ __forceinline__ void cp16(uint32_t s, const void* g) {
    asm volatile("cp.async.cg.shared.global [%0], [%1], 16;" :: "r"(s), "l"(g));
}
#define CP_COMMIT() asm volatile("cp.async.commit_group;" ::: "memory")
#define CP_WAIT0()  asm volatile("cp.async.wait_group 0;" ::: "memory")
#define CP_WAIT1()  asm volatile("cp.async.wait_group 1;" ::: "memory")

// ---------------- weight tf32 pre-convert ----------------
__global__ void cvtw_kernel(const float* __restrict__ w, uint32_t* __restrict__ o, int n4) {
    int i = blockIdx.x * 256 + threadIdx.x;
    if (i < n4) {
        float4 v = ((const float4*)w)[i];
        uint4 t = {f2tf32(v.x), f2tf32(v.y), f2tf32(v.z), f2tf32(v.w)};
        ((uint4*)o)[i] = t;
    }
}

// ---------------- embedding gather ----------------
__global__ void embed_kernel(const int* __restrict__ ids, const float* __restrict__ emb,
                             float* __restrict__ x) {
    int i = blockIdx.x * blockDim.x + threadIdx.x;
    int row = i >> 6;
    int d4  = i & 63;
    int id  = ids[row];
    ((float4*)x)[i] = ((const float4*)emb)[id * 64 + d4];
}

// ---------------- LayerNorm (optionally emits tf32 bits) ----------------
template<bool TF32OUT>
__global__ void ln_kernel(const float* __restrict__ x, const float* __restrict__ g,
                          const float* __restrict__ b, void* __restrict__ outv) {
    int row  = blockIdx.x * 8 + (threadIdx.x >> 5);
    int lane = threadIdx.x & 31;
    const float4* xr = (const float4*)(x + (size_t)row * DDIM);
    float4 v0 = xr[lane];
    float4 v1 = xr[lane + 32];
    float s  = v0.x + v0.y + v0.z + v0.w + v1.x + v1.y + v1.z + v1.w;
    float ss = v0.x*v0.x + v0.y*v0.y + v0.z*v0.z + v0.w*v0.w
             + v1.x*v1.x + v1.y*v1.y + v1.z*v1.z + v1.w*v1.w;
    #pragma unroll
    for (int off = 16; off; off >>= 1) {
        s  += __shfl_xor_sync(0xffffffffu, s,  off);
        ss += __shfl_xor_sync(0xffffffffu, ss, off);
    }
    float mean = s * (1.0f / DDIM);
    float var  = ss * (1.0f / DDIM) - mean * mean;
    float rstd = rsqrtf(var + 1e-5f);
    const float4* gp = (const float4*)g;
    const float4* bp = (const float4*)b;
    float4 g0 = gp[lane], g1 = gp[lane + 32];
    float4 b0 = bp[lane], b1 = bp[lane + 32];
    float o[8];
    o[0] = (v0.x - mean) * rstd * g0.x + b0.x;
    o[1] = (v0.y - mean) * rstd * g0.y + b0.y;
    o[2] = (v0.z - mean) * rstd * g0.z + b0.z;
    o[3] = (v0.w - mean) * rstd * g0.w + b0.w;
    o[4] = (v1.x - mean) * rstd * g1.x + b1.x;
    o[5] = (v1.y - mean) * rstd * g1.y + b1.y;
    o[6] = (v1.z - mean) * rstd * g1.z + b1.z;
    o[7] = (v1.w - mean) * rstd * g1.w + b1.w;
    if (TF32OUT) {
        uint4* op = (uint4*)((uint32_t*)outv + (size_t)row * DDIM);
        uint4 t0 = {f2tf32(o[0]), f2tf32(o[1]), f2tf32(o[2]), f2tf32(o[3])};
        uint4 t1 = {f2tf32(o[4]), f2tf32(o[5]), f2tf32(o[6]), f2tf32(o[7])};
        op[lane] = t0;
        op[lane + 32] = t1;
    } else {
        float4* op = (float4*)((float*)outv + (size_t)row * DDIM);
        float4 t0 = {o[0], o[1], o[2], o[3]};
        float4 t1 = {o[4], o[5], o[6], o[7]};
        op[lane] = t0;
        op[lane + 32] = t1;
    }
}

__device__ __forceinline__ float gelu_tanh(float x) {
    float t = tanhf(0.7978845608028654f * (x + 0.044715f * x * x * x));
    return 0.5f * x * (1.0f + t);
}

// ================= tf32 mma.sync GEMM, cp.async double-buffered =================
// BM=128, BN=128, BK=32; 256 threads = 8 warps (4x2); warp tile 32x64 (2x8 m16n8k8).
// Inputs A, W already tf32 bits in global memory.
#define AS_ST 36
#define BS_ST 136
#define ABUF (128*AS_ST)       /* 4608 u32 per stage */
#define BBUF (32*BS_ST)        /* 4352 u32 per stage */
#define GSM_BYTES ((2*ABUF + 2*BBUF) * 4)   /* 71680 B */

template<bool GELU, bool RES, bool OUT32>
__global__ void __launch_bounds__(256, 2) gemm_cp(
        const uint32_t* __restrict__ A, const uint32_t* __restrict__ W,
        const float* __restrict__ bias, const float* __restrict__ Res,
        void* __restrict__ Cv, int M, int N, int K) {
    extern __shared__ uint32_t smu[];
    const uint32_t smb = smem_u32(smu);
    int tid = threadIdx.x, lane = tid & 31, wid = tid >> 5;
    int wm = wid & 3, wn = wid >> 2;
    int gid = lane >> 2, tig = lane & 3;
    int m0 = blockIdx.y * 128, n0 = blockIdx.x * 128;

    // per-thread load coordinates (float4 granularity)
    int amm[4], akq[4], bkk[4], bnq[4];
    uint32_t adst[4], bdst[4];     // byte offsets within a stage
    #pragma unroll
    for (int i = 0; i < 4; i++) {
        int idx = tid + i * 256;
        amm[i] = idx >> 3; akq[i] = idx & 7;
        bkk[i] = idx >> 5; bnq[i] = idx & 31;
        adst[i] = (uint32_t)(amm[i] * AS_ST + akq[i] * 4) * 4;
        bdst[i] = (uint32_t)(bkk[i] * BS_ST + bnq[i] * 4) * 4;
    }
    const uint32_t aBase[2] = { smb, smb + ABUF * 4 };
    const uint32_t bBase[2] = { smb + 2 * ABUF * 4, smb + 2 * ABUF * 4 + BBUF * 4 };

    float acc[2][8][4];
    #pragma unroll
    for (int i = 0; i < 2; i++)
        #pragma unroll
        for (int j = 0; j < 8; j++)
            #pragma unroll
            for (int u = 0; u < 4; u++) acc[i][j][u] = 0.0f;

    // prologue: stage 0
    #pragma unroll
    for (int i = 0; i < 4; i++) {
        cp16(aBase[0] + adst[i], &A[(size_t)(m0 + amm[i]) * K + akq[i] * 4]);
        cp16(bBase[0] + bdst[i], &W[(size_t)bkk[i] * N + n0 + bnq[i] * 4]);
    }
    CP_COMMIT();

    int nch = K >> 5;
    for (int kc = 0; kc < nch; kc++) {
        bool more = (kc + 1 < nch);
        if (more) {
            int s = (kc + 1) & 1;
            int k0 = (kc + 1) << 5;
            #pragma unroll
            for (int i = 0; i < 4; i++) {
                cp16(aBase[s] + adst[i], &A[(size_t)(m0 + amm[i]) * K + k0 + akq[i] * 4]);
                cp16(bBase[s] + bdst[i], &W[(size_t)(k0 + bkk[i]) * N + n0 + bnq[i] * 4]);
            }
            CP_COMMIT();
            CP_WAIT1();
        } else {
            CP_WAIT0();
        }
        __syncthreads();

        const uint32_t* As = smu + (kc & 1) * ABUF;
        const uint32_t* Bs = smu + 2 * ABUF + (kc & 1) * BBUF;
        #pragma unroll
        for (int ks = 0; ks < 4; ks++) {
            int kb = ks * 8;
            uint32_t afr[2][4];
            #pragma unroll
            for (int tm = 0; tm < 2; tm++) {
                int row = wm * 32 + tm * 16 + gid;
                afr[tm][0] = As[row * AS_ST + kb + tig];
                afr[tm][1] = As[(row + 8) * AS_ST + kb + tig];
                afr[tm][2] = As[row * AS_ST + kb + tig + 4];
                afr[tm][3] = As[(row + 8) * AS_ST + kb + tig + 4];
            }
            uint32_t bfr[8][2];
            #pragma unroll
            for (int tn = 0; tn < 8; tn++) {
                int col = wn * 64 + tn * 8 + gid;
                bfr[tn][0] = Bs[(kb + tig) * BS_ST + col];
                bfr[tn][1] = Bs[(kb + tig + 4) * BS_ST + col];
            }
            #pragma unroll
            for (int tm = 0; tm < 2; tm++)
                #pragma unroll
                for (int tn = 0; tn < 8; tn++)
                    mma_tf32(acc[tm][tn], afr[tm], bfr[tn]);
        }
        __syncthreads();
    }

    // epilogue
    float* Cf = (float*)Cv;
    uint32_t* C32 = (uint32_t*)Cv;
    #pragma unroll
    for (int tm = 0; tm < 2; tm++) {
        int row = m0 + wm * 32 + tm * 16 + gid;
        #pragma unroll
        for (int tn = 0; tn < 8; tn++) {
            int col = n0 + wn * 64 + tn * 8 + tig * 2;
            float b0 = bias[col], b1 = bias[col + 1];
            #pragma unroll
            for (int half = 0; half < 2; half++) {
                int r = row + half * 8;
                float v0 = acc[tm][tn][half * 2 + 0] + b0;
                float v1 = acc[tm][tn][half * 2 + 1] + b1;
                if (GELU) { v0 = gelu_tanh(v0); v1 = gelu_tanh(v1); }
                size_t off = (size_t)r * N + col;
                if (RES) {
                    float2 rr = *(const float2*)&Res[off];
                    v0 += rr.x; v1 += rr.y;
                }
                if (OUT32) {
                    uint2 o = {f2tf32(v0), f2tf32(v1)};
                    *(uint2*)&C32[off] = o;
                } else {
                    float2 o = {v0, v1};
                    *(float2*)&Cf[off] = o;
                }
            }
        }
    }
}

// ---------------- fused attention: QK^T via tf32 MMA, fp32 softmax/PV ----------------
// Q, K arrive as tf32 bits; V fp32; O written as tf32 bits.
#define QK_ST 68
#define SS_ST 68
#define ATSM_U32 (64*QK_ST*2 + 64*64 + 64*SS_ST)
#define ATSM_BYTES (ATSM_U32 * 4)

__global__ void attn_kernel(const uint32_t* __restrict__ Q, const uint32_t* __restrict__ K,
                            const float* __restrict__ V, uint32_t* __restrict__ O) {
    extern __shared__ uint32_t smu[];
    uint32_t* qsm = smu;                       // [64][68] tf32
    uint32_t* ksm = qsm + 64 * QK_ST;          // [64][68] tf32
    float*    vsm = (float*)(ksm + 64 * QK_ST);// [64][64]
    float*    ssm = vsm + 64 * 64;             // [64][68] scores then P

    int qt   = blockIdx.x;
    int head = blockIdx.y;
    int bn   = blockIdx.z;
    int b    = bn / NBLK;
    int nb   = bn % NBLK;
    int q0   = qt * 64;
    int tid  = threadIdx.x;
    int lane = tid & 31;
    int warp = tid >> 5;
    int wq4 = warp & 3, wk2 = warp >> 2;
    int gid = lane >> 2, tig = lane & 3;

    const uint32_t* Qbase = Q + ((size_t)(b * LL + nb * WW + q0)) * DDIM + head * DH;
    #pragma unroll
    for (int i = 0; i < 4; i++) {
        int idx = tid + i * 256;
        int qi = idx >> 4, d4 = idx & 15;
        *(uint4*)&qsm[qi * QK_ST + d4 * 4] = *(const uint4*)&Qbase[(size_t)qi * DDIM + d4 * 4];
    }

    float m[8], l[8], o0[8], o1[8];
    #pragma unroll
    for (int i = 0; i < 8; i++) { m[i] = -1e30f; l[i] = 0.0f; o0[i] = 0.0f; o1[i] = 0.0f; }

    int lo = q0;
    if (nb == 0) lo = (lo > WW) ? lo : WW;
    int hi = q0 + 63 + WW;
    int cmin = lo >> 6, cmax = hi >> 6;

    float slope = exp2f(-2.0f * (float)(head + 1));
    const float scale = 0.125f;
    int kvbase = b * LL + nb * WW - WW;

    for (int c = cmin; c <= cmax; c++) {
        int kc0 = c * 64;
        __syncthreads();
        #pragma unroll
        for (int i = 0; i < 4; i++) {
            int idx = tid + i * 256;
            int kk = idx >> 4, d4 = idx & 15;
            size_t gro = ((size_t)(kvbase + kc0 + kk)) * DDIM + head * DH + d4 * 4;
            *(uint4*)&ksm[kk * QK_ST + d4 * 4] = *(const uint4*)&K[gro];
            *(float4*)&vsm[kk * 64 + d4 * 4] = *(const float4*)&V[gro];
        }
        __syncthreads();

        // S = Q @ K^T via MMA: warp computes 16q x 32k
        float cfr[4][4];
        #pragma unroll
        for (int t = 0; t < 4; t++)
            #pragma unroll
            for (int u = 0; u < 4; u++) cfr[t][u] = 0.0f;
        #pragma unroll
        for (int ks = 0; ks < 8; ks++) {
            int kb = ks * 8;
            int r0 = (wq4 * 16 + gid) * QK_ST + kb + tig;
            uint32_t af[4];
            af[0] = qsm[r0];
            af[1] = qsm[r0 + 8 * QK_ST];
            af[2] = qsm[r0 + 4];
            af[3] = qsm[r0 + 8 * QK_ST + 4];
            #pragma unroll
            for (int t = 0; t < 4; t++) {
                int col = wk2 * 32 + t * 8 + gid;
                uint32_t bf[2];
                bf[0] = ksm[col * QK_ST + kb + tig];
                bf[1] = ksm[col * QK_ST + kb + tig + 4];
                mma_tf32(cfr[t], af, bf);
            }
        }
        #pragma unroll
        for (int t = 0; t < 4; t++) {
            int klocal = wk2 * 32 + t * 8 + 2 * tig;
            int ka = kc0 + klocal, kb2 = ka + 1;
            #pragma unroll
            for (int half = 0; half < 2; half++) {
                int rloc = wq4 * 16 + gid + half * 8;
                int qg = q0 + rloc;
                bool oka = (ka >= qg) && (ka <= qg + WW) && (nb > 0 || ka >= WW);
                bool okb = (kb2 >= qg) && (kb2 <= qg + WW) && (nb > 0 || kb2 >= WW);
                float da = (float)(WW + qg - ka);
                float db = (float)(WW + qg - kb2);
                float sa = cfr[t][half * 2 + 0];
                float sb = cfr[t][half * 2 + 1];
                sa = oka ? (sa * scale - slope * da) : -1e30f;
                sb = okb ? (sb * scale - slope * db) : -1e30f;
                float2 st = {sa, sb};
                *(float2*)&ssm[rloc * SS_ST + klocal] = st;
            }
        }
        __syncthreads();

        #pragma unroll
        for (int qi = 0; qi < 8; qi++) {
            int q = warp * 8 + qi;
            float s0 = ssm[q * SS_ST + lane];
            float s1 = ssm[q * SS_ST + lane + 32];
            float mx = fmaxf(s0, s1);
            #pragma unroll
            for (int off = 16; off; off >>= 1)
                mx = fmaxf(mx, __shfl_xor_sync(0xffffffffu, mx, off));
            float mn = fmaxf(m[qi], mx);
            float fac = (m[qi] > -1e29f) ? __expf(m[qi] - mn) : 0.0f;
            float p0 = (s0 > -1e29f) ? __expf(s0 - mn) : 0.0f;
            float p1 = (s1 > -1e29f) ? __expf(s1 - mn) : 0.0f;
            float ps = p0 + p1;
            #pragma unroll
            for (int off = 16; off; off >>= 1)
                ps += __shfl_xor_sync(0xffffffffu, ps, off);
            l[qi] = l[qi] * fac + ps;
            m[qi] = mn;
            o0[qi] *= fac;
            o1[qi] *= fac;
            ssm[q * SS_ST + lane] = p0;
            ssm[q * SS_ST + lane + 32] = p1;
        }
        __syncwarp();

        #pragma unroll
        for (int kk = 0; kk < 64; kk += 4) {
            float v0[4], v1[4];
            #pragma unroll
            for (int u = 0; u < 4; u++) {
                v0[u] = vsm[(kk + u) * 64 + lane];
                v1[u] = vsm[(kk + u) * 64 + 32 + lane];
            }
            #pragma unroll
            for (int qi = 0; qi < 8; qi++) {
                float4 pv = *(const float4*)&ssm[(warp * 8 + qi) * SS_ST + kk];
                o0[qi] = fmaf(pv.x, v0[0], fmaf(pv.y, v0[1], fmaf(pv.z, v0[2], fmaf(pv.w, v0[3], o0[qi]))));
                o1[qi] = fmaf(pv.x, v1[0], fmaf(pv.y, v1[1], fmaf(pv.z, v1[2], fmaf(pv.w, v1[3], o1[qi]))));
            }
        }
        __syncwarp();
    }

    uint32_t* Ob = O + ((size_t)(b * LL + nb * WW + q0 + warp * 8)) * DDIM + head * DH;
    #pragma unroll
    for (int qi = 0; qi < 8; qi++) {
        float inv = 1.0f / l[qi];
        Ob[(size_t)qi * DDIM + lane]      = f2tf32(o0[qi] * inv);
        Ob[(size_t)qi * DDIM + lane + 32] = f2tf32(o1[qi] * inv);
    }
}

// ---------------- head: warp per row, N=14 ----------------
__global__ void head_kernel(const float* __restrict__ h, const float* __restrict__ w,
                            float* __restrict__ out) {
    int row  = blockIdx.x * 8 + (threadIdx.x >> 5);
    int lane = threadIdx.x & 31;
    float acc[VV];
    #pragma unroll
    for (int c = 0; c < VV; c++) acc[c] = 0.0f;
    for (int d = lane; d < DDIM; d += 32) {
        float xv = h[(size_t)row * DDIM + d];
        const float* wr = w + d * VV;
        #pragma unroll
        for (int c = 0; c < VV; c++) acc[c] = fmaf(xv, wr[c], acc[c]);
    }
    #pragma unroll
    for (int c = 0; c < VV; c++)
        #pragma unroll
        for (int off = 16; off; off >>= 1)
            acc[c] += __shfl_xor_sync(0xffffffffu, acc[c], off);
    if (lane < VV) out[(size_t)row * VV + lane] = acc[lane];
}

// ---------------- launch ----------------
extern "C" void kernel_launch(void* const* d_in, const int* in_sizes, int n_in,
                              void* d_out, int out_size) {
    const int*   byte_ids = (const int*)  d_in[0];
    const float* embed    = (const float*)d_in[1];
    const float* wq   = (const float*)d_in[2];
    const float* bq   = (const float*)d_in[3];
    const float* wk   = (const float*)d_in[4];
    const float* bk   = (const float*)d_in[5];
    const float* wv   = (const float*)d_in[6];
    const float* bv   = (const float*)d_in[7];
    const float* wo   = (const float*)d_in[8];
    const float* bo   = (const float*)d_in[9];
    const float* ln1g = (const float*)d_in[10];
    const float* ln1b = (const float*)d_in[11];
    const float* ln2g = (const float*)d_in[12];
    const float* ln2b = (const float*)d_in[13];
    const float* w1   = (const float*)d_in[14];
    const float* b1   = (const float*)d_in[15];
    const float* w2   = (const float*)d_in[16];
    const float* b2   = (const float*)d_in[17];
    const float* lnfg = (const float*)d_in[18];
    const float* lnfb = (const float*)d_in[19];
    const float* headw= (const float*)d_in[20];
    float* out = (float*)d_out;

    float *X, *Vf;
    uint32_t *Hb, *Q, *K, *O, *F;
    uint32_t *Wq, *Wk, *Wv, *Wo, *W1, *W2;
    cudaGetSymbolAddress((void**)&X,  g_X);
    cudaGetSymbolAddress((void**)&Hb, g_Hb);
    cudaGetSymbolAddress((void**)&Q,  g_Q);
    cudaGetSymbolAddress((void**)&K,  g_K);
    cudaGetSymbolAddress((void**)&Vf, g_V);
    cudaGetSymbolAddress((void**)&O,  g_O);
    cudaGetSymbolAddress((void**)&F,  g_F);
    cudaGetSymbolAddress((void**)&Wq, g_Wq);
    cudaGetSymbolAddress((void**)&Wk, g_Wk);
    cudaGetSymbolAddress((void**)&Wv, g_Wv);
    cudaGetSymbolAddress((void**)&Wo, g_Wo);
    cudaGetSymbolAddress((void**)&W1, g_W1);
    cudaGetSymbolAddress((void**)&W2, g_W2);

    cudaFuncSetAttribute(attn_kernel, cudaFuncAttributeMaxDynamicSharedMemorySize, ATSM_BYTES);
    cudaFuncSetAttribute(gemm_cp<false,false,true >, cudaFuncAttributeMaxDynamicSharedMemorySize, GSM_BYTES);
    cudaFuncSetAttribute(gemm_cp<false,false,false>, cudaFuncAttributeMaxDynamicSharedMemorySize, GSM_BYTES);
    cudaFuncSetAttribute(gemm_cp<false,true ,false>, cudaFuncAttributeMaxDynamicSharedMemorySize, GSM_BYTES);
    cudaFuncSetAttribute(gemm_cp<true ,false,true >, cudaFuncAttributeMaxDynamicSharedMemorySize, GSM_BYTES);

    // pre-convert weights to tf32 bits
    {
        int nDD = NLAYER * DDIM * DDIM / 4;
        int nDF = NLAYER * DDIM * FFD / 4;
        cvtw_kernel<<<(nDD + 255) / 256, 256>>>(wq, Wq, nDD);
        cvtw_kernel<<<(nDD + 255) / 256, 256>>>(wk, Wk, nDD);
        cvtw_kernel<<<(nDD + 255) / 256, 256>>>(wv, Wv, nDD);
        cvtw_kernel<<<(nDD + 255) / 256, 256>>>(wo, Wo, nDD);
        cvtw_kernel<<<(nDF + 255) / 256, 256>>>(w1, W1, nDF);
        cvtw_kernel<<<(nDF + 255) / 256, 256>>>(w2, W2, nDF);
    }

    embed_kernel<<<BL * 64 / 256, 256>>>(byte_ids, embed, X);

    dim3 gD(DDIM / 128, BL / 128);   // (2, 256)
    dim3 gF(FFD / 128,  BL / 128);   // (8, 256)
    dim3 gA(8, HH, BB * NBLK);
    const size_t SMB = GSM_BYTES;

    for (int l = 0; l < NLAYER; l++) {
        ln_kernel<true><<<BL / 8, 256>>>(X, ln1g + l * DDIM, ln1b + l * DDIM, Hb);
        gemm_cp<false, false, true ><<<gD, 256, SMB>>>(Hb, Wq + (size_t)l * DDIM * DDIM, bq + l * DDIM, nullptr, Q, BL, DDIM, DDIM);
        gemm_cp<false, false, true ><<<gD, 256, SMB>>>(Hb, Wk + (size_t)l * DDIM * DDIM, bk + l * DDIM, nullptr, K, BL, DDIM, DDIM);
        gemm_cp<false, false, false><<<gD, 256, SMB>>>(Hb, Wv + (size_t)l * DDIM * DDIM, bv + l * DDIM, nullptr, Vf, BL, DDIM, DDIM);
        attn_kernel<<<gA, 256, ATSM_BYTES>>>(Q, K, Vf, O);
        gemm_cp<false, true , false><<<gD, 256, SMB>>>(O, Wo + (size_t)l * DDIM * DDIM, bo + l * DDIM, X, X, BL, DDIM, DDIM);
        ln_kernel<true><<<BL / 8, 256>>>(X, ln2g + l * DDIM, ln2b + l * DDIM, Hb);
        gemm_cp<true , false, true ><<<gF, 256, SMB>>>(Hb, W1 + (size_t)l * DDIM * FFD, b1 + l * FFD, nullptr, F, BL, FFD, DDIM);
        gemm_cp<false, true , false><<<gD, 256, SMB>>>(F, W2 + (size_t)l * FFD * DDIM, b2 + l * DDIM, X, X, BL, DDIM, FFD);
    }
    ln_kernel<false><<<BL / 8, 256>>>(X, lnfg, lnfb, Vf);
    head_kernel<<<BL / 8, 256>>>(Vf, headw, out);
}

// round 8
// speedup vs baseline: 1.5988x; 1.1483x over previous
#include <cuda_runtime.h>
#include <math.h>
#include <stdint.h>

#define BB 4
#define LL 8192
#define DDIM 256
#define HH 4
#define NLAYER 4
#define FFD 1024
#define WW 512
#define VV 14
#define DH 64
#define BL (BB*LL)     /* 32768 rows */
#define NBLK (LL/WW)   /* 16 windows per sequence */

// ---------------- scratch (static device globals; no allocations) ----------------
__device__ float    g_X [BL*DDIM];     // residual (fp32)
__device__ uint32_t g_Hb[BL*DDIM];     // LN output (tf32 bits)
__device__ uint32_t g_Q [BL*DDIM];     // tf32 bits
__device__ uint32_t g_K [BL*DDIM];     // tf32 bits
__device__ uint32_t g_V [BL*DDIM];     // tf32 bits (also final-LN fp32 buffer)
__device__ uint32_t g_O [BL*DDIM];     // attention out (tf32 bits)
__device__ uint32_t g_F [BL*FFD];      // FFN hidden (tf32 bits)
// converted weights (tf32 bits)
__device__ uint32_t g_Wq[NLAYER*DDIM*DDIM];
__device__ uint32_t g_Wk[NLAYER*DDIM*DDIM];
__device__ uint32_t g_Wv[NLAYER*DDIM*DDIM];
__device__ uint32_t g_Wo[NLAYER*DDIM*DDIM];
__device__ uint32_t g_W1[NLAYER*DDIM*FFD];
__device__ uint32_t g_W2[NLAYER*FFD*DDIM];

__device__ __forceinline__ uint32_t f2tf32(float x) {
    uint32_t r;
    asm("cvt.rna.tf32.f32 %0, %1;" : "=r"(r) : "f"(x));
    return r;
}
__device__ __forceinline__ void mma_tf32(float* c, const uint32_t* a, const uint32_t* b) {
    asm volatile(
        "mma.sync.aligned.m16n8k8.row.col.f32.tf32.tf32.f32 "
        "{%0,%1,%2,%3}, {%4,%5,%6,%7}, {%8,%9}, {%0,%1,%2,%3};"
        : "+f"(c[0]), "+f"(c[1]), "+f"(c[2]), "+f"(c[3])
        : "r"(a[0]), "r"(a[1]), "r"(a[2]), "r"(a[3]), "r"(b[0]), "r"(b[1]));
}
__device__ __forceinline__ uint32_t smem_u32(const void* p) {
    uint32_t a;
    asm("{ .reg .u64 t; cvta.to.shared.u64 t, %1; cvt.u32.u64 %0, t; }" : "=r"(a) : "l"(p));
    return a;
}
__device__ __forceinline__ void cp16(uint32_t s, const void* g) {
    asm volatile("cp.async.cg.shared.global [%0], [%1], 16;" :: "r"(s), "l"(g));
}
#define CP_COMMIT() asm volatile("cp.async.commit_group;" ::: "memory")
#define CP_WAIT0()  asm volatile("cp.async.wait_group 0;" ::: "memory")
#define CP_WAIT1()  asm volatile("cp.async.wait_group 1;" ::: "memory")

// ---------------- weight tf32 pre-convert ----------------
__global__ void cvtw_kernel(const float* __restrict__ w, uint32_t* __restrict__ o, int n4) {
    int i = blockIdx.x * 256 + threadIdx.x;
    if (i < n4) {
        float4 v = ((const float4*)w)[i];
        uint4 t = {f2tf32(v.x), f2tf32(v.y), f2tf32(v.z), f2tf32(v.w)};
        ((uint4*)o)[i] = t;
    }
}

// ---------------- embedding gather ----------------
__global__ void embed_kernel(const int* __restrict__ ids, const float* __restrict__ emb,
                             float* __restrict__ x) {
    int i = blockIdx.x * blockDim.x + threadIdx.x;
    int row = i >> 6;
    int d4  = i & 63;
    int id  = ids[row];
    ((float4*)x)[i] = ((const float4*)emb)[id * 64 + d4];
}

// ---------------- LayerNorm (optionally emits tf32 bits) ----------------
template<bool TF32OUT>
__global__ void ln_kernel(const float* __restrict__ x, const float* __restrict__ g,
                          const float* __restrict__ b, void* __restrict__ outv) {
    int row  = blockIdx.x * 8 + (threadIdx.x >> 5);
    int lane = threadIdx.x & 31;
    const float4* xr = (const float4*)(x + (size_t)row * DDIM);
    float4 v0 = xr[lane];
    float4 v1 = xr[lane + 32];
    float s  = v0.x + v0.y + v0.z + v0.w + v1.x + v1.y + v1.z + v1.w;
    float ss = v0.x*v0.x + v0.y*v0.y + v0.z*v0.z + v0.w*v0.w
             + v1.x*v1.x + v1.y*v1.y + v1.z*v1.z + v1.w*v1.w;
    #pragma unroll
    for (int off = 16; off; off >>= 1) {
        s  += __shfl_xor_sync(0xffffffffu, s,  off);
        ss += __shfl_xor_sync(0xffffffffu, ss, off);
    }
    float mean = s * (1.0f / DDIM);
    float var  = ss * (1.0f / DDIM) - mean * mean;
    float rstd = rsqrtf(var + 1e-5f);
    const float4* gp = (const float4*)g;
    const float4* bp = (const float4*)b;
    float4 g0 = gp[lane], g1 = gp[lane + 32];
    float4 b0 = bp[lane], b1 = bp[lane + 32];
    float o[8];
    o[0] = (v0.x - mean) * rstd * g0.x + b0.x;
    o[1] = (v0.y - mean) * rstd * g0.y + b0.y;
    o[2] = (v0.z - mean) * rstd * g0.z + b0.z;
    o[3] = (v0.w - mean) * rstd * g0.w + b0.w;
    o[4] = (v1.x - mean) * rstd * g1.x + b1.x;
    o[5] = (v1.y - mean) * rstd * g1.y + b1.y;
    o[6] = (v1.z - mean) * rstd * g1.z + b1.z;
    o[7] = (v1.w - mean) * rstd * g1.w + b1.w;
    if (TF32OUT) {
        uint4* op = (uint4*)((uint32_t*)outv + (size_t)row * DDIM);
        uint4 t0 = {f2tf32(o[0]), f2tf32(o[1]), f2tf32(o[2]), f2tf32(o[3])};
        uint4 t1 = {f2tf32(o[4]), f2tf32(o[5]), f2tf32(o[6]), f2tf32(o[7])};
        op[lane] = t0;
        op[lane + 32] = t1;
    } else {
        float4* op = (float4*)((float*)outv + (size_t)row * DDIM);
        float4 t0 = {o[0], o[1], o[2], o[3]};
        float4 t1 = {o[4], o[5], o[6], o[7]};
        op[lane] = t0;
        op[lane + 32] = t1;
    }
}

__device__ __forceinline__ float gelu_tanh(float x) {
    float t = tanhf(0.7978845608028654f * (x + 0.044715f * x * x * x));
    return 0.5f * x * (1.0f + t);
}

// ================= shared tf32 GEMM core, cp.async double-buffered =================
#define AS_ST 36
#define BS_ST 136
#define ABUF (128*AS_ST)       /* u32 per stage */
#define BBUF (32*BS_ST)
#define GSM_BYTES ((2*ABUF + 2*BBUF) * 4)

template<bool GELU, bool RES, bool OUT32>
__device__ __forceinline__ void gemm_core(
        const uint32_t* __restrict__ A, const uint32_t* __restrict__ W,
        const float* __restrict__ bias, const float* __restrict__ Res,
        void* __restrict__ Cv, int N, int K, int m0, int n0, uint32_t* smu) {
    const uint32_t smb = smem_u32(smu);
    int tid = threadIdx.x, lane = tid & 31, wid = tid >> 5;
    int wm = wid & 3, wn = wid >> 2;
    int gid = lane >> 2, tig = lane & 3;

    int amm[4], akq[4], bkk[4], bnq[4];
    uint32_t adst[4], bdst[4];
    #pragma unroll
    for (int i = 0; i < 4; i++) {
        int idx = tid + i * 256;
        amm[i] = idx >> 3; akq[i] = idx & 7;
        bkk[i] = idx >> 5; bnq[i] = idx & 31;
        adst[i] = (uint32_t)(amm[i] * AS_ST + akq[i] * 4) * 4;
        bdst[i] = (uint32_t)(bkk[i] * BS_ST + bnq[i] * 4) * 4;
    }
    const uint32_t aBase[2] = { smb, smb + ABUF * 4 };
    const uint32_t bBase[2] = { smb + 2 * ABUF * 4, smb + 2 * ABUF * 4 + BBUF * 4 };

    float acc[2][8][4];
    #pragma unroll
    for (int i = 0; i < 2; i++)
        #pragma unroll
        for (int j = 0; j < 8; j++)
            #pragma unroll
            for (int u = 0; u < 4; u++) acc[i][j][u] = 0.0f;

    #pragma unroll
    for (int i = 0; i < 4; i++) {
        cp16(aBase[0] + adst[i], &A[(size_t)(m0 + amm[i]) * K + akq[i] * 4]);
        cp16(bBase[0] + bdst[i], &W[(size_t)bkk[i] * N + n0 + bnq[i] * 4]);
    }
    CP_COMMIT();

    int nch = K >> 5;
    for (int kc = 0; kc < nch; kc++) {
        bool more = (kc + 1 < nch);
        if (more) {
            int s = (kc + 1) & 1;
            int k0 = (kc + 1) << 5;
            #pragma unroll
            for (int i = 0; i < 4; i++) {
                cp16(aBase[s] + adst[i], &A[(size_t)(m0 + amm[i]) * K + k0 + akq[i] * 4]);
                cp16(bBase[s] + bdst[i], &W[(size_t)(k0 + bkk[i]) * N + n0 + bnq[i] * 4]);
            }
            CP_COMMIT();
            CP_WAIT1();
        } else {
            CP_WAIT0();
        }
        __syncthreads();

        const uint32_t* As = smu + (kc & 1) * ABUF;
        const uint32_t* Bs = smu + 2 * ABUF + (kc & 1) * BBUF;
        #pragma unroll
        for (int ks = 0; ks < 4; ks++) {
            int kb = ks * 8;
            uint32_t afr[2][4];
            #pragma unroll
            for (int tm = 0; tm < 2; tm++) {
                int row = wm * 32 + tm * 16 + gid;
                afr[tm][0] = As[row * AS_ST + kb + tig];
                afr[tm][1] = As[(row + 8) * AS_ST + kb + tig];
                afr[tm][2] = As[row * AS_ST + kb + tig + 4];
                afr[tm][3] = As[(row + 8) * AS_ST + kb + tig + 4];
            }
            uint32_t bfr[8][2];
            #pragma unroll
            for (int tn = 0; tn < 8; tn++) {
                int col = wn * 64 + tn * 8 + gid;
                bfr[tn][0] = Bs[(kb + tig) * BS_ST + col];
                bfr[tn][1] = Bs[(kb + tig + 4) * BS_ST + col];
            }
            #pragma unroll
            for (int tm = 0; tm < 2; tm++)
                #pragma unroll
                for (int tn = 0; tn < 8; tn++)
                    mma_tf32(acc[tm][tn], afr[tm], bfr[tn]);
        }
        __syncthreads();
    }

    float* Cf = (float*)Cv;
    uint32_t* C32 = (uint32_t*)Cv;
    #pragma unroll
    for (int tm = 0; tm < 2; tm++) {
        int row = m0 + wm * 32 + tm * 16 + gid;
        #pragma unroll
        for (int tn = 0; tn < 8; tn++) {
            int col = n0 + wn * 64 + tn * 8 + tig * 2;
            float b0 = bias[col], b1 = bias[col + 1];
            #pragma unroll
            for (int half = 0; half < 2; half++) {
                int r = row + half * 8;
                float v0 = acc[tm][tn][half * 2 + 0] + b0;
                float v1 = acc[tm][tn][half * 2 + 1] + b1;
                if (GELU) { v0 = gelu_tanh(v0); v1 = gelu_tanh(v1); }
                size_t off = (size_t)r * N + col;
                if (RES) {
                    float2 rr = *(const float2*)&Res[off];
                    v0 += rr.x; v1 += rr.y;
                }
                if (OUT32) {
                    uint2 o = {f2tf32(v0), f2tf32(v1)};
                    *(uint2*)&C32[off] = o;
                } else {
                    float2 o = {v0, v1};
                    *(float2*)&Cf[off] = o;
                }
            }
        }
    }
}

template<bool GELU, bool RES, bool OUT32>
__global__ void __launch_bounds__(256, 2) gemm_cp(
        const uint32_t* __restrict__ A, const uint32_t* __restrict__ W,
        const float* __restrict__ bias, const float* __restrict__ Res,
        void* __restrict__ Cv, int N, int K) {
    extern __shared__ uint32_t smu[];
    gemm_core<GELU, RES, OUT32>(A, W, bias, Res, Cv, N, K,
                                blockIdx.y * 128, blockIdx.x * 128, smu);
}

// fused QKV: grid.x = 6 -> (mat 0..2) x (n-half 0..1)
__global__ void __launch_bounds__(256, 2) qkv_cp(
        const uint32_t* __restrict__ A,
        const uint32_t* __restrict__ Wq, const uint32_t* __restrict__ Wk, const uint32_t* __restrict__ Wv,
        const float* __restrict__ bq, const float* __restrict__ bk, const float* __restrict__ bv,
        uint32_t* __restrict__ Q, uint32_t* __restrict__ K, uint32_t* __restrict__ V) {
    extern __shared__ uint32_t smu[];
    int mat = blockIdx.x >> 1;
    const uint32_t* W = (mat == 0) ? Wq : (mat == 1) ? Wk : Wv;
    const float* bias = (mat == 0) ? bq : (mat == 1) ? bk : bv;
    uint32_t* C = (mat == 0) ? Q : (mat == 1) ? K : V;
    gemm_core<false, false, true>(A, W, bias, nullptr, C, DDIM, DDIM,
                                  blockIdx.y * 128, (blockIdx.x & 1) * 128, smu);
}

// ---------------- fused attention: QK^T and PV both via tf32 MMA ----------------
#define AT_ST 68
#define ATSM_U32 (4*64*AT_ST + 128)
#define ATSM_BYTES (ATSM_U32 * 4)

__global__ void attn_kernel(const uint32_t* __restrict__ Q, const uint32_t* __restrict__ K,
                            const uint32_t* __restrict__ V, uint32_t* __restrict__ O) {
    extern __shared__ uint32_t smu[];
    uint32_t* qsm  = smu;                        // [64][68] tf32
    uint32_t* ksm  = qsm + 64 * AT_ST;           // [64][68] tf32
    uint32_t* vsmT = ksm + 64 * AT_ST;           // [68-stride][key] transposed tf32
    uint32_t* ssm  = vsmT + 64 * AT_ST;          // [64][68] float scores -> tf32 P bits
    float*    fsm  = (float*)(ssm + 64 * AT_ST); // [64] fac
    float*    lsm  = fsm + 64;                   // [64] l

    int qt   = blockIdx.x;
    int head = blockIdx.y;
    int bn   = blockIdx.z;
    int b    = bn / NBLK;
    int nb   = bn % NBLK;
    int q0   = qt * 64;
    int tid  = threadIdx.x;
    int lane = tid & 31;
    int warp = tid >> 5;
    int wq4 = warp & 3, wk2 = warp >> 2;
    int gid = lane >> 2, tig = lane & 3;

    const uint32_t* Qbase = Q + ((size_t)(b * LL + nb * WW + q0)) * DDIM + head * DH;
    #pragma unroll
    for (int i = 0; i < 4; i++) {
        int idx = tid + i * 256;
        int qi = idx >> 4, d4 = idx & 15;
        *(uint4*)&qsm[qi * AT_ST + d4 * 4] = *(const uint4*)&Qbase[(size_t)qi * DDIM + d4 * 4];
    }

    float m[8], l[8];
    #pragma unroll
    for (int i = 0; i < 8; i++) { m[i] = -1e30f; l[i] = 0.0f; }
    float ofr[4][4];
    #pragma unroll
    for (int t = 0; t < 4; t++)
        #pragma unroll
        for (int u = 0; u < 4; u++) ofr[t][u] = 0.0f;

    int lo = q0;
    if (nb == 0) lo = (lo > WW) ? lo : WW;
    int hi = q0 + 63 + WW;
    int cmin = lo >> 6, cmax = hi >> 6;

    float slope = exp2f(-2.0f * (float)(head + 1));
    const float scale = 0.125f;
    int kvbase = b * LL + nb * WW - WW;

    for (int c = cmin; c <= cmax; c++) {
        int kc0 = c * 64;
        __syncthreads();
        #pragma unroll
        for (int i = 0; i < 4; i++) {
            int idx = tid + i * 256;
            int kk = idx >> 4, d4 = idx & 15;
            size_t gro = ((size_t)(kvbase + kc0 + kk)) * DDIM + head * DH + d4 * 4;
            *(uint4*)&ksm[kk * AT_ST + d4 * 4] = *(const uint4*)&K[gro];
            uint4 vv = *(const uint4*)&V[gro];
            vsmT[(d4 * 4 + 0) * AT_ST + kk] = vv.x;
            vsmT[(d4 * 4 + 1) * AT_ST + kk] = vv.y;
            vsmT[(d4 * 4 + 2) * AT_ST + kk] = vv.z;
            vsmT[(d4 * 4 + 3) * AT_ST + kk] = vv.w;
        }
        __syncthreads();

        // S = Q @ K^T: warp computes 16q x 32k
        float cfr[4][4];
        #pragma unroll
        for (int t = 0; t < 4; t++)
            #pragma unroll
            for (int u = 0; u < 4; u++) cfr[t][u] = 0.0f;
        #pragma unroll
        for (int ks = 0; ks < 8; ks++) {
            int kb = ks * 8;
            int r0 = (wq4 * 16 + gid) * AT_ST + kb + tig;
            uint32_t af[4];
            af[0] = qsm[r0];
            af[1] = qsm[r0 + 8 * AT_ST];
            af[2] = qsm[r0 + 4];
            af[3] = qsm[r0 + 8 * AT_ST + 4];
            #pragma unroll
            for (int t = 0; t < 4; t++) {
                int col = wk2 * 32 + t * 8 + gid;
                uint32_t bf[2];
                bf[0] = ksm[col * AT_ST + kb + tig];
                bf[1] = ksm[col * AT_ST + kb + tig + 4];
                mma_tf32(cfr[t], af, bf);
            }
        }
        #pragma unroll
        for (int t = 0; t < 4; t++) {
            int klocal = wk2 * 32 + t * 8 + 2 * tig;
            int ka = kc0 + klocal, kb2 = ka + 1;
            #pragma unroll
            for (int half = 0; half < 2; half++) {
                int rloc = wq4 * 16 + gid + half * 8;
                int qg = q0 + rloc;
                bool oka = (ka >= qg) && (ka <= qg + WW) && (nb > 0 || ka >= WW);
                bool okb = (kb2 >= qg) && (kb2 <= qg + WW) && (nb > 0 || kb2 >= WW);
                float da = (float)(WW + qg - ka);
                float db = (float)(WW + qg - kb2);
                float sa = cfr[t][half * 2 + 0];
                float sb = cfr[t][half * 2 + 1];
                sa = oka ? (sa * scale - slope * da) : -1e30f;
                sb = okb ? (sb * scale - slope * db) : -1e30f;
                float2 st = {sa, sb};
                *(float2*)&((float*)ssm)[rloc * AT_ST + klocal] = st;
            }
        }
        __syncthreads();

        // online softmax; warp owns rows [8*warp, 8*warp+8); P stored as tf32 bits
        #pragma unroll
        for (int qi = 0; qi < 8; qi++) {
            int q = warp * 8 + qi;
            float s0 = ((float*)ssm)[q * AT_ST + lane];
            float s1 = ((float*)ssm)[q * AT_ST + lane + 32];
            float mx = fmaxf(s0, s1);
            #pragma unroll
            for (int off = 16; off; off >>= 1)
                mx = fmaxf(mx, __shfl_xor_sync(0xffffffffu, mx, off));
            float mn = fmaxf(m[qi], mx);
            float fac = (m[qi] > -1e29f) ? __expf(m[qi] - mn) : 0.0f;
            float p0 = (s0 > -1e29f) ? __expf(s0 - mn) : 0.0f;
            float p1 = (s1 > -1e29f) ? __expf(s1 - mn) : 0.0f;
            float ps = p0 + p1;
            #pragma unroll
            for (int off = 16; off; off >>= 1)
                ps += __shfl_xor_sync(0xffffffffu, ps, off);
            l[qi] = l[qi] * fac + ps;
            m[qi] = mn;
            ssm[q * AT_ST + lane] = f2tf32(p0);
            ssm[q * AT_ST + lane + 32] = f2tf32(p1);
            if (lane == 0) fsm[q] = fac;
        }
        __syncthreads();

        // o = o*fac + P @ V (fragment layout: 16q x 32dim per warp)
        {
            float fa = fsm[wq4 * 16 + gid];
            float fb = fsm[wq4 * 16 + gid + 8];
            #pragma unroll
            for (int t = 0; t < 4; t++) {
                ofr[t][0] *= fa; ofr[t][1] *= fa;
                ofr[t][2] *= fb; ofr[t][3] *= fb;
            }
            #pragma unroll
            for (int ks = 0; ks < 8; ks++) {
                int kb = ks * 8;
                int r0 = (wq4 * 16 + gid) * AT_ST + kb + tig;
                uint32_t af[4];
                af[0] = ssm[r0];
                af[1] = ssm[r0 + 8 * AT_ST];
                af[2] = ssm[r0 + 4];
                af[3] = ssm[r0 + 8 * AT_ST + 4];
                #pragma unroll
                for (int t = 0; t < 4; t++) {
                    int col = wk2 * 32 + t * 8 + gid;
                    uint32_t bf[2];
                    bf[0] = vsmT[col * AT_ST + kb + tig];
                    bf[1] = vsmT[col * AT_ST + kb + tig + 4];
                    mma_tf32(ofr[t], af, bf);
                }
            }
        }
    }

    if (lane == 0) {
        #pragma unroll
        for (int qi = 0; qi < 8; qi++) lsm[warp * 8 + qi] = l[qi];
    }
    __syncthreads();

    float ia = 1.0f / lsm[wq4 * 16 + gid];
    float ib = 1.0f / lsm[wq4 * 16 + gid + 8];
    size_t rowa = (size_t)(b * LL + nb * WW + q0 + wq4 * 16 + gid) * DDIM + head * DH;
    size_t rowb = rowa + 8 * DDIM;
    #pragma unroll
    for (int t = 0; t < 4; t++) {
        int col = wk2 * 32 + t * 8 + 2 * tig;
        uint2 oa = {f2tf32(ofr[t][0] * ia), f2tf32(ofr[t][1] * ia)};
        uint2 ob = {f2tf32(ofr[t][2] * ib), f2tf32(ofr[t][3] * ib)};
        *(uint2*)&O[rowa + col] = oa;
        *(uint2*)&O[rowb + col] = ob;
    }
}

// ---------------- head: warp per row, N=14 ----------------
__global__ void head_kernel(const float* __restrict__ h, const float* __restrict__ w,
                            float* __restrict__ out) {
    int row  = blockIdx.x * 8 + (threadIdx.x >> 5);
    int lane = threadIdx.x & 31;
    float acc[VV];
    #pragma unroll
    for (int c = 0; c < VV; c++) acc[c] = 0.0f;
    for (int d = lane; d < DDIM; d += 32) {
        float xv = h[(size_t)row * DDIM + d];
        const float* wr = w + d * VV;
        #pragma unroll
        for (int c = 0; c < VV; c++) acc[c] = fmaf(xv, wr[c], acc[c]);
    }
    #pragma unroll
    for (int c = 0; c < VV; c++)
        #pragma unroll
        for (int off = 16; off; off >>= 1)
            acc[c] += __shfl_xor_sync(0xffffffffu, acc[c], off);
    if (lane < VV) out[(size_t)row * VV + lane] = acc[lane];
}

// ---------------- launch ----------------
extern "C" void kernel_launch(void* const* d_in, const int* in_sizes, int n_in,
                              void* d_out, int out_size) {
    const int*   byte_ids = (const int*)  d_in[0];
    const float* embed    = (const float*)d_in[1];
    const float* wq   = (const float*)d_in[2];
    const float* bq   = (const float*)d_in[3];
    const float* wk   = (const float*)d_in[4];
    const float* bk   = (const float*)d_in[5];
    const float* wv   = (const float*)d_in[6];
    const float* bv   = (const float*)d_in[7];
    const float* wo   = (const float*)d_in[8];
    const float* bo   = (const float*)d_in[9];
    const float* ln1g = (const float*)d_in[10];
    const float* ln1b = (const float*)d_in[11];
    const float* ln2g = (const float*)d_in[12];
    const float* ln2b = (const float*)d_in[13];
    const float* w1   = (const float*)d_in[14];
    const float* b1   = (const float*)d_in[15];
    const float* w2   = (const float*)d_in[16];
    const float* b2   = (const float*)d_in[17];
    const float* lnfg = (const float*)d_in[18];
    const float* lnfb = (const float*)d_in[19];
    const float* headw= (const float*)d_in[20];
    float* out = (float*)d_out;

    float *X;
    uint32_t *Hb, *Q, *K, *Vb, *O, *F;
    uint32_t *Wq, *Wk, *Wv, *Wo, *W1, *W2;
    cudaGetSymbolAddress((void**)&X,  g_X);
    cudaGetSymbolAddress((void**)&Hb, g_Hb);
    cudaGetSymbolAddress((void**)&Q,  g_Q);
    cudaGetSymbolAddress((void**)&K,  g_K);
    cudaGetSymbolAddress((void**)&Vb, g_V);
    cudaGetSymbolAddress((void**)&O,  g_O);
    cudaGetSymbolAddress((void**)&F,  g_F);
    cudaGetSymbolAddress((void**)&Wq, g_Wq);
    cudaGetSymbolAddress((void**)&Wk, g_Wk);
    cudaGetSymbolAddress((void**)&Wv, g_Wv);
    cudaGetSymbolAddress((void**)&Wo, g_Wo);
    cudaGetSymbolAddress((void**)&W1, g_W1);
    cudaGetSymbolAddress((void**)&W2, g_W2);

    cudaFuncSetAttribute(attn_kernel, cudaFuncAttributeMaxDynamicSharedMemorySize, ATSM_BYTES);
    cudaFuncSetAttribute(qkv_cp, cudaFuncAttributeMaxDynamicSharedMemorySize, GSM_BYTES);
    cudaFuncSetAttribute(gemm_cp<false,true ,false>, cudaFuncAttributeMaxDynamicSharedMemorySize, GSM_BYTES);
    cudaFuncSetAttribute(gemm_cp<true ,false,true >, cudaFuncAttributeMaxDynamicSharedMemorySize, GSM_BYTES);

    // pre-convert weights to tf32 bits
    {
        int nDD = NLAYER * DDIM * DDIM / 4;
        int nDF = NLAYER * DDIM * FFD / 4;
        cvtw_kernel<<<(nDD + 255) / 256, 256>>>(wq, Wq, nDD);
        cvtw_kernel<<<(nDD + 255) / 256, 256>>>(wk, Wk, nDD);
        cvtw_kernel<<<(nDD + 255) / 256, 256>>>(wv, Wv, nDD);
        cvtw_kernel<<<(nDD + 255) / 256, 256>>>(wo, Wo, nDD);
        cvtw_kernel<<<(nDF + 255) / 256, 256>>>(w1, W1, nDF);
        cvtw_kernel<<<(nDF + 255) / 256, 256>>>(w2, W2, nDF);
    }

    embed_kernel<<<BL * 64 / 256, 256>>>(byte_ids, embed, X);

    dim3 gQKV(6, BL / 128);
    dim3 gD(DDIM / 128, BL / 128);
    dim3 gF(FFD / 128,  BL / 128);
    dim3 gA(8, HH, BB * NBLK);
    const size_t SMB = GSM_BYTES;

    for (int l = 0; l < NLAYER; l++) {
        ln_kernel<true><<<BL / 8, 256>>>(X, ln1g + l * DDIM, ln1b + l * DDIM, Hb);
        qkv_cp<<<gQKV, 256, SMB>>>(Hb,
            Wq + (size_t)l * DDIM * DDIM, Wk + (size_t)l * DDIM * DDIM, Wv + (size_t)l * DDIM * DDIM,
            bq + l * DDIM, bk + l * DDIM, bv + l * DDIM, Q, K, Vb);
        attn_kernel<<<gA, 256, ATSM_BYTES>>>(Q, K, Vb, O);
        gemm_cp<false, true , false><<<gD, 256, SMB>>>(O, Wo + (size_t)l * DDIM * DDIM, bo + l * DDIM, X, X, DDIM, DDIM);
        ln_kernel<true><<<BL / 8, 256>>>(X, ln2g + l * DDIM, ln2b + l * DDIM, Hb);
        gemm_cp<true , false, true ><<<gF, 256, SMB>>>(Hb, W1 + (size_t)l * DDIM * FFD, b1 + l * FFD, nullptr, F, FFD, DDIM);
        gemm_cp<false, true , false><<<gD, 256, SMB>>>(F, W2 + (size_t)l * FFD * DDIM, b2 + l * DDIM, X, X, DDIM, FFD);
    }
    ln_kernel<false><<<BL / 8, 256>>>(X, lnfg, lnfb, (float*)Vb);
    head_kernel<<<BL / 8, 256>>>((float*)Vb, headw, out);
}

// round 9
// speedup vs baseline: 1.6158x; 1.0106x over previous
#include <cuda_runtime.h>
#include <math.h>
#include <stdint.h>

#define BB 4
#define LL 8192
#define DDIM 256
#define HH 4
#define NLAYER 4
#define FFD 1024
#define WW 512
#define VV 14
#define DH 64
#define BL (BB*LL)     /* 32768 rows */
#define NBLK (LL/WW)   /* 16 windows per sequence */

// ---------------- scratch (static device globals; no allocations) ----------------
__device__ float    g_X [BL*DDIM];     // residual (fp32)
__device__ uint32_t g_Hb[BL*DDIM];     // LN output (tf32 bits)
__device__ uint32_t g_Q [BL*DDIM];     // tf32 bits
__device__ uint32_t g_K [BL*DDIM];     // tf32 bits
__device__ uint32_t g_V [BL*DDIM];     // tf32 bits
__device__ uint32_t g_O [BL*DDIM];     // attention out (tf32 bits)
__device__ uint32_t g_F [BL*FFD];      // FFN hidden (tf32 bits)
// converted weights (tf32 bits)
__device__ uint32_t g_Wq[NLAYER*DDIM*DDIM];
__device__ uint32_t g_Wk[NLAYER*DDIM*DDIM];
__device__ uint32_t g_Wv[NLAYER*DDIM*DDIM];
__device__ uint32_t g_Wo[NLAYER*DDIM*DDIM];
__device__ uint32_t g_W1[NLAYER*DDIM*FFD];
__device__ uint32_t g_W2[NLAYER*FFD*DDIM];

__device__ __forceinline__ uint32_t f2tf32(float x) {
    uint32_t r;
    asm("cvt.rna.tf32.f32 %0, %1;" : "=r"(r) : "f"(x));
    return r;
}
__device__ __forceinline__ void mma_tf32(float* c, const uint32_t* a, const uint32_t* b) {
    asm volatile(
        "mma.sync.aligned.m16n8k8.row.col.f32.tf32.tf32.f32 "
        "{%0,%1,%2,%3}, {%4,%5,%6,%7}, {%8,%9}, {%0,%1,%2,%3};"
        : "+f"(c[0]), "+f"(c[1]), "+f"(c[2]), "+f"(c[3])
        : "r"(a[0]), "r"(a[1]), "r"(a[2]), "r"(a[3]), "r"(b[0]), "r"(b[1]));
}
__device__ __forceinline__ uint32_t smem_u32(const void* p) {
    uint32_t a;
    asm("{ .reg .u64 t; cvta.to.shared.u64 t, %1; cvt.u32.u64 %0, t; }" : "=r"(a) : "l"(p));
    return a;
}
__device__ __forceinline__ void cp16(uint32_t s, const void* g) {
    asm volatile("cp.async.cg.shared.global [%0], [%1], 16;" :: "r"(s), "l"(g));
}
#define CP_COMMIT() asm volatile("cp.async.commit_group;" ::: "memory")
#define CP_WAIT0()  asm volatile("cp.async.wait_group 0;" ::: "memory")
#define CP_WAIT1()  asm volatile("cp.async.wait_group 1;" ::: "memory")
#define BAR_PAIR(id) asm volatile("bar.sync %0, 64;" :: "r"(id) : "memory")

// ---------------- fused weight tf32 pre-convert (all 6 weights, 1 launch) ----------------
#define NDD (NLAYER*DDIM*DDIM/4)
#define NDF (NLAYER*DDIM*FFD/4)
__global__ void cvtw_all(const float* __restrict__ wq, const float* __restrict__ wk,
                         const float* __restrict__ wv, const float* __restrict__ wo,
                         const float* __restrict__ w1, const float* __restrict__ w2) {
    int i = blockIdx.x * 256 + threadIdx.x;
    const float* src;
    uint32_t* dst;
    int off;
    if (i < NDD)            { src = wq; dst = g_Wq; off = i; }
    else if (i < 2*NDD)     { src = wk; dst = g_Wk; off = i - NDD; }
    else if (i < 3*NDD)     { src = wv; dst = g_Wv; off = i - 2*NDD; }
    else if (i < 4*NDD)     { src = wo; dst = g_Wo; off = i - 3*NDD; }
    else if (i < 4*NDD+NDF) { src = w1; dst = g_W1; off = i - 4*NDD; }
    else if (i < 4*NDD+2*NDF) { src = w2; dst = g_W2; off = i - 4*NDD - NDF; }
    else return;
    float4 v = ((const float4*)src)[off];
    uint4 t = {f2tf32(v.x), f2tf32(v.y), f2tf32(v.z), f2tf32(v.w)};
    ((uint4*)dst)[off] = t;
}

// ---------------- embedding gather ----------------
__global__ void embed_kernel(const int* __restrict__ ids, const float* __restrict__ emb,
                             float* __restrict__ x) {
    int i = blockIdx.x * blockDim.x + threadIdx.x;
    int row = i >> 6;
    int d4  = i & 63;
    int id  = ids[row];
    ((float4*)x)[i] = ((const float4*)emb)[id * 64 + d4];
}

// ---------------- LayerNorm -> tf32 bits ----------------
__global__ void ln_kernel(const float* __restrict__ x, const float* __restrict__ g,
                          const float* __restrict__ b, uint32_t* __restrict__ outv) {
    int row  = blockIdx.x * 8 + (threadIdx.x >> 5);
    int lane = threadIdx.x & 31;
    const float4* xr = (const float4*)(x + (size_t)row * DDIM);
    float4 v0 = xr[lane];
    float4 v1 = xr[lane + 32];
    float s  = v0.x + v0.y + v0.z + v0.w + v1.x + v1.y + v1.z + v1.w;
    float ss = v0.x*v0.x + v0.y*v0.y + v0.z*v0.z + v0.w*v0.w
             + v1.x*v1.x + v1.y*v1.y + v1.z*v1.z + v1.w*v1.w;
    #pragma unroll
    for (int off = 16; off; off >>= 1) {
        s  += __shfl_xor_sync(0xffffffffu, s,  off);
        ss += __shfl_xor_sync(0xffffffffu, ss, off);
    }
    float mean = s * (1.0f / DDIM);
    float var  = ss * (1.0f / DDIM) - mean * mean;
    float rstd = rsqrtf(var + 1e-5f);
    const float4* gp = (const float4*)g;
    const float4* bp = (const float4*)b;
    float4 g0 = gp[lane], g1 = gp[lane + 32];
    float4 b0 = bp[lane], b1 = bp[lane + 32];
    uint4* op = (uint4*)(outv + (size_t)row * DDIM);
    uint4 t0, t1;
    t0.x = f2tf32((v0.x - mean) * rstd * g0.x + b0.x);
    t0.y = f2tf32((v0.y - mean) * rstd * g0.y + b0.y);
    t0.z = f2tf32((v0.z - mean) * rstd * g0.z + b0.z);
    t0.w = f2tf32((v0.w - mean) * rstd * g0.w + b0.w);
    t1.x = f2tf32((v1.x - mean) * rstd * g1.x + b1.x);
    t1.y = f2tf32((v1.y - mean) * rstd * g1.y + b1.y);
    t1.z = f2tf32((v1.z - mean) * rstd * g1.z + b1.z);
    t1.w = f2tf32((v1.w - mean) * rstd * g1.w + b1.w);
    op[lane] = t0;
    op[lane + 32] = t1;
}

__device__ __forceinline__ float gelu_tanh(float x) {
    float t = tanhf(0.7978845608028654f * (x + 0.044715f * x * x * x));
    return 0.5f * x * (1.0f + t);
}

// ================= shared tf32 GEMM core, cp.async double-buffered =================
#define AS_ST 36
#define BS_ST 136
#define ABUF (128*AS_ST)
#define BBUF (32*BS_ST)
#define GSM_BYTES ((2*ABUF + 2*BBUF) * 4)

template<bool GELU, bool RES, bool OUT32>
__device__ __forceinline__ void gemm_core(
        const uint32_t* __restrict__ A, const uint32_t* __restrict__ W,
        const float* __restrict__ bias, const float* __restrict__ Res,
        void* __restrict__ Cv, int N, int K, int m0, int n0, uint32_t* smu) {
    const uint32_t smb = smem_u32(smu);
    int tid = threadIdx.x, lane = tid & 31, wid = tid >> 5;
    int wm = wid & 3, wn = wid >> 2;
    int gid = lane >> 2, tig = lane & 3;

    int amm[4], akq[4], bkk[4], bnq[4];
    uint32_t adst[4], bdst[4];
    #pragma unroll
    for (int i = 0; i < 4; i++) {
        int idx = tid + i * 256;
        amm[i] = idx >> 3; akq[i] = idx & 7;
        bkk[i] = idx >> 5; bnq[i] = idx & 31;
        adst[i] = (uint32_t)(amm[i] * AS_ST + akq[i] * 4) * 4;
        bdst[i] = (uint32_t)(bkk[i] * BS_ST + bnq[i] * 4) * 4;
    }
    const uint32_t aBase[2] = { smb, smb + ABUF * 4 };
    const uint32_t bBase[2] = { smb + 2 * ABUF * 4, smb + 2 * ABUF * 4 + BBUF * 4 };

    float acc[2][8][4];
    #pragma unroll
    for (int i = 0; i < 2; i++)
        #pragma unroll
        for (int j = 0; j < 8; j++)
            #pragma unroll
            for (int u = 0; u < 4; u++) acc[i][j][u] = 0.0f;

    #pragma unroll
    for (int i = 0; i < 4; i++) {
        cp16(aBase[0] + adst[i], &A[(size_t)(m0 + amm[i]) * K + akq[i] * 4]);
        cp16(bBase[0] + bdst[i], &W[(size_t)bkk[i] * N + n0 + bnq[i] * 4]);
    }
    CP_COMMIT();

    int nch = K >> 5;
    for (int kc = 0; kc < nch; kc++) {
        bool more = (kc + 1 < nch);
        if (more) {
            int s = (kc + 1) & 1;
            int k0 = (kc + 1) << 5;
            #pragma unroll
            for (int i = 0; i < 4; i++) {
                cp16(aBase[s] + adst[i], &A[(size_t)(m0 + amm[i]) * K + k0 + akq[i] * 4]);
                cp16(bBase[s] + bdst[i], &W[(size_t)(k0 + bkk[i]) * N + n0 + bnq[i] * 4]);
            }
            CP_COMMIT();
            CP_WAIT1();
        } else {
            CP_WAIT0();
        }
        __syncthreads();

        const uint32_t* As = smu + (kc & 1) * ABUF;
        const uint32_t* Bs = smu + 2 * ABUF + (kc & 1) * BBUF;
        #pragma unroll
        for (int ks = 0; ks < 4; ks++) {
            int kb = ks * 8;
            uint32_t afr[2][4];
            #pragma unroll
            for (int tm = 0; tm < 2; tm++) {
                int row = wm * 32 + tm * 16 + gid;
                afr[tm][0] = As[row * AS_ST + kb + tig];
                afr[tm][1] = As[(row + 8) * AS_ST + kb + tig];
                afr[tm][2] = As[row * AS_ST + kb + tig + 4];
                afr[tm][3] = As[(row + 8) * AS_ST + kb + tig + 4];
            }
            uint32_t bfr[8][2];
            #pragma unroll
            for (int tn = 0; tn < 8; tn++) {
                int col = wn * 64 + tn * 8 + gid;
                bfr[tn][0] = Bs[(kb + tig) * BS_ST + col];
                bfr[tn][1] = Bs[(kb + tig + 4) * BS_ST + col];
            }
            #pragma unroll
            for (int tm = 0; tm < 2; tm++)
                #pragma unroll
                for (int tn = 0; tn < 8; tn++)
                    mma_tf32(acc[tm][tn], afr[tm], bfr[tn]);
        }
        __syncthreads();
    }

    float* Cf = (float*)Cv;
    uint32_t* C32 = (uint32_t*)Cv;
    #pragma unroll
    for (int tm = 0; tm < 2; tm++) {
        int row = m0 + wm * 32 + tm * 16 + gid;
        #pragma unroll
        for (int tn = 0; tn < 8; tn++) {
            int col = n0 + wn * 64 + tn * 8 + tig * 2;
            float b0 = bias[col], b1 = bias[col + 1];
            #pragma unroll
            for (int half = 0; half < 2; half++) {
                int r = row + half * 8;
                float v0 = acc[tm][tn][half * 2 + 0] + b0;
                float v1 = acc[tm][tn][half * 2 + 1] + b1;
                if (GELU) { v0 = gelu_tanh(v0); v1 = gelu_tanh(v1); }
                size_t off = (size_t)r * N + col;
                if (RES) {
                    float2 rr = *(const float2*)&Res[off];
                    v0 += rr.x; v1 += rr.y;
                }
                if (OUT32) {
                    uint2 o = {f2tf32(v0), f2tf32(v1)};
                    *(uint2*)&C32[off] = o;
                } else {
                    float2 o = {v0, v1};
                    *(float2*)&Cf[off] = o;
                }
            }
        }
    }
}

template<bool GELU, bool RES, bool OUT32>
__global__ void __launch_bounds__(256, 2) gemm_cp(
        const uint32_t* __restrict__ A, const uint32_t* __restrict__ W,
        const float* __restrict__ bias, const float* __restrict__ Res,
        void* __restrict__ Cv, int N, int K) {
    extern __shared__ uint32_t smu[];
    gemm_core<GELU, RES, OUT32>(A, W, bias, Res, Cv, N, K,
                                blockIdx.y * 128, blockIdx.x * 128, smu);
}

// fused QKV: grid.x = 6 -> (mat 0..2) x (n-half 0..1)
__global__ void __launch_bounds__(256, 2) qkv_cp(
        const uint32_t* __restrict__ A,
        const uint32_t* __restrict__ Wq, const uint32_t* __restrict__ Wk, const uint32_t* __restrict__ Wv,
        const float* __restrict__ bq, const float* __restrict__ bk, const float* __restrict__ bv,
        uint32_t* __restrict__ Q, uint32_t* __restrict__ K, uint32_t* __restrict__ V) {
    extern __shared__ uint32_t smu[];
    int mat = blockIdx.x >> 1;
    const uint32_t* W = (mat == 0) ? Wq : (mat == 1) ? Wk : Wv;
    const float* bias = (mat == 0) ? bq : (mat == 1) ? bk : bv;
    uint32_t* C = (mat == 0) ? Q : (mat == 1) ? K : V;
    gemm_core<false, false, true>(A, W, bias, nullptr, C, DDIM, DDIM,
                                  blockIdx.y * 128, (blockIdx.x & 1) * 128, smu);
}

// ---------------- fused attention: QK^T and PV via tf32 MMA, pair-scoped barriers ----------------
#define QS_ST 68
#define KS_ST 68
#define VS_ST 72
#define SS_ST 68
#define ATSM_U32 (64*QS_ST + 64*KS_ST + 64*VS_ST + 64*SS_ST + 128)
#define ATSM_BYTES (ATSM_U32 * 4)

__global__ void attn_kernel(const uint32_t* __restrict__ Q, const uint32_t* __restrict__ K,
                            const uint32_t* __restrict__ V, uint32_t* __restrict__ O) {
    extern __shared__ uint32_t smu[];
    uint32_t* qsm = smu;                        // [64][68]
    uint32_t* ksm = qsm + 64 * QS_ST;           // [64][68] rows = keys
    uint32_t* vsm = ksm + 64 * KS_ST;           // [64][72] rows = keys (no transpose)
    uint32_t* ssm = vsm + 64 * VS_ST;           // [64][68] float scores -> tf32 P bits
    float*    fsm = (float*)(ssm + 64 * SS_ST); // [64] fac
    float*    lsm = fsm + 64;                   // [64] l

    int qt   = blockIdx.x;
    int head = blockIdx.y;
    int bn   = blockIdx.z;
    int b    = bn / NBLK;
    int nb   = bn % NBLK;
    int q0   = qt * 64;
    int tid  = threadIdx.x;
    int lane = tid & 31;
    int warp = tid >> 5;
    int wq4 = warp & 3, wk2 = warp >> 2;
    int gid = lane >> 2, tig = lane & 3;
    int barid = 1 + wq4;

    const uint32_t* Qbase = Q + ((size_t)(b * LL + nb * WW + q0)) * DDIM + head * DH;
    #pragma unroll
    for (int i = 0; i < 4; i++) {
        int idx = tid + i * 256;
        int qi = idx >> 4, d4 = idx & 15;
        *(uint4*)&qsm[qi * QS_ST + d4 * 4] = *(const uint4*)&Qbase[(size_t)qi * DDIM + d4 * 4];
    }

    float m[8], l[8];
    #pragma unroll
    for (int i = 0; i < 8; i++) { m[i] = -1e30f; l[i] = 0.0f; }
    float ofr[4][4];
    #pragma unroll
    for (int t = 0; t < 4; t++)
        #pragma unroll
        for (int u = 0; u < 4; u++) ofr[t][u] = 0.0f;

    int lo = q0;
    if (nb == 0) lo = (lo > WW) ? lo : WW;
    int hi = q0 + 63 + WW;
    int cmin = lo >> 6, cmax = hi >> 6;

    float slope = exp2f(-2.0f * (float)(head + 1));
    const float scale = 0.125f;
    int kvbase = b * LL + nb * WW - WW;

    for (int c = cmin; c <= cmax; c++) {
        int kc0 = c * 64;
        __syncthreads();   // all PV of previous chunk done; ksm/vsm free
        #pragma unroll
        for (int i = 0; i < 4; i++) {
            int idx = tid + i * 256;
            int kk = idx >> 4, d4 = idx & 15;
            size_t gro = ((size_t)(kvbase + kc0 + kk)) * DDIM + head * DH + d4 * 4;
            *(uint4*)&ksm[kk * KS_ST + d4 * 4] = *(const uint4*)&K[gro];
            *(uint4*)&vsm[kk * VS_ST + d4 * 4] = *(const uint4*)&V[gro];
        }
        __syncthreads();   // K/V visible

        // S = Q @ K^T: warp computes rows [16*wq4,16*wq4+16) x keys [32*wk2, +32)
        float cfr[4][4];
        #pragma unroll
        for (int t = 0; t < 4; t++)
            #pragma unroll
            for (int u = 0; u < 4; u++) cfr[t][u] = 0.0f;
        #pragma unroll
        for (int ks = 0; ks < 8; ks++) {
            int kb = ks * 8;
            int r0 = (wq4 * 16 + gid) * QS_ST + kb + tig;
            uint32_t af[4];
            af[0] = qsm[r0];
            af[1] = qsm[r0 + 8 * QS_ST];
            af[2] = qsm[r0 + 4];
            af[3] = qsm[r0 + 8 * QS_ST + 4];
            #pragma unroll
            for (int t = 0; t < 4; t++) {
                int col = wk2 * 32 + t * 8 + gid;
                uint32_t bf[2];
                bf[0] = ksm[col * KS_ST + kb + tig];
                bf[1] = ksm[col * KS_ST + kb + tig + 4];
                mma_tf32(cfr[t], af, bf);
            }
        }
        #pragma unroll
        for (int t = 0; t < 4; t++) {
            int klocal = wk2 * 32 + t * 8 + 2 * tig;
            int ka = kc0 + klocal, kb2 = ka + 1;
            #pragma unroll
            for (int half = 0; half < 2; half++) {
                int rloc = wq4 * 16 + gid + half * 8;
                int qg = q0 + rloc;
                bool oka = (ka >= qg) && (ka <= qg + WW) && (nb > 0 || ka >= WW);
                bool okb = (kb2 >= qg) && (kb2 <= qg + WW) && (nb > 0 || kb2 >= WW);
                float da = (float)(WW + qg - ka);
                float db = (float)(WW + qg - kb2);
                float sa = cfr[t][half * 2 + 0];
                float sb = cfr[t][half * 2 + 1];
                sa = oka ? (sa * scale - slope * da) : -1e30f;
                sb = okb ? (sb * scale - slope * db) : -1e30f;
                float2 st = {sa, sb};
                *(float2*)&((float*)ssm)[rloc * SS_ST + klocal] = st;
            }
        }
        BAR_PAIR(barid);   // both wk2 halves of this pair's score rows visible

        // online softmax: warp owns rows [16*wq4 + 8*wk2, +8)
        #pragma unroll
        for (int qi = 0; qi < 8; qi++) {
            int q = wq4 * 16 + wk2 * 8 + qi;
            float s0 = ((float*)ssm)[q * SS_ST + lane];
            float s1 = ((float*)ssm)[q * SS_ST + lane + 32];
            float mx = fmaxf(s0, s1);
            #pragma unroll
            for (int off = 16; off; off >>= 1)
                mx = fmaxf(mx, __shfl_xor_sync(0xffffffffu, mx, off));
            float mn = fmaxf(m[qi], mx);
            float fac = (m[qi] > -1e29f) ? __expf(m[qi] - mn) : 0.0f;
            float p0 = (s0 > -1e29f) ? __expf(s0 - mn) : 0.0f;
            float p1 = (s1 > -1e29f) ? __expf(s1 - mn) : 0.0f;
            float ps = p0 + p1;
            #pragma unroll
            for (int off = 16; off; off >>= 1)
                ps += __shfl_xor_sync(0xffffffffu, ps, off);
            l[qi] = l[qi] * fac + ps;
            m[qi] = mn;
            ssm[q * SS_ST + lane] = f2tf32(p0);
            ssm[q * SS_ST + lane + 32] = f2tf32(p1);
            if (lane == 0) fsm[q] = fac;
        }
        BAR_PAIR(barid);   // P + fac visible within pair

        // o = o*fac + P @ V
        {
            float fa = fsm[wq4 * 16 + gid];
            float fb = fsm[wq4 * 16 + gid + 8];
            #pragma unroll
            for (int t = 0; t < 4; t++) {
                ofr[t][0] *= fa; ofr[t][1] *= fa;
                ofr[t][2] *= fb; ofr[t][3] *= fb;
            }
            #pragma unroll
            for (int ks = 0; ks < 8; ks++) {
                int kb = ks * 8;
                int r0 = (wq4 * 16 + gid) * SS_ST + kb + tig;
                uint32_t af[4];
                af[0] = ssm[r0];
                af[1] = ssm[r0 + 8 * SS_ST];
                af[2] = ssm[r0 + 4];
                af[3] = ssm[r0 + 8 * SS_ST + 4];
                #pragma unroll
                for (int t = 0; t < 4; t++) {
                    int col = wk2 * 32 + t * 8 + gid;
                    uint32_t bf[2];
                    bf[0] = vsm[(kb + tig) * VS_ST + col];
                    bf[1] = vsm[(kb + tig + 4) * VS_ST + col];
                    mma_tf32(ofr[t], af, bf);
                }
            }
        }
    }

    if (lane == 0) {
        #pragma unroll
        for (int qi = 0; qi < 8; qi++) lsm[wq4 * 16 + wk2 * 8 + qi] = l[qi];
    }
    BAR_PAIR(barid);

    float ia = 1.0f / lsm[wq4 * 16 + gid];
    float ib = 1.0f / lsm[wq4 * 16 + gid + 8];
    size_t rowa = (size_t)(b * LL + nb * WW + q0 + wq4 * 16 + gid) * DDIM + head * DH;
    size_t rowb = rowa + 8 * DDIM;
    #pragma unroll
    for (int t = 0; t < 4; t++) {
        int col = wk2 * 32 + t * 8 + 2 * tig;
        uint2 oa = {f2tf32(ofr[t][0] * ia), f2tf32(ofr[t][1] * ia)};
        uint2 ob = {f2tf32(ofr[t][2] * ib), f2tf32(ofr[t][3] * ib)};
        *(uint2*)&O[rowa + col] = oa;
        *(uint2*)&O[rowb + col] = ob;
    }
}

// ---------------- head with fused final LayerNorm: warp per row, N=14 ----------------
__global__ void head_kernel(const float* __restrict__ x, const float* __restrict__ g,
                            const float* __restrict__ bb, const float* __restrict__ w,
                            float* __restrict__ out) {
    int row  = blockIdx.x * 8 + (threadIdx.x >> 5);
    int lane = threadIdx.x & 31;
    const float4* xr = (const float4*)(x + (size_t)row * DDIM);
    float4 v0 = xr[lane];
    float4 v1 = xr[lane + 32];
    float s  = v0.x + v0.y + v0.z + v0.w + v1.x + v1.y + v1.z + v1.w;
    float ss = v0.x*v0.x + v0.y*v0.y + v0.z*v0.z + v0.w*v0.w
             + v1.x*v1.x + v1.y*v1.y + v1.z*v1.z + v1.w*v1.w;
    #pragma unroll
    for (int off = 16; off; off >>= 1) {
        s  += __shfl_xor_sync(0xffffffffu, s,  off);
        ss += __shfl_xor_sync(0xffffffffu, ss, off);
    }
    float mean = s * (1.0f / DDIM);
    float var  = ss * (1.0f / DDIM) - mean * mean;
    float rstd = rsqrtf(var + 1e-5f);
    const float4* gp = (const float4*)g;
    const float4* bp = (const float4*)bb;
    float4 g0 = gp[lane], g1 = gp[lane + 32];
    float4 b0 = bp[lane], b1 = bp[lane + 32];
    float h[8];
    h[0] = (v0.x - mean) * rstd * g0.x + b0.x;
    h[1] = (v0.y - mean) * rstd * g0.y + b0.y;
    h[2] = (v0.z - mean) * rstd * g0.z + b0.z;
    h[3] = (v0.w - mean) * rstd * g0.w + b0.w;
    h[4] = (v1.x - mean) * rstd * g1.x + b1.x;
    h[5] = (v1.y - mean) * rstd * g1.y + b1.y;
    h[6] = (v1.z - mean) * rstd * g1.z + b1.z;
    h[7] = (v1.w - mean) * rstd * g1.w + b1.w;

    float acc[VV];
    #pragma unroll
    for (int c = 0; c < VV; c++) acc[c] = 0.0f;
    #pragma unroll
    for (int u = 0; u < 8; u++) {
        int d = (u < 4) ? (lane * 4 + u) : (128 + lane * 4 + (u - 4));
        const float* wr = w + d * VV;
        #pragma unroll
        for (int c = 0; c < VV; c++) acc[c] = fmaf(h[u], wr[c], acc[c]);
    }
    #pragma unroll
    for (int c = 0; c < VV; c++)
        #pragma unroll
        for (int off = 16; off; off >>= 1)
            acc[c] += __shfl_xor_sync(0xffffffffu, acc[c], off);
    if (lane < VV) out[(size_t)row * VV + lane] = acc[lane];
}

// ---------------- launch ----------------
extern "C" void kernel_launch(void* const* d_in, const int* in_sizes, int n_in,
                              void* d_out, int out_size) {
    const int*   byte_ids = (const int*)  d_in[0];
    const float* embed    = (const float*)d_in[1];
    const float* wq   = (const float*)d_in[2];
    const float* bq   = (const float*)d_in[3];
    const float* wk   = (const float*)d_in[4];
    const float* bk   = (const float*)d_in[5];
    const float* wv   = (const float*)d_in[6];
    const float* bv   = (const float*)d_in[7];
    const float* wo   = (const float*)d_in[8];
    const float* bo   = (const float*)d_in[9];
    const float* ln1g = (const float*)d_in[10];
    const float* ln1b = (const float*)d_in[11];
    const float* ln2g = (const float*)d_in[12];
    const float* ln2b = (const float*)d_in[13];
    const float* w1   = (const float*)d_in[14];
    const float* b1   = (const float*)d_in[15];
    const float* w2   = (const float*)d_in[16];
    const float* b2   = (const float*)d_in[17];
    const float* lnfg = (const float*)d_in[18];
    const float* lnfb = (const float*)d_in[19];
    const float* headw= (const float*)d_in[20];
    float* out = (float*)d_out;

    float *X;
    uint32_t *Hb, *Q, *K, *Vb, *O, *F;
    uint32_t *Wq, *Wk, *Wv, *Wo, *W1, *W2;
    cudaGetSymbolAddress((void**)&X,  g_X);
    cudaGetSymbolAddress((void**)&Hb, g_Hb);
    cudaGetSymbolAddress((void**)&Q,  g_Q);
    cudaGetSymbolAddress((void**)&K,  g_K);
    cudaGetSymbolAddress((void**)&Vb, g_V);
    cudaGetSymbolAddress((void**)&O,  g_O);
    cudaGetSymbolAddress((void**)&F,  g_F);
    cudaGetSymbolAddress((void**)&Wq, g_Wq);
    cudaGetSymbolAddress((void**)&Wk, g_Wk);
    cudaGetSymbolAddress((void**)&Wv, g_Wv);
    cudaGetSymbolAddress((void**)&Wo, g_Wo);
    cudaGetSymbolAddress((void**)&W1, g_W1);
    cudaGetSymbolAddress((void**)&W2, g_W2);

    cudaFuncSetAttribute(attn_kernel, cudaFuncAttributeMaxDynamicSharedMemorySize, ATSM_BYTES);
    cudaFuncSetAttribute(qkv_cp, cudaFuncAttributeMaxDynamicSharedMemorySize, GSM_BYTES);
    cudaFuncSetAttribute(gemm_cp<false,true ,false>, cudaFuncAttributeMaxDynamicSharedMemorySize, GSM_BYTES);
    cudaFuncSetAttribute(gemm_cp<true ,false,true >, cudaFuncAttributeMaxDynamicSharedMemorySize, GSM_BYTES);

    // pre-convert all weights to tf32 bits (one launch)
    {
        int tot4 = 4 * NDD + 2 * NDF;
        cvtw_all<<<(tot4 + 255) / 256, 256>>>(wq, wk, wv, wo, w1, w2);
    }

    embed_kernel<<<BL * 64 / 256, 256>>>(byte_ids, embed, X);

    dim3 gQKV(6, BL / 128);
    dim3 gD(DDIM / 128, BL / 128);
    dim3 gF(FFD / 128,  BL / 128);
    dim3 gA(8, HH, BB * NBLK);
    const size_t SMB = GSM_BYTES;

    for (int l = 0; l < NLAYER; l++) {
        ln_kernel<<<BL / 8, 256>>>(X, ln1g + l * DDIM, ln1b + l * DDIM, Hb);
        qkv_cp<<<gQKV, 256, SMB>>>(Hb,
            Wq + (size_t)l * DDIM * DDIM, Wk + (size_t)l * DDIM * DDIM, Wv + (size_t)l * DDIM * DDIM,
            bq + l * DDIM, bk + l * DDIM, bv + l * DDIM, Q, K, Vb);
        attn_kernel<<<gA, 256, ATSM_BYTES>>>(Q, K, Vb, O);
        gemm_cp<false, true , false><<<gD, 256, SMB>>>(O, Wo + (size_t)l * DDIM * DDIM, bo + l * DDIM, X, X, DDIM, DDIM);
        ln_kernel<<<BL / 8, 256>>>(X, ln2g + l * DDIM, ln2b + l * DDIM, Hb);
        gemm_cp<true , false, true ><<<gF, 256, SMB>>>(Hb, W1 + (size_t)l * DDIM * FFD, b1 + l * FFD, nullptr, F, FFD, DDIM);
        gemm_cp<false, true , false><<<gD, 256, SMB>>>(F, W2 + (size_t)l * FFD * DDIM, b2 + l * DDIM, X, X, DDIM, FFD);
    }
    head_kernel<<<BL / 8, 256>>>(X, lnfg, lnfb, headw, out);
}

// round 14
// speedup vs baseline: 1.6172x; 1.0009x over previous
#include <cuda_runtime.h>
#include <math.h>
#include <stdint.h>

#define BB 4
#define LL 8192
#define DDIM 256
#define HH 4
#define NLAYER 4
#define FFD 1024
#define WW 512
#define VV 14
#define DH 64
#define BL (BB*LL)     /* 32768 rows */
#define NBLK (LL/WW)   /* 16 windows per sequence */

// ---------------- scratch (static device globals; no allocations) ----------------
__device__ float    g_X [BL*DDIM];     // residual (fp32)
__device__ uint32_t g_Hb[BL*DDIM];     // LN output (tf32 bits)
__device__ uint32_t g_Q [BL*DDIM];     // tf32 bits
__device__ uint32_t g_K [BL*DDIM];     // tf32 bits
__device__ uint32_t g_V [BL*DDIM];     // tf32 bits
__device__ uint32_t g_O [BL*DDIM];     // attention out (tf32 bits)
__device__ uint32_t g_F [BL*FFD];      // FFN hidden (tf32 bits)
// converted weights (tf32 bits)
__device__ uint32_t g_Wq[NLAYER*DDIM*DDIM];
__device__ uint32_t g_Wk[NLAYER*DDIM*DDIM];
__device__ uint32_t g_Wv[NLAYER*DDIM*DDIM];
__device__ uint32_t g_Wo[NLAYER*DDIM*DDIM];
__device__ uint32_t g_W1[NLAYER*DDIM*FFD];
__device__ uint32_t g_W2[NLAYER*FFD*DDIM];

__device__ __forceinline__ uint32_t f2tf32(float x) {
    uint32_t r;
    asm("cvt.rna.tf32.f32 %0, %1;" : "=r"(r) : "f"(x));
    return r;
}
__device__ __forceinline__ void mma_tf32(float* c, const uint32_t* a, const uint32_t* b) {
    asm volatile(
        "mma.sync.aligned.m16n8k8.row.col.f32.tf32.tf32.f32 "
        "{%0,%1,%2,%3}, {%4,%5,%6,%7}, {%8,%9}, {%0,%1,%2,%3};"
        : "+f"(c[0]), "+f"(c[1]), "+f"(c[2]), "+f"(c[3])
        : "r"(a[0]), "r"(a[1]), "r"(a[2]), "r"(a[3]), "r"(b[0]), "r"(b[1]));
}
__device__ __forceinline__ uint32_t smem_u32(const void* p) {
    uint32_t a;
    asm("{ .reg .u64 t; cvta.to.shared.u64 t, %1; cvt.u32.u64 %0, t; }" : "=r"(a) : "l"(p));
    return a;
}
__device__ __forceinline__ void cp16(uint32_t s, const void* g) {
    asm volatile("cp.async.cg.shared.global [%0], [%1], 16;" :: "r"(s), "l"(g));
}
#define CP_COMMIT() asm volatile("cp.async.commit_group;" ::: "memory")
#define CP_WAIT0()  asm volatile("cp.async.wait_group 0;" ::: "memory")
#define CP_WAIT1()  asm volatile("cp.async.wait_group 1;" ::: "memory")
#define BAR_PAIR(id) asm volatile("bar.sync %0, 64;" :: "r"(id) : "memory")

// ---------------- fused weight tf32 pre-convert (all 6 weights, 1 launch) ----------------
#define NDD (NLAYER*DDIM*DDIM/4)
#define NDF (NLAYER*DDIM*FFD/4)
__global__ void cvtw_all(const float* __restrict__ wq, const float* __restrict__ wk,
                         const float* __restrict__ wv, const float* __restrict__ wo,
                         const float* __restrict__ w1, const float* __restrict__ w2) {
    int i = blockIdx.x * 256 + threadIdx.x;
    const float* src;
    uint32_t* dst;
    int off;
    if (i < NDD)            { src = wq; dst = g_Wq; off = i; }
    else if (i < 2*NDD)     { src = wk; dst = g_Wk; off = i - NDD; }
    else if (i < 3*NDD)     { src = wv; dst = g_Wv; off = i - 2*NDD; }
    else if (i < 4*NDD)     { src = wo; dst = g_Wo; off = i - 3*NDD; }
    else if (i < 4*NDD+NDF) { src = w1; dst = g_W1; off = i - 4*NDD; }
    else if (i < 4*NDD+2*NDF) { src = w2; dst = g_W2; off = i - 4*NDD - NDF; }
    else return;
    float4 v = ((const float4*)src)[off];
    uint4 t = {f2tf32(v.x), f2tf32(v.y), f2tf32(v.z), f2tf32(v.w)};
    ((uint4*)dst)[off] = t;
}

// ---------------- embedding gather ----------------
__global__ void embed_kernel(const int* __restrict__ ids, const float* __restrict__ emb,
                             float* __restrict__ x) {
    int i = blockIdx.x * blockDim.x + threadIdx.x;
    int row = i >> 6;
    int d4  = i & 63;
    int id  = ids[row];
    ((float4*)x)[i] = ((const float4*)emb)[id * 64 + d4];
}

// ---------------- LayerNorm -> tf32 bits ----------------
__global__ void ln_kernel(const float* __restrict__ x, const float* __restrict__ g,
                          const float* __restrict__ b, uint32_t* __restrict__ outv) {
    int row  = blockIdx.x * 8 + (threadIdx.x >> 5);
    int lane = threadIdx.x & 31;
    const float4* xr = (const float4*)(x + (size_t)row * DDIM);
    float4 v0 = xr[lane];
    float4 v1 = xr[lane + 32];
    float s  = v0.x + v0.y + v0.z + v0.w + v1.x + v1.y + v1.z + v1.w;
    float ss = v0.x*v0.x + v0.y*v0.y + v0.z*v0.z + v0.w*v0.w
             + v1.x*v1.x + v1.y*v1.y + v1.z*v1.z + v1.w*v1.w;
    #pragma unroll
    for (int off = 16; off; off >>= 1) {
        s  += __shfl_xor_sync(0xffffffffu, s,  off);
        ss += __shfl_xor_sync(0xffffffffu, ss, off);
    }
    float mean = s * (1.0f / DDIM);
    float var  = ss * (1.0f / DDIM) - mean * mean;
    float rstd = rsqrtf(var + 1e-5f);
    const float4* gp = (const float4*)g;
    const float4* bp = (const float4*)b;
    float4 g0 = gp[lane], g1 = gp[lane + 32];
    float4 b0 = bp[lane], b1 = bp[lane + 32];
    uint4* op = (uint4*)(outv + (size_t)row * DDIM);
    uint4 t0, t1;
    t0.x = f2tf32((v0.x - mean) * rstd * g0.x + b0.x);
    t0.y = f2tf32((v0.y - mean) * rstd * g0.y + b0.y);
    t0.z = f2tf32((v0.z - mean) * rstd * g0.z + b0.z);
    t0.w = f2tf32((v0.w - mean) * rstd * g0.w + b0.w);
    t1.x = f2tf32((v1.x - mean) * rstd * g1.x + b1.x);
    t1.y = f2tf32((v1.y - mean) * rstd * g1.y + b1.y);
    t1.z = f2tf32((v1.z - mean) * rstd * g1.z + b1.z);
    t1.w = f2tf32((v1.w - mean) * rstd * g1.w + b1.w);
    op[lane] = t0;
    op[lane + 32] = t1;
}

__device__ __forceinline__ float gelu_tanh(float x) {
    float t = tanhf(0.7978845608028654f * (x + 0.044715f * x * x * x));
    return 0.5f * x * (1.0f + t);
}

// ================= shared tf32 GEMM core, 3-stage cp.async, 1 sync/chunk =================
#define AS_ST 36
#define BS_ST 136
#define ABUF (128*AS_ST)
#define BBUF (32*BS_ST)
#define STG_U32 (ABUF + BBUF)
#define GSM_BYTES (3 * STG_U32 * 4)

template<bool GELU, bool RES, bool OUT32>
__device__ __forceinline__ void gemm_core(
        const uint32_t* __restrict__ A, const uint32_t* __restrict__ W,
        const float* __restrict__ bias, const float* __restrict__ Res,
        void* __restrict__ Cv, int N, int K, int m0, int n0, uint32_t* smu) {
    const uint32_t smb = smem_u32(smu);
    int tid = threadIdx.x, lane = tid & 31, wid = tid >> 5;
    int wm = wid & 3, wn = wid >> 2;
    int gid = lane >> 2, tig = lane & 3;

    int amm[4], akq[4], bkk[4], bnq[4];
    uint32_t adst[4], bdst[4];
    #pragma unroll
    for (int i = 0; i < 4; i++) {
        int idx = tid + i * 256;
        amm[i] = idx >> 3; akq[i] = idx & 7;
        bkk[i] = idx >> 5; bnq[i] = idx & 31;
        adst[i] = (uint32_t)(amm[i] * AS_ST + akq[i] * 4) * 4;
        bdst[i] = (uint32_t)(bkk[i] * BS_ST + bnq[i] * 4) * 4;
    }

    float acc[2][8][4];
    #pragma unroll
    for (int i = 0; i < 2; i++)
        #pragma unroll
        for (int j = 0; j < 8; j++)
            #pragma unroll
            for (int u = 0; u < 4; u++) acc[i][j][u] = 0.0f;

    int nch = K >> 5;
    // prologue: stages 0 and 1, one commit group each
    #pragma unroll
    for (int st = 0; st < 2; st++) {
        uint32_t base = smb + st * STG_U32 * 4;
        int k0 = st << 5;
        #pragma unroll
        for (int i = 0; i < 4; i++) {
            cp16(base + adst[i], &A[(size_t)(m0 + amm[i]) * K + k0 + akq[i] * 4]);
            cp16(base + ABUF * 4 + bdst[i], &W[(size_t)(k0 + bkk[i]) * N + n0 + bnq[i] * 4]);
        }
        CP_COMMIT();
    }

    int stage = 0;          // stage index of chunk kc
    for (int kc = 0; kc < nch; kc++) {
        CP_WAIT1();          // chunk kc's group complete (this thread)
        __syncthreads();     // all threads' data visible; stage kc-1 compute done
        int pre = kc + 2;
        if (pre < nch) {
            int pst = pre % 3;
            uint32_t base = smb + pst * STG_U32 * 4;
            int k0 = pre << 5;
            #pragma unroll
            for (int i = 0; i < 4; i++) {
                cp16(base + adst[i], &A[(size_t)(m0 + amm[i]) * K + k0 + akq[i] * 4]);
                cp16(base + ABUF * 4 + bdst[i], &W[(size_t)(k0 + bkk[i]) * N + n0 + bnq[i] * 4]);
            }
        }
        CP_COMMIT();         // always commit (possibly empty) to keep group count uniform

        const uint32_t* As = smu + stage * STG_U32;
        const uint32_t* Bs = As + ABUF;
        #pragma unroll
        for (int ks = 0; ks < 4; ks++) {
            int kb = ks * 8;
            uint32_t afr[2][4];
            #pragma unroll
            for (int tm = 0; tm < 2; tm++) {
                int row = wm * 32 + tm * 16 + gid;
                afr[tm][0] = As[row * AS_ST + kb + tig];
                afr[tm][1] = As[(row + 8) * AS_ST + kb + tig];
                afr[tm][2] = As[row * AS_ST + kb + tig + 4];
                afr[tm][3] = As[(row + 8) * AS_ST + kb + tig + 4];
            }
            uint32_t bfr[8][2];
            #pragma unroll
            for (int tn = 0; tn < 8; tn++) {
                int col = wn * 64 + tn * 8 + gid;
                bfr[tn][0] = Bs[(kb + tig) * BS_ST + col];
                bfr[tn][1] = Bs[(kb + tig + 4) * BS_ST + col];
            }
            #pragma unroll
            for (int tm = 0; tm < 2; tm++)
                #pragma unroll
                for (int tn = 0; tn < 8; tn++)
                    mma_tf32(acc[tm][tn], afr[tm], bfr[tn]);
        }
        stage = (stage + 1 == 3) ? 0 : stage + 1;
    }

    float* Cf = (float*)Cv;
    uint32_t* C32 = (uint32_t*)Cv;
    #pragma unroll
    for (int tm = 0; tm < 2; tm++) {
        int row = m0 + wm * 32 + tm * 16 + gid;
        #pragma unroll
        for (int tn = 0; tn < 8; tn++) {
            int col = n0 + wn * 64 + tn * 8 + tig * 2;
            float b0 = bias[col], b1 = bias[col + 1];
            #pragma unroll
            for (int half = 0; half < 2; half++) {
                int r = row + half * 8;
                float v0 = acc[tm][tn][half * 2 + 0] + b0;
                float v1 = acc[tm][tn][half * 2 + 1] + b1;
                if (GELU) { v0 = gelu_tanh(v0); v1 = gelu_tanh(v1); }
                size_t off = (size_t)r * N + col;
                if (RES) {
                    float2 rr = *(const float2*)&Res[off];
                    v0 += rr.x; v1 += rr.y;
                }
                if (OUT32) {
                    uint2 o = {f2tf32(v0), f2tf32(v1)};
                    *(uint2*)&C32[off] = o;
                } else {
                    float2 o = {v0, v1};
                    *(float2*)&Cf[off] = o;
                }
            }
        }
    }
}

template<bool GELU, bool RES, bool OUT32>
__global__ void __launch_bounds__(256, 2) gemm_cp(
        const uint32_t* __restrict__ A, const uint32_t* __restrict__ W,
        const float* __restrict__ bias, const float* __restrict__ Res,
        void* __restrict__ Cv, int N, int K) {
    extern __shared__ uint32_t smu[];
    gemm_core<GELU, RES, OUT32>(A, W, bias, Res, Cv, N, K,
                                blockIdx.y * 128, blockIdx.x * 128, smu);
}

// fused QKV: grid.x = 6 -> (mat 0..2) x (n-half 0..1)
__global__ void __launch_bounds__(256, 2) qkv_cp(
        const uint32_t* __restrict__ A,
        const uint32_t* __restrict__ Wq, const uint32_t* __restrict__ Wk, const uint32_t* __restrict__ Wv,
        const float* __restrict__ bq, const float* __restrict__ bk, const float* __restrict__ bv,
        uint32_t* __restrict__ Q, uint32_t* __restrict__ K, uint32_t* __restrict__ V) {
    extern __shared__ uint32_t smu[];
    int mat = blockIdx.x >> 1;
    const uint32_t* W = (mat == 0) ? Wq : (mat == 1) ? Wk : Wv;
    const float* bias = (mat == 0) ? bq : (mat == 1) ? bk : bv;
    uint32_t* C = (mat == 0) ? Q : (mat == 1) ? K : V;
    gemm_core<false, false, true>(A, W, bias, nullptr, C, DDIM, DDIM,
                                  blockIdx.y * 128, (blockIdx.x & 1) * 128, smu);
}

// ---------------- fused attention: QK^T and PV via tf32 MMA, pair-scoped barriers ----------------
#define QS_ST 68
#define KS_ST 68
#define VS_ST 72
#define SS_ST 68
#define ATSM_U32 (64*QS_ST + 64*KS_ST + 64*VS_ST + 64*SS_ST + 128)
#define ATSM_BYTES (ATSM_U32 * 4)

__global__ void attn_kernel(const uint32_t* __restrict__ Q, const uint32_t* __restrict__ K,
                            const uint32_t* __restrict__ V, uint32_t* __restrict__ O) {
    extern __shared__ uint32_t smu[];
    uint32_t* qsm = smu;                        // [64][68]
    uint32_t* ksm = qsm + 64 * QS_ST;           // [64][68] rows = keys
    uint32_t* vsm = ksm + 64 * KS_ST;           // [64][72] rows = keys
    uint32_t* ssm = vsm + 64 * VS_ST;           // [64][68] float scores -> tf32 P bits
    float*    fsm = (float*)(ssm + 64 * SS_ST); // [64] fac
    float*    lsm = fsm + 64;                   // [64] l

    int qt   = blockIdx.x;
    int head = blockIdx.y;
    int bn   = blockIdx.z;
    int b    = bn / NBLK;
    int nb   = bn % NBLK;
    int q0   = qt * 64;
    int tid  = threadIdx.x;
    int lane = tid & 31;
    int warp = tid >> 5;
    int wq4 = warp & 3, wk2 = warp >> 2;
    int gid = lane >> 2, tig = lane & 3;
    int barid = 1 + wq4;

    const uint32_t* Qbase = Q + ((size_t)(b * LL + nb * WW + q0)) * DDIM + head * DH;
    #pragma unroll
    for (int i = 0; i < 4; i++) {
        int idx = tid + i * 256;
        int qi = idx >> 4, d4 = idx & 15;
        *(uint4*)&qsm[qi * QS_ST + d4 * 4] = *(const uint4*)&Qbase[(size_t)qi * DDIM + d4 * 4];
    }

    float m[8], l[8];
    #pragma unroll
    for (int i = 0; i < 8; i++) { m[i] = -1e30f; l[i] = 0.0f; }
    float ofr[4][4];
    #pragma unroll
    for (int t = 0; t < 4; t++)
        #pragma unroll
        for (int u = 0; u < 4; u++) ofr[t][u] = 0.0f;

    int lo = q0;
    if (nb == 0) lo = (lo > WW) ? lo : WW;
    int hi = q0 + 63 + WW;
    int cmin = lo >> 6, cmax = hi >> 6;

    float slope = exp2f(-2.0f * (float)(head + 1));
    const float scale = 0.125f;
    int kvbase = b * LL + nb * WW - WW;

    for (int c = cmin; c <= cmax; c++) {
        int kc0 = c * 64;
        __syncthreads();
        #pragma unroll
        for (int i = 0; i < 4; i++) {
            int idx = tid + i * 256;
            int kk = idx >> 4, d4 = idx & 15;
            size_t gro = ((size_t)(kvbase + kc0 + kk)) * DDIM + head * DH + d4 * 4;
            *(uint4*)&ksm[kk * KS_ST + d4 * 4] = *(const uint4*)&K[gro];
            *(uint4*)&vsm[kk * VS_ST + d4 * 4] = *(const uint4*)&V[gro];
        }
        __syncthreads();

        float cfr[4][4];
        #pragma unroll
        for (int t = 0; t < 4; t++)
            #pragma unroll
            for (int u = 0; u < 4; u++) cfr[t][u] = 0.0f;
        #pragma unroll
        for (int ks = 0; ks < 8; ks++) {
            int kb = ks * 8;
            int r0 = (wq4 * 16 + gid) * QS_ST + kb + tig;
            uint32_t af[4];
            af[0] = qsm[r0];
            af[1] = qsm[r0 + 8 * QS_ST];
            af[2] = qsm[r0 + 4];
            af[3] = qsm[r0 + 8 * QS_ST + 4];
            #pragma unroll
            for (int t = 0; t < 4; t++) {
                int col = wk2 * 32 + t * 8 + gid;
                uint32_t bf[2];
                bf[0] = ksm[col * KS_ST + kb + tig];
                bf[1] = ksm[col * KS_ST + kb + tig + 4];
                mma_tf32(cfr[t], af, bf);
            }
        }
        #pragma unroll
        for (int t = 0; t < 4; t++) {
            int klocal = wk2 * 32 + t * 8 + 2 * tig;
            int ka = kc0 + klocal, kb2 = ka + 1;
            #pragma unroll
            for (int half = 0; half < 2; half++) {
                int rloc = wq4 * 16 + gid + half * 8;
                int qg = q0 + rloc;
                bool oka = (ka >= qg) && (ka <= qg + WW) && (nb > 0 || ka >= WW);
                bool okb = (kb2 >= qg) && (kb2 <= qg + WW) && (nb > 0 || kb2 >= WW);
                float da = (float)(WW + qg - ka);
                float db = (float)(WW + qg - kb2);
                float sa = cfr[t][half * 2 + 0];
                float sb = cfr[t][half * 2 + 1];
                sa = oka ? (sa * scale - slope * da) : -1e30f;
                sb = okb ? (sb * scale - slope * db) : -1e30f;
                float2 st = {sa, sb};
                *(float2*)&((float*)ssm)[rloc * SS_ST + klocal] = st;
            }
        }
        BAR_PAIR(barid);

        #pragma unroll
        for (int qi = 0; qi < 8; qi++) {
            int q = wq4 * 16 + wk2 * 8 + qi;
            float s0 = ((float*)ssm)[q * SS_ST + lane];
            float s1 = ((float*)ssm)[q * SS_ST + lane + 32];
            float mx = fmaxf(s0, s1);
            #pragma unroll
            for (int off = 16; off; off >>= 1)
                mx = fmaxf(mx, __shfl_xor_sync(0xffffffffu, mx, off));
            float mn = fmaxf(m[qi], mx);
            float fac = (m[qi] > -1e29f) ? __expf(m[qi] - mn) : 0.0f;
            float p0 = (s0 > -1e29f) ? __expf(s0 - mn) : 0.0f;
            float p1 = (s1 > -1e29f) ? __expf(s1 - mn) : 0.0f;
            float ps = p0 + p1;
            #pragma unroll
            for (int off = 16; off; off >>= 1)
                ps += __shfl_xor_sync(0xffffffffu, ps, off);
            l[qi] = l[qi] * fac + ps;
            m[qi] = mn;
            ssm[q * SS_ST + lane] = f2tf32(p0);
            ssm[q * SS_ST + lane + 32] = f2tf32(p1);
            if (lane == 0) fsm[q] = fac;
        }
        BAR_PAIR(barid);

        {
            float fa = fsm[wq4 * 16 + gid];
            float fb = fsm[wq4 * 16 + gid + 8];
            #pragma unroll
            for (int t = 0; t < 4; t++) {
                ofr[t][0] *= fa; ofr[t][1] *= fa;
                ofr[t][2] *= fb; ofr[t][3] *= fb;
            }
            #pragma unroll
            for (int ks = 0; ks < 8; ks++) {
                int kb = ks * 8;
                int r0 = (wq4 * 16 + gid) * SS_ST + kb + tig;
                uint32_t af[4];
                af[0] = ssm[r0];
                af[1] = ssm[r0 + 8 * SS_ST];
                af[2] = ssm[r0 + 4];
                af[3] = ssm[r0 + 8 * SS_ST + 4];
                #pragma unroll
                for (int t = 0; t < 4; t++) {
                    int col = wk2 * 32 + t * 8 + gid;
                    uint32_t bf[2];
                    bf[0] = vsm[(kb + tig) * VS_ST + col];
                    bf[1] = vsm[(kb + tig + 4) * VS_ST + col];
                    mma_tf32(ofr[t], af, bf);
                }
            }
        }
    }

    if (lane == 0) {
        #pragma unroll
        for (int qi = 0; qi < 8; qi++) lsm[wq4 * 16 + wk2 * 8 + qi] = l[qi];
    }
    BAR_PAIR(barid);

    float ia = 1.0f / lsm[wq4 * 16 + gid];
    float ib = 1.0f / lsm[wq4 * 16 + gid + 8];
    size_t rowa = (size_t)(b * LL + nb * WW + q0 + wq4 * 16 + gid) * DDIM + head * DH;
    size_t rowb = rowa + 8 * DDIM;
    #pragma unroll
    for (int t = 0; t < 4; t++) {
        int col = wk2 * 32 + t * 8 + 2 * tig;
        uint2 oa = {f2tf32(ofr[t][0] * ia), f2tf32(ofr[t][1] * ia)};
        uint2 ob = {f2tf32(ofr[t][2] * ib), f2tf32(ofr[t][3] * ib)};
        *(uint2*)&O[rowa + col] = oa;
        *(uint2*)&O[rowb + col] = ob;
    }
}

// ---------------- head with fused final LayerNorm: warp per row, N=14 ----------------
__global__ void head_kernel(const float* __restrict__ x, const float* __restrict__ g,
                            const float* __restrict__ bb, const float* __restrict__ w,
                            float* __restrict__ out) {
    int row  = blockIdx.x * 8 + (threadIdx.x >> 5);
    int lane = threadIdx.x & 31;
    const float4* xr = (const float4*)(x + (size_t)row * DDIM);
    float4 v0 = xr[lane];
    float4 v1 = xr[lane + 32];
    float s  = v0.x + v0.y + v0.z + v0.w + v1.x + v1.y + v1.z + v1.w;
    float ss = v0.x*v0.x + v0.y*v0.y + v0.z*v0.z + v0.w*v0.w
             + v1.x*v1.x + v1.y*v1.y + v1.z*v1.z + v1.w*v1.w;
    #pragma unroll
    for (int off = 16; off; off >>= 1) {
        s  += __shfl_xor_sync(0xffffffffu, s,  off);
        ss += __shfl_xor_sync(0xffffffffu, ss, off);
    }
    float mean = s * (1.0f / DDIM);
    float var  = ss * (1.0f / DDIM) - mean * mean;
    float rstd = rsqrtf(var + 1e-5f);
    const float4* gp = (const float4*)g;
    const float4* bp = (const float4*)bb;
    float4 g0 = gp[lane], g1 = gp[lane + 32];
    float4 b0 = bp[lane], b1 = bp[lane + 32];
    float h[8];
    h[0] = (v0.x - mean) * rstd * g0.x + b0.x;
    h[1] = (v0.y - mean) * rstd * g0.y + b0.y;
    h[2] = (v0.z - mean) * rstd * g0.z + b0.z;
    h[3] = (v0.w - mean) * rstd * g0.w + b0.w;
    h[4] = (v1.x - mean) * rstd * g1.x + b1.x;
    h[5] = (v1.y - mean) * rstd * g1.y + b1.y;
    h[6] = (v1.z - mean) * rstd * g1.z + b1.z;
    h[7] = (v1.w - mean) * rstd * g1.w + b1.w;

    float acc[VV];
    #pragma unroll
    for (int c = 0; c < VV; c++) acc[c] = 0.0f;
    #pragma unroll
    for (int u = 0; u < 8; u++) {
        int d = (u < 4) ? (lane * 4 + u) : (128 + lane * 4 + (u - 4));
        const float* wr = w + d * VV;
        #pragma unroll
        for (int c = 0; c < VV; c++) acc[c] = fmaf(h[u], wr[c], acc[c]);
    }
    #pragma unroll
    for (int c = 0; c < VV; c++)
        #pragma unroll
        for (int off = 16; off; off >>= 1)
            acc[c] += __shfl_xor_sync(0xffffffffu, acc[c], off);
    if (lane < VV) out[(size_t)row * VV + lane] = acc[lane];
}

// ---------------- launch ----------------
extern "C" void kernel_launch(void* const* d_in, const int* in_sizes, int n_in,
                              void* d_out, int out_size) {
    const int*   byte_ids = (const int*)  d_in[0];
    const float* embed    = (const float*)d_in[1];
    const float* wq   = (const float*)d_in[2];
    const float* bq   = (const float*)d_in[3];
    const float* wk   = (const float*)d_in[4];
    const float* bk   = (const float*)d_in[5];
    const float* wv   = (const float*)d_in[6];
    const float* bv   = (const float*)d_in[7];
    const float* wo   = (const float*)d_in[8];
    const float* bo   = (const float*)d_in[9];
    const float* ln1g = (const float*)d_in[10];
    const float* ln1b = (const float*)d_in[11];
    const float* ln2g = (const float*)d_in[12];
    const float* ln2b = (const float*)d_in[13];
    const float* w1   = (const float*)d_in[14];
    const float* b1   = (const float*)d_in[15];
    const float* w2   = (const float*)d_in[16];
    const float* b2   = (const float*)d_in[17];
    const float* lnfg = (const float*)d_in[18];
    const float* lnfb = (const float*)d_in[19];
    const float* headw= (const float*)d_in[20];
    float* out = (float*)d_out;

    float *X;
    uint32_t *Hb, *Q, *K, *Vb, *O, *F;
    uint32_t *Wq, *Wk, *Wv, *Wo, *W1, *W2;
    cudaGetSymbolAddress((void**)&X,  g_X);
    cudaGetSymbolAddress((void**)&Hb, g_Hb);
    cudaGetSymbolAddress((void**)&Q,  g_Q);
    cudaGetSymbolAddress((void**)&K,  g_K);
    cudaGetSymbolAddress((void**)&Vb, g_V);
    cudaGetSymbolAddress((void**)&O,  g_O);
    cudaGetSymbolAddress((void**)&F,  g_F);
    cudaGetSymbolAddress((void**)&Wq, g_Wq);
    cudaGetSymbolAddress((void**)&Wk, g_Wk);
    cudaGetSymbolAddress((void**)&Wv, g_Wv);
    cudaGetSymbolAddress((void**)&Wo, g_Wo);
    cudaGetSymbolAddress((void**)&W1, g_W1);
    cudaGetSymbolAddress((void**)&W2, g_W2);

    cudaFuncSetAttribute(attn_kernel, cudaFuncAttributeMaxDynamicSharedMemorySize, ATSM_BYTES);
    cudaFuncSetAttribute(qkv_cp, cudaFuncAttributeMaxDynamicSharedMemorySize, GSM_BYTES);
    cudaFuncSetAttribute(gemm_cp<false,true ,false>, cudaFuncAttributeMaxDynamicSharedMemorySize, GSM_BYTES);
    cudaFuncSetAttribute(gemm_cp<true ,false,true >, cudaFuncAttributeMaxDynamicSharedMemorySize, GSM_BYTES);

    // pre-convert all weights to tf32 bits (one launch)
    {
        int tot4 = 4 * NDD + 2 * NDF;
        cvtw_all<<<(tot4 + 255) / 256, 256>>>(wq, wk, wv, wo, w1, w2);
    }

    embed_kernel<<<BL * 64 / 256, 256>>>(byte_ids, embed, X);

    dim3 gQKV(6, BL / 128);
    dim3 gD(DDIM / 128, BL / 128);
    dim3 gF(FFD / 128,  BL / 128);
    dim3 gA(8, HH, BB * NBLK);
    const size_t SMB = GSM_BYTES;

    for (int l = 0; l < NLAYER; l++) {
        ln_kernel<<<BL / 8, 256>>>(X, ln1g + l * DDIM, ln1b + l * DDIM, Hb);
        qkv_cp<<<gQKV, 256, SMB>>>(Hb,
            Wq + (size_t)l * DDIM * DDIM, Wk + (size_t)l * DDIM * DDIM, Wv + (size_t)l * DDIM * DDIM,
            bq + l * DDIM, bk + l * DDIM, bv + l * DDIM, Q, K, Vb);
        attn_kernel<<<gA, 256, ATSM_BYTES>>>(Q, K, Vb, O);
        gemm_cp<false, true , false><<<gD, 256, SMB>>>(O, Wo + (size_t)l * DDIM * DDIM, bo + l * DDIM, X, X, DDIM, DDIM);
        ln_kernel<<<BL / 8, 256>>>(X, ln2g + l * DDIM, ln2b + l * DDIM, Hb);
        gemm_cp<true , false, true ><<<gF, 256, SMB>>>(Hb, W1 + (size_t)l * DDIM * FFD, b1 + l * FFD, nullptr, F, FFD, DDIM);
        gemm_cp<false, true , false><<<gD, 256, SMB>>>(F, W2 + (size_t)l * FFD * DDIM, b2 + l * DDIM, X, X, DDIM, FFD);
    }
    head_kernel<<<BL / 8, 256>>>(X, lnfg, lnfb, headw, out);
}

// round 16
// speedup vs baseline: 1.6544x; 1.0230x over previous
#include <cuda_runtime.h>
#include <math.h>
#include <stdint.h>

#define BB 4
#define LL 8192
#define DDIM 256
#define HH 4
#define NLAYER 4
#define FFD 1024
#define WW 512
#define VV 14
#define DH 64
#define BL (BB*LL)     /* 32768 rows */
#define NBLK (LL/WW)   /* 16 windows per sequence */

// ---------------- scratch (static device globals; no allocations) ----------------
__device__ float    g_X [BL*DDIM];     // residual (fp32)
__device__ uint32_t g_Hb[BL*DDIM];     // LN output (tf32 bits)
__device__ uint32_t g_Q [BL*DDIM];     // tf32 bits
__device__ uint32_t g_K [BL*DDIM];     // tf32 bits
__device__ uint32_t g_V [BL*DDIM];     // tf32 bits
__device__ uint32_t g_O [BL*DDIM];     // attention out (tf32 bits)
__device__ uint32_t g_F [BL*FFD];      // FFN hidden (tf32 bits)
// converted weights, TRANSPOSED to [n][k] (tf32 bits)
__device__ uint32_t g_Wq[NLAYER*DDIM*DDIM];
__device__ uint32_t g_Wk[NLAYER*DDIM*DDIM];
__device__ uint32_t g_Wv[NLAYER*DDIM*DDIM];
__device__ uint32_t g_Wo[NLAYER*DDIM*DDIM];
__device__ uint32_t g_W1[NLAYER*DDIM*FFD];
__device__ uint32_t g_W2[NLAYER*FFD*DDIM];

__device__ __forceinline__ uint32_t f2tf32(float x) {
    uint32_t r;
    asm("cvt.rna.tf32.f32 %0, %1;" : "=r"(r) : "f"(x));
    return r;
}
__device__ __forceinline__ void mma_tf32(float* c, const uint32_t* a, const uint32_t* b) {
    asm volatile(
        "mma.sync.aligned.m16n8k8.row.col.f32.tf32.tf32.f32 "
        "{%0,%1,%2,%3}, {%4,%5,%6,%7}, {%8,%9}, {%0,%1,%2,%3};"
        : "+f"(c[0]), "+f"(c[1]), "+f"(c[2]), "+f"(c[3])
        : "r"(a[0]), "r"(a[1]), "r"(a[2]), "r"(a[3]), "r"(b[0]), "r"(b[1]));
}
__device__ __forceinline__ void ldsm_x4(uint32_t* r, uint32_t addr) {
    asm volatile("ldmatrix.sync.aligned.m8n8.x4.shared.b16 {%0,%1,%2,%3}, [%4];"
        : "=r"(r[0]), "=r"(r[1]), "=r"(r[2]), "=r"(r[3]) : "r"(addr));
}
__device__ __forceinline__ uint32_t smem_u32(const void* p) {
    uint32_t a;
    asm("{ .reg .u64 t; cvta.to.shared.u64 t, %1; cvt.u32.u64 %0, t; }" : "=r"(a) : "l"(p));
    return a;
}
__device__ __forceinline__ void cp16(uint32_t s, const void* g) {
    asm volatile("cp.async.cg.shared.global [%0], [%1], 16;" :: "r"(s), "l"(g));
}
#define CP_COMMIT() asm volatile("cp.async.commit_group;" ::: "memory")
#define CP_WAIT1()  asm volatile("cp.async.wait_group 1;" ::: "memory")
#define BAR_PAIR(id) asm volatile("bar.sync %0, 64;" :: "r"(id) : "memory")

// ---------------- fused weight tf32 convert + TRANSPOSE ([k][n] -> [n][k]) ----------------
// grid: 3072 blocks of 256 threads; 32x32 tiles via 32x33 smem.
__global__ void cvtw_t(const float* __restrict__ wq, const float* __restrict__ wk,
                       const float* __restrict__ wv, const float* __restrict__ wo,
                       const float* __restrict__ w1, const float* __restrict__ w2) {
    __shared__ uint32_t t[32][33];
    int bid = blockIdx.x;
    const float* src;
    uint32_t* dst;
    int Kd, Nd, layer, tk, tn;
    if (bid < 1024) {
        int mat = bid >> 8, rem = bid & 255;
        layer = rem >> 6;
        int tile = rem & 63;
        tk = tile >> 3; tn = tile & 7;
        Kd = DDIM; Nd = DDIM;
        src = (mat == 0) ? wq : (mat == 1) ? wk : (mat == 2) ? wv : wo;
        dst = (mat == 0) ? g_Wq : (mat == 1) ? g_Wk : (mat == 2) ? g_Wv : g_Wo;
    } else if (bid < 2048) {
        int rem = bid - 1024;
        layer = rem >> 8;
        int tile = rem & 255;
        tk = tile >> 5; tn = tile & 31;     // K=256 (8 tiles), N=1024 (32 tiles)
        Kd = DDIM; Nd = FFD;
        src = w1; dst = g_W1;
    } else {
        int rem = bid - 2048;
        layer = rem >> 8;
        int tile = rem & 255;
        tk = tile >> 3; tn = tile & 7;      // K=1024 (32 tiles), N=256 (8 tiles)
        Kd = FFD; Nd = DDIM;
        src = w2; dst = g_W2;
    }
    src += (size_t)layer * Kd * Nd;
    dst += (size_t)layer * Kd * Nd;
    int k0 = tk * 32, n0 = tn * 32;
    int tx = threadIdx.x & 31, ty = threadIdx.x >> 5;   // 32 x 8
    #pragma unroll
    for (int j = 0; j < 4; j++)
        t[ty + 8 * j][tx] = f2tf32(src[(size_t)(k0 + ty + 8 * j) * Nd + n0 + tx]);
    __syncthreads();
    #pragma unroll
    for (int j = 0; j < 4; j++)
        dst[(size_t)(n0 + ty + 8 * j) * Kd + k0 + tx] = t[tx][ty + 8 * j];
}

// ---------------- embedding gather ----------------
__global__ void embed_kernel(const int* __restrict__ ids, const float* __restrict__ emb,
                             float* __restrict__ x) {
    int i = blockIdx.x * blockDim.x + threadIdx.x;
    int row = i >> 6;
    int d4  = i & 63;
    int id  = ids[row];
    ((float4*)x)[i] = ((const float4*)emb)[id * 64 + d4];
}

// ---------------- LayerNorm -> tf32 bits ----------------
__global__ void ln_kernel(const float* __restrict__ x, const float* __restrict__ g,
                          const float* __restrict__ b, uint32_t* __restrict__ outv) {
    int row  = blockIdx.x * 8 + (threadIdx.x >> 5);
    int lane = threadIdx.x & 31;
    const float4* xr = (const float4*)(x + (size_t)row * DDIM);
    float4 v0 = xr[lane];
    float4 v1 = xr[lane + 32];
    float s  = v0.x + v0.y + v0.z + v0.w + v1.x + v1.y + v1.z + v1.w;
    float ss = v0.x*v0.x + v0.y*v0.y + v0.z*v0.z + v0.w*v0.w
             + v1.x*v1.x + v1.y*v1.y + v1.z*v1.z + v1.w*v1.w;
    #pragma unroll
    for (int off = 16; off; off >>= 1) {
        s  += __shfl_xor_sync(0xffffffffu, s,  off);
        ss += __shfl_xor_sync(0xffffffffu, ss, off);
    }
    float mean = s * (1.0f / DDIM);
    float var  = ss * (1.0f / DDIM) - mean * mean;
    float rstd = rsqrtf(var + 1e-5f);
    const float4* gp = (const float4*)g;
    const float4* bp = (const float4*)b;
    float4 g0 = gp[lane], g1 = gp[lane + 32];
    float4 b0 = bp[lane], b1 = bp[lane + 32];
    uint4* op = (uint4*)(outv + (size_t)row * DDIM);
    uint4 t0, t1;
    t0.x = f2tf32((v0.x - mean) * rstd * g0.x + b0.x);
    t0.y = f2tf32((v0.y - mean) * rstd * g0.y + b0.y);
    t0.z = f2tf32((v0.z - mean) * rstd * g0.z + b0.z);
    t0.w = f2tf32((v0.w - mean) * rstd * g0.w + b0.w);
    t1.x = f2tf32((v1.x - mean) * rstd * g1.x + b1.x);
    t1.y = f2tf32((v1.y - mean) * rstd * g1.y + b1.y);
    t1.z = f2tf32((v1.z - mean) * rstd * g1.z + b1.z);
    t1.w = f2tf32((v1.w - mean) * rstd * g1.w + b1.w);
    op[lane] = t0;
    op[lane + 32] = t1;
}

__device__ __forceinline__ float gelu_tanh(float x) {
    float t = tanhf(0.7978845608028654f * (x + 0.044715f * x * x * x));
    return 0.5f * x * (1.0f + t);
}

// ================= tf32 GEMM core: 3-stage cp.async + ldmatrix fragments =================
// A [m][k] stride 36; B (W^T) [n][k] stride 36. BM=BN=128, BK=32.
#define AS_ST 36
#define ABUF (128*AS_ST)
#define STG_U32 (2*ABUF)
#define GSM_BYTES (3 * STG_U32 * 4)   /* 110592 B -> 2 CTAs/SM */

template<bool GELU, bool RES, bool OUT32>
__device__ __forceinline__ void gemm_core(
        const uint32_t* __restrict__ A, const uint32_t* __restrict__ Wt,
        const float* __restrict__ bias, const float* __restrict__ Res,
        void* __restrict__ Cv, int N, int K, int m0, int n0, uint32_t* smu) {
    const uint32_t smb = smem_u32(smu);
    int tid = threadIdx.x, lane = tid & 31, wid = tid >> 5;
    int wm = wid & 3, wn = wid >> 2;
    int gid = lane >> 2, tig = lane & 3;

    // cp.async coords (shared by A and B tiles: row = idx>>3, kquad = idx&7)
    int amm[4], akq[4];
    uint32_t adst[4];
    #pragma unroll
    for (int i = 0; i < 4; i++) {
        int idx = tid + i * 256;
        amm[i] = idx >> 3; akq[i] = idx & 7;
        adst[i] = (uint32_t)(amm[i] * AS_ST + akq[i] * 4) * 4;
    }

    // ldmatrix per-thread byte offsets within a stage
    int lr = lane & 7;
    uint32_t aoff[2], boff[4];
    {
        int a_row = (lane >> 3) & 1;       // +8 rows for tiles 1,3
        int a_k   = (lane >> 4);           // +4 k for tiles 2,3
        #pragma unroll
        for (int tm = 0; tm < 2; tm++)
            aoff[tm] = (uint32_t)(((wm * 32 + tm * 16 + lr + a_row * 8) * AS_ST) + a_k * 4) * 4;
        int b_n = (lane >> 4);             // +8 n for tiles 2,3
        int b_k = (lane >> 3) & 1;         // +4 k for tiles 1,3
        #pragma unroll
        for (int p = 0; p < 4; p++)
            boff[p] = (uint32_t)(((wn * 64 + p * 16 + lr + b_n * 8) * AS_ST) + b_k * 4) * 4;
    }

    float acc[2][8][4];
    #pragma unroll
    for (int i = 0; i < 2; i++)
        #pragma unroll
        for (int j = 0; j < 8; j++)
            #pragma unroll
            for (int u = 0; u < 4; u++) acc[i][j][u] = 0.0f;

    int nch = K >> 5;
    // prologue: stages 0,1
    #pragma unroll
    for (int st = 0; st < 2; st++) {
        uint32_t base = smb + st * STG_U32 * 4;
        int k0 = st << 5;
        #pragma unroll
        for (int i = 0; i < 4; i++) {
            cp16(base + adst[i], &A[(size_t)(m0 + amm[i]) * K + k0 + akq[i] * 4]);
            cp16(base + ABUF * 4 + adst[i], &Wt[(size_t)(n0 + amm[i]) * K + k0 + akq[i] * 4]);
        }
        CP_COMMIT();
    }

    int stage = 0;
    for (int kc = 0; kc < nch; kc++) {
        CP_WAIT1();
        __syncthreads();
        int pre = kc + 2;
        if (pre < nch) {
            int pst = pre % 3;
            uint32_t base = smb + pst * STG_U32 * 4;
            int k0 = pre << 5;
            #pragma unroll
            for (int i = 0; i < 4; i++) {
                cp16(base + adst[i], &A[(size_t)(m0 + amm[i]) * K + k0 + akq[i] * 4]);
                cp16(base + ABUF * 4 + adst[i], &Wt[(size_t)(n0 + amm[i]) * K + k0 + akq[i] * 4]);
            }
        }
        CP_COMMIT();

        uint32_t aBase = smb + stage * STG_U32 * 4;
        uint32_t bBase = aBase + ABUF * 4;
        #pragma unroll
        for (int ks = 0; ks < 4; ks++) {
            uint32_t kbb = ks * 32;        // kb*4 bytes (kb = ks*8 cols)
            uint32_t afr[2][4];
            ldsm_x4(afr[0], aBase + aoff[0] + kbb);
            ldsm_x4(afr[1], aBase + aoff[1] + kbb);
            uint32_t bfr[4][4];
            #pragma unroll
            for (int p = 0; p < 4; p++)
                ldsm_x4(bfr[p], bBase + boff[p] + kbb);
            #pragma unroll
            for (int tm = 0; tm < 2; tm++)
                #pragma unroll
                for (int p = 0; p < 4; p++) {
                    mma_tf32(acc[tm][2 * p],     afr[tm], &bfr[p][0]);
                    mma_tf32(acc[tm][2 * p + 1], afr[tm], &bfr[p][2]);
                }
        }
        stage = (stage + 1 == 3) ? 0 : stage + 1;
    }

    float* Cf = (float*)Cv;
    uint32_t* C32 = (uint32_t*)Cv;
    #pragma unroll
    for (int tm = 0; tm < 2; tm++) {
        int row = m0 + wm * 32 + tm * 16 + gid;
        #pragma unroll
        for (int tn = 0; tn < 8; tn++) {
            int col = n0 + wn * 64 + tn * 8 + tig * 2;
            float b0 = bias[col], b1 = bias[col + 1];
            #pragma unroll
            for (int half = 0; half < 2; half++) {
                int r = row + half * 8;
                float v0 = acc[tm][tn][half * 2 + 0] + b0;
                float v1 = acc[tm][tn][half * 2 + 1] + b1;
                if (GELU) { v0 = gelu_tanh(v0); v1 = gelu_tanh(v1); }
                size_t off = (size_t)r * N + col;
                if (RES) {
                    float2 rr = *(const float2*)&Res[off];
                    v0 += rr.x; v1 += rr.y;
                }
                if (OUT32) {
                    uint2 o = {f2tf32(v0), f2tf32(v1)};
                    *(uint2*)&C32[off] = o;
                } else {
                    float2 o = {v0, v1};
                    *(float2*)&Cf[off] = o;
                }
            }
        }
    }
}

template<bool GELU, bool RES, bool OUT32>
__global__ void __launch_bounds__(256, 2) gemm_cp(
        const uint32_t* __restrict__ A, const uint32_t* __restrict__ Wt,
        const float* __restrict__ bias, const float* __restrict__ Res,
        void* __restrict__ Cv, int N, int K) {
    extern __shared__ uint32_t smu[];
    gemm_core<GELU, RES, OUT32>(A, Wt, bias, Res, Cv, N, K,
                                blockIdx.y * 128, blockIdx.x * 128, smu);
}

// fused QKV: grid.x = 6 -> (mat 0..2) x (n-half 0..1)
__global__ void __launch_bounds__(256, 2) qkv_cp(
        const uint32_t* __restrict__ A,
        const uint32_t* __restrict__ Wq, const uint32_t* __restrict__ Wk, const uint32_t* __restrict__ Wv,
        const float* __restrict__ bq, const float* __restrict__ bk, const float* __restrict__ bv,
        uint32_t* __restrict__ Q, uint32_t* __restrict__ K, uint32_t* __restrict__ V) {
    extern __shared__ uint32_t smu[];
    int mat = blockIdx.x >> 1;
    const uint32_t* W = (mat == 0) ? Wq : (mat == 1) ? Wk : Wv;
    const float* bias = (mat == 0) ? bq : (mat == 1) ? bk : bv;
    uint32_t* C = (mat == 0) ? Q : (mat == 1) ? K : V;
    gemm_core<false, false, true>(A, W, bias, nullptr, C, DDIM, DDIM,
                                  blockIdx.y * 128, (blockIdx.x & 1) * 128, smu);
}

// ---------------- fused attention: QK^T and PV via tf32 MMA, pair-scoped barriers ----------------
#define QS_ST 68
#define KS_ST 68
#define VS_ST 72
#define SS_ST 68
#define ATSM_U32 (64*QS_ST + 64*KS_ST + 64*VS_ST + 64*SS_ST + 128)
#define ATSM_BYTES (ATSM_U32 * 4)

__global__ void attn_kernel(const uint32_t* __restrict__ Q, const uint32_t* __restrict__ K,
                            const uint32_t* __restrict__ V, uint32_t* __restrict__ O) {
    extern __shared__ uint32_t smu[];
    uint32_t* qsm = smu;                        // [64][68]
    uint32_t* ksm = qsm + 64 * QS_ST;           // [64][68] rows = keys
    uint32_t* vsm = ksm + 64 * KS_ST;           // [64][72] rows = keys
    uint32_t* ssm = vsm + 64 * VS_ST;           // [64][68] float scores -> tf32 P bits
    float*    fsm = (float*)(ssm + 64 * SS_ST); // [64] fac
    float*    lsm = fsm + 64;                   // [64] l

    int qt   = blockIdx.x;
    int head = blockIdx.y;
    int bn   = blockIdx.z;
    int b    = bn / NBLK;
    int nb   = bn % NBLK;
    int q0   = qt * 64;
    int tid  = threadIdx.x;
    int lane = tid & 31;
    int warp = tid >> 5;
    int wq4 = warp & 3, wk2 = warp >> 2;
    int gid = lane >> 2, tig = lane & 3;
    int barid = 1 + wq4;

    const uint32_t* Qbase = Q + ((size_t)(b * LL + nb * WW + q0)) * DDIM + head * DH;
    #pragma unroll
    for (int i = 0; i < 4; i++) {
        int idx = tid + i * 256;
        int qi = idx >> 4, d4 = idx & 15;
        *(uint4*)&qsm[qi * QS_ST + d4 * 4] = *(const uint4*)&Qbase[(size_t)qi * DDIM + d4 * 4];
    }

    float m[8], l[8];
    #pragma unroll
    for (int i = 0; i < 8; i++) { m[i] = -1e30f; l[i] = 0.0f; }
    float ofr[4][4];
    #pragma unroll
    for (int t = 0; t < 4; t++)
        #pragma unroll
        for (int u = 0; u < 4; u++) ofr[t][u] = 0.0f;

    int lo = q0;
    if (nb == 0) lo = (lo > WW) ? lo : WW;
    int hi = q0 + 63 + WW;
    int cmin = lo >> 6, cmax = hi >> 6;

    float slope = exp2f(-2.0f * (float)(head + 1));
    const float scale = 0.125f;
    int kvbase = b * LL + nb * WW - WW;

    for (int c = cmin; c <= cmax; c++) {
        int kc0 = c * 64;
        __syncthreads();
        #pragma unroll
        for (int i = 0; i < 4; i++) {
            int idx = tid + i * 256;
            int kk = idx >> 4, d4 = idx & 15;
            size_t gro = ((size_t)(kvbase + kc0 + kk)) * DDIM + head * DH + d4 * 4;
            *(uint4*)&ksm[kk * KS_ST + d4 * 4] = *(const uint4*)&K[gro];
            *(uint4*)&vsm[kk * VS_ST + d4 * 4] = *(const uint4*)&V[gro];
        }
        __syncthreads();

        float cfr[4][4];
        #pragma unroll
        for (int t = 0; t < 4; t++)
            #pragma unroll
            for (int u = 0; u < 4; u++) cfr[t][u] = 0.0f;
        #pragma unroll
        for (int ks = 0; ks < 8; ks++) {
            int kb = ks * 8;
            int r0 = (wq4 * 16 + gid) * QS_ST + kb + tig;
            uint32_t af[4];
            af[0] = qsm[r0];
            af[1] = qsm[r0 + 8 * QS_ST];
            af[2] = qsm[r0 + 4];
            af[3] = qsm[r0 + 8 * QS_ST + 4];
            #pragma unroll
            for (int t = 0; t < 4; t++) {
                int col = wk2 * 32 + t * 8 + gid;
                uint32_t bf[2];
                bf[0] = ksm[col * KS_ST + kb + tig];
                bf[1] = ksm[col * KS_ST + kb + tig + 4];
                mma_tf32(cfr[t], af, bf);
            }
        }
        #pragma unroll
        for (int t = 0; t < 4; t++) {
            int klocal = wk2 * 32 + t * 8 + 2 * tig;
            int ka = kc0 + klocal, kb2 = ka + 1;
            #pragma unroll
            for (int half = 0; half < 2; half++) {
                int rloc = wq4 * 16 + gid + half * 8;
                int qg = q0 + rloc;
                bool oka = (ka >= qg) && (ka <= qg + WW) && (nb > 0 || ka >= WW);
                bool okb = (kb2 >= qg) && (kb2 <= qg + WW) && (nb > 0 || kb2 >= WW);
                float da = (float)(WW + qg - ka);
                float db = (float)(WW + qg - kb2);
                float sa = cfr[t][half * 2 + 0];
                float sb = cfr[t][half * 2 + 1];
                sa = oka ? (sa * scale - slope * da) : -1e30f;
                sb = okb ? (sb * scale - slope * db) : -1e30f;
                float2 st = {sa, sb};
                *(float2*)&((float*)ssm)[rloc * SS_ST + klocal] = st;
            }
        }
        BAR_PAIR(barid);

        #pragma unroll
        for (int qi = 0; qi < 8; qi++) {
            int q = wq4 * 16 + wk2 * 8 + qi;
            float s0 = ((float*)ssm)[q * SS_ST + lane];
            float s1 = ((float*)ssm)[q * SS_ST + lane + 32];
            float mx = fmaxf(s0, s1);
            #pragma unroll
            for (int off = 16; off; off >>= 1)
                mx = fmaxf(mx, __shfl_xor_sync(0xffffffffu, mx, off));
            float mn = fmaxf(m[qi], mx);
            float fac = (m[qi] > -1e29f) ? __expf(m[qi] - mn) : 0.0f;
            float p0 = (s0 > -1e29f) ? __expf(s0 - mn) : 0.0f;
            float p1 = (s1 > -1e29f) ? __expf(s1 - mn) : 0.0f;
            float ps = p0 + p1;
            #pragma unroll
            for (int off = 16; off; off >>= 1)
                ps += __shfl_xor_sync(0xffffffffu, ps, off);
            l[qi] = l[qi] * fac + ps;
            m[qi] = mn;
            ssm[q * SS_ST + lane] = f2tf32(p0);
            ssm[q * SS_ST + lane + 32] = f2tf32(p1);
            if (lane == 0) fsm[q] = fac;
        }
        BAR_PAIR(barid);

        {
            float fa = fsm[wq4 * 16 + gid];
            float fb = fsm[wq4 * 16 + gid + 8];
            #pragma unroll
            for (int t = 0; t < 4; t++) {
                ofr[t][0] *= fa; ofr[t][1] *= fa;
                ofr[t][2] *= fb; ofr[t][3] *= fb;
            }
            #pragma unroll
            for (int ks = 0; ks < 8; ks++) {
                int kb = ks * 8;
                int r0 = (wq4 * 16 + gid) * SS_ST + kb + tig;
                uint32_t af[4];
                af[0] = ssm[r0];
                af[1] = ssm[r0 + 8 * SS_ST];
                af[2] = ssm[r0 + 4];
                af[3] = ssm[r0 + 8 * SS_ST + 4];
                #pragma unroll
                for (int t = 0; t < 4; t++) {
                    int col = wk2 * 32 + t * 8 + gid;
                    uint32_t bf[2];
                    bf[0] = vsm[(kb + tig) * VS_ST + col];
                    bf[1] = vsm[(kb + tig + 4) * VS_ST + col];
                    mma_tf32(ofr[t], af, bf);
                }
            }
        }
    }

    if (lane == 0) {
        #pragma unroll
        for (int qi = 0; qi < 8; qi++) lsm[wq4 * 16 + wk2 * 8 + qi] = l[qi];
    }
    BAR_PAIR(barid);

    float ia = 1.0f / lsm[wq4 * 16 + gid];
    float ib = 1.0f / lsm[wq4 * 16 + gid + 8];
    size_t rowa = (size_t)(b * LL + nb * WW + q0 + wq4 * 16 + gid) * DDIM + head * DH;
    size_t rowb = rowa + 8 * DDIM;
    #pragma unroll
    for (int t = 0; t < 4; t++) {
        int col = wk2 * 32 + t * 8 + 2 * tig;
        uint2 oa = {f2tf32(ofr[t][0] * ia), f2tf32(ofr[t][1] * ia)};
        uint2 ob = {f2tf32(ofr[t][2] * ib), f2tf32(ofr[t][3] * ib)};
        *(uint2*)&O[rowa + col] = oa;
        *(uint2*)&O[rowb + col] = ob;
    }
}

// ---------------- head with fused final LayerNorm: warp per row, N=14 ----------------
__global__ void head_kernel(const float* __restrict__ x, const float* __restrict__ g,
                            const float* __restrict__ bb, const float* __restrict__ w,
                            float* __restrict__ out) {
    int row  = blockIdx.x * 8 + (threadIdx.x >> 5);
    int lane = threadIdx.x & 31;
    const float4* xr = (const float4*)(x + (size_t)row * DDIM);
    float4 v0 = xr[lane];
    float4 v1 = xr[lane + 32];
    float s  = v0.x + v0.y + v0.z + v0.w + v1.x + v1.y + v1.z + v1.w;
    float ss = v0.x*v0.x + v0.y*v0.y + v0.z*v0.z + v0.w*v0.w
             + v1.x*v1.x + v1.y*v1.y + v1.z*v1.z + v1.w*v1.w;
    #pragma unroll
    for (int off = 16; off; off >>= 1) {
        s  += __shfl_xor_sync(0xffffffffu, s,  off);
        ss += __shfl_xor_sync(0xffffffffu, ss, off);
    }
    float mean = s * (1.0f / DDIM);
    float var  = ss * (1.0f / DDIM) - mean * mean;
    float rstd = rsqrtf(var + 1e-5f);
    const float4* gp = (const float4*)g;
    const float4* bp = (const float4*)bb;
    float4 g0 = gp[lane], g1 = gp[lane + 32];
    float4 b0 = bp[lane], b1 = bp[lane + 32];
    float h[8];
    h[0] = (v0.x - mean) * rstd * g0.x + b0.x;
    h[1] = (v0.y - mean) * rstd * g0.y + b0.y;
    h[2] = (v0.z - mean) * rstd * g0.z + b0.z;
    h[3] = (v0.w - mean) * rstd * g0.w + b0.w;
    h[4] = (v1.x - mean) * rstd * g1.x + b1.x;
    h[5] = (v1.y - mean) * rstd * g1.y + b1.y;
    h[6] = (v1.z - mean) * rstd * g1.z + b1.z;
    h[7] = (v1.w - mean) * rstd * g1.w + b1.w;

    float acc[VV];
    #pragma unroll
    for (int c = 0; c < VV; c++) acc[c] = 0.0f;
    #pragma unroll
    for (int u = 0; u < 8; u++) {
        int d = (u < 4) ? (lane * 4 + u) : (128 + lane * 4 + (u - 4));
        const float* wr = w + d * VV;
        #pragma unroll
        for (int c = 0; c < VV; c++) acc[c] = fmaf(h[u], wr[c], acc[c]);
    }
    #pragma unroll
    for (int c = 0; c < VV; c++)
        #pragma unroll
        for (int off = 16; off; off >>= 1)
            acc[c] += __shfl_xor_sync(0xffffffffu, acc[c], off);
    if (lane < VV) out[(size_t)row * VV + lane] = acc[lane];
}

// ---------------- launch ----------------
extern "C" void kernel_launch(void* const* d_in, const int* in_sizes, int n_in,
                              void* d_out, int out_size) {
    const int*   byte_ids = (const int*)  d_in[0];
    const float* embed    = (const float*)d_in[1];
    const float* wq   = (const float*)d_in[2];
    const float* bq   = (const float*)d_in[3];
    const float* wk   = (const float*)d_in[4];
    const float* bk   = (const float*)d_in[5];
    const float* wv   = (const float*)d_in[6];
    const float* bv   = (const float*)d_in[7];
    const float* wo   = (const float*)d_in[8];
    const float* bo   = (const float*)d_in[9];
    const float* ln1g = (const float*)d_in[10];
    const float* ln1b = (const float*)d_in[11];
    const float* ln2g = (const float*)d_in[12];
    const float* ln2b = (const float*)d_in[13];
    const float* w1   = (const float*)d_in[14];
    const float* b1   = (const float*)d_in[15];
    const float* w2   = (const float*)d_in[16];
    const float* b2   = (const float*)d_in[17];
    const float* lnfg = (const float*)d_in[18];
    const float* lnfb = (const float*)d_in[19];
    const float* headw= (const float*)d_in[20];
    float* out = (float*)d_out;

    float *X;
    uint32_t *Hb, *Q, *K, *Vb, *O, *F;
    uint32_t *Wq, *Wk, *Wv, *Wo, *W1, *W2;
    cudaGetSymbolAddress((void**)&X,  g_X);
    cudaGetSymbolAddress((void**)&Hb, g_Hb);
    cudaGetSymbolAddress((void**)&Q,  g_Q);
    cudaGetSymbolAddress((void**)&K,  g_K);
    cudaGetSymbolAddress((void**)&Vb, g_V);
    cudaGetSymbolAddress((void**)&O,  g_O);
    cudaGetSymbolAddress((void**)&F,  g_F);
    cudaGetSymbolAddress((void**)&Wq, g_Wq);
    cudaGetSymbolAddress((void**)&Wk, g_Wk);
    cudaGetSymbolAddress((void**)&Wv, g_Wv);
    cudaGetSymbolAddress((void**)&Wo, g_Wo);
    cudaGetSymbolAddress((void**)&W1, g_W1);
    cudaGetSymbolAddress((void**)&W2, g_W2);

    cudaFuncSetAttribute(attn_kernel, cudaFuncAttributeMaxDynamicSharedMemorySize, ATSM_BYTES);
    cudaFuncSetAttribute(qkv_cp, cudaFuncAttributeMaxDynamicSharedMemorySize, GSM_BYTES);
    cudaFuncSetAttribute(gemm_cp<false,true ,false>, cudaFuncAttributeMaxDynamicSharedMemorySize, GSM_BYTES);
    cudaFuncSetAttribute(gemm_cp<true ,false,true >, cudaFuncAttributeMaxDynamicSharedMemorySize, GSM_BYTES);

    // pre-convert + transpose all weights to tf32 [n][k] (one launch)
    cvtw_t<<<3072, 256>>>(wq, wk, wv, wo, w1, w2);

    embed_kernel<<<BL * 64 / 256, 256>>>(byte_ids, embed, X);

    dim3 gQKV(6, BL / 128);
    dim3 gD(DDIM / 128, BL / 128);
    dim3 gF(FFD / 128,  BL / 128);
    dim3 gA(8, HH, BB * NBLK);
    const size_t SMB = GSM_BYTES;

    for (int l = 0; l < NLAYER; l++) {
        ln_kernel<<<BL / 8, 256>>>(X, ln1g + l * DDIM, ln1b + l * DDIM, Hb);
        qkv_cp<<<gQKV, 256, SMB>>>(Hb,
            Wq + (size_t)l * DDIM * DDIM, Wk + (size_t)l * DDIM * DDIM, Wv + (size_t)l * DDIM * DDIM,
            bq + l * DDIM, bk + l * DDIM, bv + l * DDIM, Q, K, Vb);
        attn_kernel<<<gA, 256, ATSM_BYTES>>>(Q, K, Vb, O);
        gemm_cp<false, true , false><<<gD, 256, SMB>>>(O, Wo + (size_t)l * DDIM * DDIM, bo + l * DDIM, X, X, DDIM, DDIM);
        ln_kernel<<<BL / 8, 256>>>(X, ln2g + l * DDIM, ln2b + l * DDIM, Hb);
        gemm_cp<true , false, true ><<<gF, 256, SMB>>>(Hb, W1 + (size_t)l * DDIM * FFD, b1 + l * FFD, nullptr, F, FFD, DDIM);
        gemm_cp<false, true , false><<<gD, 256, SMB>>>(F, W2 + (size_t)l * FFD * DDIM, b2 + l * DDIM, X, X, DDIM, FFD);
    }
    head_kernel<<<BL / 8, 256>>>(X, lnfg, lnfb, headw, out);
}

// round 17
// speedup vs baseline: 1.9074x; 1.1529x over previous
#include <cuda_runtime.h>
#include <math.h>
#include <stdint.h>

#define BB 4
#define LL 8192
#define DDIM 256
#define HH 4
#define NLAYER 4
#define FFD 1024
#define WW 512
#define VV 14
#define DH 64
#define BL (BB*LL)     /* 32768 rows */
#define NBLK (LL/WW)   /* 16 windows per sequence */

// ---------------- scratch (static device globals; no allocations) ----------------
__device__ float    g_X [BL*DDIM];     // residual (fp32)
__device__ uint32_t g_Hb[BL*DDIM];     // LN output (tf32 bits)
__device__ uint32_t g_Q [BL*DDIM];     // tf32 bits
__device__ uint32_t g_K [BL*DDIM];     // tf32 bits
__device__ uint32_t g_V [BL*DDIM];     // tf32 bits
__device__ uint32_t g_O [BL*DDIM];     // attention out (tf32 bits)
__device__ uint32_t g_F [BL*FFD];      // FFN hidden (tf32 bits)
// converted weights, TRANSPOSED to [n][k] (tf32 bits)
__device__ uint32_t g_Wq[NLAYER*DDIM*DDIM];
__device__ uint32_t g_Wk[NLAYER*DDIM*DDIM];
__device__ uint32_t g_Wv[NLAYER*DDIM*DDIM];
__device__ uint32_t g_Wo[NLAYER*DDIM*DDIM];
__device__ uint32_t g_W1[NLAYER*DDIM*FFD];
__device__ uint32_t g_W2[NLAYER*FFD*DDIM];

__device__ __forceinline__ uint32_t f2tf32(float x) {
    uint32_t r;
    asm("cvt.rna.tf32.f32 %0, %1;" : "=r"(r) : "f"(x));
    return r;
}
__device__ __forceinline__ void mma_tf32(float* c, const uint32_t* a, const uint32_t* b) {
    asm volatile(
        "mma.sync.aligned.m16n8k8.row.col.f32.tf32.tf32.f32 "
        "{%0,%1,%2,%3}, {%4,%5,%6,%7}, {%8,%9}, {%0,%1,%2,%3};"
        : "+f"(c[0]), "+f"(c[1]), "+f"(c[2]), "+f"(c[3])
        : "r"(a[0]), "r"(a[1]), "r"(a[2]), "r"(a[3]), "r"(b[0]), "r"(b[1]));
}
__device__ __forceinline__ void ldsm_x4(uint32_t* r, uint32_t addr) {
    asm volatile("ldmatrix.sync.aligned.m8n8.x4.shared.b16 {%0,%1,%2,%3}, [%4];"
        : "=r"(r[0]), "=r"(r[1]), "=r"(r[2]), "=r"(r[3]) : "r"(addr));
}
__device__ __forceinline__ uint32_t smem_u32(const void* p) {
    uint32_t a;
    asm("{ .reg .u64 t; cvta.to.shared.u64 t, %1; cvt.u32.u64 %0, t; }" : "=r"(a) : "l"(p));
    return a;
}
__device__ __forceinline__ void cp16(uint32_t s, const void* g) {
    asm volatile("cp.async.cg.shared.global [%0], [%1], 16;" :: "r"(s), "l"(g));
}
#define CP_COMMIT() asm volatile("cp.async.commit_group;" ::: "memory")
#define CP_WAIT1()  asm volatile("cp.async.wait_group 1;" ::: "memory")
#define BAR_PAIR(id) asm volatile("bar.sync %0, 64;" :: "r"(id) : "memory")

// ---------------- fused weight tf32 convert + TRANSPOSE ([k][n] -> [n][k]) ----------------
__global__ void cvtw_t(const float* __restrict__ wq, const float* __restrict__ wk,
                       const float* __restrict__ wv, const float* __restrict__ wo,
                       const float* __restrict__ w1, const float* __restrict__ w2) {
    __shared__ uint32_t t[32][33];
    int bid = blockIdx.x;
    const float* src;
    uint32_t* dst;
    int Kd, Nd, layer, tk, tn;
    if (bid < 1024) {
        int mat = bid >> 8, rem = bid & 255;
        layer = rem >> 6;
        int tile = rem & 63;
        tk = tile >> 3; tn = tile & 7;
        Kd = DDIM; Nd = DDIM;
        src = (mat == 0) ? wq : (mat == 1) ? wk : (mat == 2) ? wv : wo;
        dst = (mat == 0) ? g_Wq : (mat == 1) ? g_Wk : (mat == 2) ? g_Wv : g_Wo;
    } else if (bid < 2048) {
        int rem = bid - 1024;
        layer = rem >> 8;
        int tile = rem & 255;
        tk = tile >> 5; tn = tile & 31;
        Kd = DDIM; Nd = FFD;
        src = w1; dst = g_W1;
    } else {
        int rem = bid - 2048;
        layer = rem >> 8;
        int tile = rem & 255;
        tk = tile >> 3; tn = tile & 7;
        Kd = FFD; Nd = DDIM;
        src = w2; dst = g_W2;
    }
    src += (size_t)layer * Kd * Nd;
    dst += (size_t)layer * Kd * Nd;
    int k0 = tk * 32, n0 = tn * 32;
    int tx = threadIdx.x & 31, ty = threadIdx.x >> 5;
    #pragma unroll
    for (int j = 0; j < 4; j++)
        t[ty + 8 * j][tx] = f2tf32(src[(size_t)(k0 + ty + 8 * j) * Nd + n0 + tx]);
    __syncthreads();
    #pragma unroll
    for (int j = 0; j < 4; j++)
        dst[(size_t)(n0 + ty + 8 * j) * Kd + k0 + tx] = t[tx][ty + 8 * j];
}

// ---------------- embedding gather ----------------
__global__ void embed_kernel(const int* __restrict__ ids, const float* __restrict__ emb,
                             float* __restrict__ x) {
    int i = blockIdx.x * blockDim.x + threadIdx.x;
    int row = i >> 6;
    int d4  = i & 63;
    int id  = ids[row];
    ((float4*)x)[i] = ((const float4*)emb)[id * 64 + d4];
}

// ---------------- LayerNorm -> tf32 bits ----------------
__global__ void ln_kernel(const float* __restrict__ x, const float* __restrict__ g,
                          const float* __restrict__ b, uint32_t* __restrict__ outv) {
    int row  = blockIdx.x * 8 + (threadIdx.x >> 5);
    int lane = threadIdx.x & 31;
    const float4* xr = (const float4*)(x + (size_t)row * DDIM);
    float4 v0 = xr[lane];
    float4 v1 = xr[lane + 32];
    float s  = v0.x + v0.y + v0.z + v0.w + v1.x + v1.y + v1.z + v1.w;
    float ss = v0.x*v0.x + v0.y*v0.y + v0.z*v0.z + v0.w*v0.w
             + v1.x*v1.x + v1.y*v1.y + v1.z*v1.z + v1.w*v1.w;
    #pragma unroll
    for (int off = 16; off; off >>= 1) {
        s  += __shfl_xor_sync(0xffffffffu, s,  off);
        ss += __shfl_xor_sync(0xffffffffu, ss, off);
    }
    float mean = s * (1.0f / DDIM);
    float var  = ss * (1.0f / DDIM) - mean * mean;
    float rstd = rsqrtf(var + 1e-5f);
    const float4* gp = (const float4*)g;
    const float4* bp = (const float4*)b;
    float4 g0 = gp[lane], g1 = gp[lane + 32];
    float4 b0 = bp[lane], b1 = bp[lane + 32];
    uint4* op = (uint4*)(outv + (size_t)row * DDIM);
    uint4 t0, t1;
    t0.x = f2tf32((v0.x - mean) * rstd * g0.x + b0.x);
    t0.y = f2tf32((v0.y - mean) * rstd * g0.y + b0.y);
    t0.z = f2tf32((v0.z - mean) * rstd * g0.z + b0.z);
    t0.w = f2tf32((v0.w - mean) * rstd * g0.w + b0.w);
    t1.x = f2tf32((v1.x - mean) * rstd * g1.x + b1.x);
    t1.y = f2tf32((v1.y - mean) * rstd * g1.y + b1.y);
    t1.z = f2tf32((v1.z - mean) * rstd * g1.z + b1.z);
    t1.w = f2tf32((v1.w - mean) * rstd * g1.w + b1.w);
    op[lane] = t0;
    op[lane + 32] = t1;
}

__device__ __forceinline__ float gelu_tanh(float x) {
    float t = tanhf(0.7978845608028654f * (x + 0.044715f * x * x * x));
    return 0.5f * x * (1.0f + t);
}

// ================= tf32 GEMM core: 3-stage cp.async + ldmatrix fragments =================
#define AS_ST 36
#define ABUF (128*AS_ST)
#define STG_U32 (2*ABUF)
#define GSM_BYTES (3 * STG_U32 * 4)

template<bool GELU, bool RES, bool OUT32>
__device__ __forceinline__ void gemm_core(
        const uint32_t* __restrict__ A, const uint32_t* __restrict__ Wt,
        const float* __restrict__ bias, const float* __restrict__ Res,
        void* __restrict__ Cv, int N, int K, int m0, int n0, uint32_t* smu) {
    const uint32_t smb = smem_u32(smu);
    int tid = threadIdx.x, lane = tid & 31, wid = tid >> 5;
    int wm = wid & 3, wn = wid >> 2;
    int gid = lane >> 2, tig = lane & 3;

    int amm[4], akq[4];
    uint32_t adst[4];
    #pragma unroll
    for (int i = 0; i < 4; i++) {
        int idx = tid + i * 256;
        amm[i] = idx >> 3; akq[i] = idx & 7;
        adst[i] = (uint32_t)(amm[i] * AS_ST + akq[i] * 4) * 4;
    }

    int lr = lane & 7;
    uint32_t aoff[2], boff[4];
    {
        int a_row = (lane >> 3) & 1;
        int a_k   = (lane >> 4);
        #pragma unroll
        for (int tm = 0; tm < 2; tm++)
            aoff[tm] = (uint32_t)(((wm * 32 + tm * 16 + lr + a_row * 8) * AS_ST) + a_k * 4) * 4;
        int b_n = (lane >> 4);
        int b_k = (lane >> 3) & 1;
        #pragma unroll
        for (int p = 0; p < 4; p++)
            boff[p] = (uint32_t)(((wn * 64 + p * 16 + lr + b_n * 8) * AS_ST) + b_k * 4) * 4;
    }

    float acc[2][8][4];
    #pragma unroll
    for (int i = 0; i < 2; i++)
        #pragma unroll
        for (int j = 0; j < 8; j++)
            #pragma unroll
            for (int u = 0; u < 4; u++) acc[i][j][u] = 0.0f;

    int nch = K >> 5;
    #pragma unroll
    for (int st = 0; st < 2; st++) {
        uint32_t base = smb + st * STG_U32 * 4;
        int k0 = st << 5;
        #pragma unroll
        for (int i = 0; i < 4; i++) {
            cp16(base + adst[i], &A[(size_t)(m0 + amm[i]) * K + k0 + akq[i] * 4]);
            cp16(base + ABUF * 4 + adst[i], &Wt[(size_t)(n0 + amm[i]) * K + k0 + akq[i] * 4]);
        }
        CP_COMMIT();
    }

    int stage = 0;
    for (int kc = 0; kc < nch; kc++) {
        CP_WAIT1();
        __syncthreads();
        int pre = kc + 2;
        if (pre < nch) {
            int pst = pre % 3;
            uint32_t base = smb + pst * STG_U32 * 4;
            int k0 = pre << 5;
            #pragma unroll
            for (int i = 0; i < 4; i++) {
                cp16(base + adst[i], &A[(size_t)(m0 + amm[i]) * K + k0 + akq[i] * 4]);
                cp16(base + ABUF * 4 + adst[i], &Wt[(size_t)(n0 + amm[i]) * K + k0 + akq[i] * 4]);
            }
        }
        CP_COMMIT();

        uint32_t aBase = smb + stage * STG_U32 * 4;
        uint32_t bBase = aBase + ABUF * 4;
        #pragma unroll
        for (int ks = 0; ks < 4; ks++) {
            uint32_t kbb = ks * 32;
            uint32_t afr[2][4];
            ldsm_x4(afr[0], aBase + aoff[0] + kbb);
            ldsm_x4(afr[1], aBase + aoff[1] + kbb);
            uint32_t bfr[4][4];
            #pragma unroll
            for (int p = 0; p < 4; p++)
                ldsm_x4(bfr[p], bBase + boff[p] + kbb);
            #pragma unroll
            for (int tm = 0; tm < 2; tm++)
                #pragma unroll
                for (int p = 0; p < 4; p++) {
                    mma_tf32(acc[tm][2 * p],     afr[tm], &bfr[p][0]);
                    mma_tf32(acc[tm][2 * p + 1], afr[tm], &bfr[p][2]);
                }
        }
        stage = (stage + 1 == 3) ? 0 : stage + 1;
    }

    float* Cf = (float*)Cv;
    uint32_t* C32 = (uint32_t*)Cv;
    #pragma unroll
    for (int tm = 0; tm < 2; tm++) {
        int row = m0 + wm * 32 + tm * 16 + gid;
        #pragma unroll
        for (int tn = 0; tn < 8; tn++) {
            int col = n0 + wn * 64 + tn * 8 + tig * 2;
            float b0 = bias[col], b1 = bias[col + 1];
            #pragma unroll
            for (int half = 0; half < 2; half++) {
                int r = row + half * 8;
                float v0 = acc[tm][tn][half * 2 + 0] + b0;
                float v1 = acc[tm][tn][half * 2 + 1] + b1;
                if (GELU) { v0 = gelu_tanh(v0); v1 = gelu_tanh(v1); }
                size_t off = (size_t)r * N + col;
                if (RES) {
                    float2 rr = *(const float2*)&Res[off];
                    v0 += rr.x; v1 += rr.y;
                }
                if (OUT32) {
                    uint2 o = {f2tf32(v0), f2tf32(v1)};
                    *(uint2*)&C32[off] = o;
                } else {
                    float2 o = {v0, v1};
                    *(float2*)&Cf[off] = o;
                }
            }
        }
    }
}

template<bool GELU, bool RES, bool OUT32>
__global__ void __launch_bounds__(256, 2) gemm_cp(
        const uint32_t* __restrict__ A, const uint32_t* __restrict__ Wt,
        const float* __restrict__ bias, const float* __restrict__ Res,
        void* __restrict__ Cv, int N, int K) {
    extern __shared__ uint32_t smu[];
    gemm_core<GELU, RES, OUT32>(A, Wt, bias, Res, Cv, N, K,
                                blockIdx.y * 128, blockIdx.x * 128, smu);
}

// fused QKV: grid.x = 6 -> (mat 0..2) x (n-half 0..1)
__global__ void __launch_bounds__(256, 2) qkv_cp(
        const uint32_t* __restrict__ A,
        const uint32_t* __restrict__ Wq, const uint32_t* __restrict__ Wk, const uint32_t* __restrict__ Wv,
        const float* __restrict__ bq, const float* __restrict__ bk, const float* __restrict__ bv,
        uint32_t* __restrict__ Q, uint32_t* __restrict__ K, uint32_t* __restrict__ V) {
    extern __shared__ uint32_t smu[];
    int mat = blockIdx.x >> 1;
    const uint32_t* W = (mat == 0) ? Wq : (mat == 1) ? Wk : Wv;
    const float* bias = (mat == 0) ? bq : (mat == 1) ? bk : bv;
    uint32_t* C = (mat == 0) ? Q : (mat == 1) ? K : V;
    gemm_core<false, false, true>(A, W, bias, nullptr, C, DDIM, DDIM,
                                  blockIdx.y * 128, (blockIdx.x & 1) * 128, smu);
}

// ---------------- fused attention: no-max softmax (exp direct), deferred l-reduction ----------------
#define QS_ST 68
#define KS_ST 68
#define VS_ST 72
#define SS_ST 68
#define ATSM_U32 (64*QS_ST + 64*KS_ST + 64*VS_ST + 64*SS_ST + 64)
#define ATSM_BYTES (ATSM_U32 * 4)

__global__ void attn_kernel(const uint32_t* __restrict__ Q, const uint32_t* __restrict__ K,
                            const uint32_t* __restrict__ V, uint32_t* __restrict__ O) {
    extern __shared__ uint32_t smu[];
    uint32_t* qsm = smu;                        // [64][68]
    uint32_t* ksm = qsm + 64 * QS_ST;           // [64][68] rows = keys
    uint32_t* vsm = ksm + 64 * KS_ST;           // [64][72] rows = keys
    uint32_t* ssm = vsm + 64 * VS_ST;           // [64][68] float scores -> tf32 P bits
    float*    lsm = (float*)(ssm + 64 * SS_ST); // [64] l

    int qt   = blockIdx.x;
    int head = blockIdx.y;
    int bn   = blockIdx.z;
    int b    = bn / NBLK;
    int nb   = bn % NBLK;
    int q0   = qt * 64;
    int tid  = threadIdx.x;
    int lane = tid & 31;
    int warp = tid >> 5;
    int wq4 = warp & 3, wk2 = warp >> 2;
    int gid = lane >> 2, tig = lane & 3;
    int barid = 1 + wq4;

    const uint32_t* Qbase = Q + ((size_t)(b * LL + nb * WW + q0)) * DDIM + head * DH;
    #pragma unroll
    for (int i = 0; i < 4; i++) {
        int idx = tid + i * 256;
        int qi = idx >> 4, d4 = idx & 15;
        *(uint4*)&qsm[qi * QS_ST + d4 * 4] = *(const uint4*)&Qbase[(size_t)qi * DDIM + d4 * 4];
    }

    float l[8];
    #pragma unroll
    for (int i = 0; i < 8; i++) l[i] = 0.0f;
    float ofr[4][4];
    #pragma unroll
    for (int t = 0; t < 4; t++)
        #pragma unroll
        for (int u = 0; u < 4; u++) ofr[t][u] = 0.0f;

    int lo = q0;
    if (nb == 0) lo = (lo > WW) ? lo : WW;
    int hi = q0 + 63 + WW;
    int cmin = lo >> 6, cmax = hi >> 6;

    float slope = exp2f(-2.0f * (float)(head + 1));
    const float scale = 0.125f;
    int kvbase = b * LL + nb * WW - WW;

    for (int c = cmin; c <= cmax; c++) {
        int kc0 = c * 64;
        __syncthreads();
        #pragma unroll
        for (int i = 0; i < 4; i++) {
            int idx = tid + i * 256;
            int kk = idx >> 4, d4 = idx & 15;
            size_t gro = ((size_t)(kvbase + kc0 + kk)) * DDIM + head * DH + d4 * 4;
            *(uint4*)&ksm[kk * KS_ST + d4 * 4] = *(const uint4*)&K[gro];
            *(uint4*)&vsm[kk * VS_ST + d4 * 4] = *(const uint4*)&V[gro];
        }
        __syncthreads();

        // S = Q @ K^T: warp computes rows [16*wq4,+16) x keys [32*wk2,+32)
        float cfr[4][4];
        #pragma unroll
        for (int t = 0; t < 4; t++)
            #pragma unroll
            for (int u = 0; u < 4; u++) cfr[t][u] = 0.0f;
        #pragma unroll
        for (int ks = 0; ks < 8; ks++) {
            int kb = ks * 8;
            int r0 = (wq4 * 16 + gid) * QS_ST + kb + tig;
            uint32_t af[4];
            af[0] = qsm[r0];
            af[1] = qsm[r0 + 8 * QS_ST];
            af[2] = qsm[r0 + 4];
            af[3] = qsm[r0 + 8 * QS_ST + 4];
            #pragma unroll
            for (int t = 0; t < 4; t++) {
                int col = wk2 * 32 + t * 8 + gid;
                uint32_t bf[2];
                bf[0] = ksm[col * KS_ST + kb + tig];
                bf[1] = ksm[col * KS_ST + kb + tig + 4];
                mma_tf32(cfr[t], af, bf);
            }
        }
        #pragma unroll
        for (int t = 0; t < 4; t++) {
            int klocal = wk2 * 32 + t * 8 + 2 * tig;
            int ka = kc0 + klocal, kb2 = ka + 1;
            #pragma unroll
            for (int half = 0; half < 2; half++) {
                int rloc = wq4 * 16 + gid + half * 8;
                int qg = q0 + rloc;
                bool oka = (ka >= qg) && (ka <= qg + WW) && (nb > 0 || ka >= WW);
                bool okb = (kb2 >= qg) && (kb2 <= qg + WW) && (nb > 0 || kb2 >= WW);
                float da = (float)(WW + qg - ka);
                float db = (float)(WW + qg - kb2);
                float sa = cfr[t][half * 2 + 0];
                float sb = cfr[t][half * 2 + 1];
                sa = oka ? (sa * scale - slope * da) : -1e30f;
                sb = okb ? (sb * scale - slope * db) : -1e30f;
                float2 st = {sa, sb};
                *(float2*)&((float*)ssm)[rloc * SS_ST + klocal] = st;
            }
        }
        BAR_PAIR(barid);

        // softmax without max-shift: p = exp(s) (underflows to 0 when masked);
        // l accumulated lane-locally, reduced once after the chunk loop.
        #pragma unroll
        for (int qi = 0; qi < 8; qi++) {
            int q = wq4 * 16 + wk2 * 8 + qi;
            float s0 = ((float*)ssm)[q * SS_ST + lane];
            float s1 = ((float*)ssm)[q * SS_ST + lane + 32];
            float p0 = __expf(s0);
            float p1 = __expf(s1);
            l[qi] += p0 + p1;
            ssm[q * SS_ST + lane] = f2tf32(p0);
            ssm[q * SS_ST + lane + 32] = f2tf32(p1);
        }
        BAR_PAIR(barid);

        // o += P @ V
        #pragma unroll
        for (int ks = 0; ks < 8; ks++) {
            int kb = ks * 8;
            int r0 = (wq4 * 16 + gid) * SS_ST + kb + tig;
            uint32_t af[4];
            af[0] = ssm[r0];
            af[1] = ssm[r0 + 8 * SS_ST];
            af[2] = ssm[r0 + 4];
            af[3] = ssm[r0 + 8 * SS_ST + 4];
            #pragma unroll
            for (int t = 0; t < 4; t++) {
                int col = wk2 * 32 + t * 8 + gid;
                uint32_t bf[2];
                bf[0] = vsm[(kb + tig) * VS_ST + col];
                bf[1] = vsm[(kb + tig + 4) * VS_ST + col];
                mma_tf32(ofr[t], af, bf);
            }
        }
    }

    // final l reduction (once) and store
    #pragma unroll
    for (int qi = 0; qi < 8; qi++) {
        float ls = l[qi];
        #pragma unroll
        for (int off = 16; off; off >>= 1)
            ls += __shfl_xor_sync(0xffffffffu, ls, off);
        if (lane == 0) lsm[wq4 * 16 + wk2 * 8 + qi] = ls;
    }
    BAR_PAIR(barid);

    float ia = 1.0f / lsm[wq4 * 16 + gid];
    float ib = 1.0f / lsm[wq4 * 16 + gid + 8];
    size_t rowa = (size_t)(b * LL + nb * WW + q0 + wq4 * 16 + gid) * DDIM + head * DH;
    size_t rowb = rowa + 8 * DDIM;
    #pragma unroll
    for (int t = 0; t < 4; t++) {
        int col = wk2 * 32 + t * 8 + 2 * tig;
        uint2 oa = {f2tf32(ofr[t][0] * ia), f2tf32(ofr[t][1] * ia)};
        uint2 ob = {f2tf32(ofr[t][2] * ib), f2tf32(ofr[t][3] * ib)};
        *(uint2*)&O[rowa + col] = oa;
        *(uint2*)&O[rowb + col] = ob;
    }
}

// ---------------- head with fused final LayerNorm: warp per row, N=14 ----------------
__global__ void head_kernel(const float* __restrict__ x, const float* __restrict__ g,
                            const float* __restrict__ bb, const float* __restrict__ w,
                            float* __restrict__ out) {
    int row  = blockIdx.x * 8 + (threadIdx.x >> 5);
    int lane = threadIdx.x & 31;
    const float4* xr = (const float4*)(x + (size_t)row * DDIM);
    float4 v0 = xr[lane];
    float4 v1 = xr[lane + 32];
    float s  = v0.x + v0.y + v0.z + v0.w + v1.x + v1.y + v1.z + v1.w;
    float ss = v0.x*v0.x + v0.y*v0.y + v0.z*v0.z + v0.w*v0.w
             + v1.x*v1.x + v1.y*v1.y + v1.z*v1.z + v1.w*v1.w;
    #pragma unroll
    for (int off = 16; off; off >>= 1) {
        s  += __shfl_xor_sync(0xffffffffu, s,  off);
        ss += __shfl_xor_sync(0xffffffffu, ss, off);
    }
    float mean = s * (1.0f / DDIM);
    float var  = ss * (1.0f / DDIM) - mean * mean;
    float rstd = rsqrtf(var + 1e-5f);
    const float4* gp = (const float4*)g;
    const float4* bp = (const float4*)bb;
    float4 g0 = gp[lane], g1 = gp[lane + 32];
    float4 b0 = bp[lane], b1 = bp[lane + 32];
    float h[8];
    h[0] = (v0.x - mean) * rstd * g0.x + b0.x;
    h[1] = (v0.y - mean) * rstd * g0.y + b0.y;
    h[2] = (v0.z - mean) * rstd * g0.z + b0.z;
    h[3] = (v0.w - mean) * rstd * g0.w + b0.w;
    h[4] = (v1.x - mean) * rstd * g1.x + b1.x;
    h[5] = (v1.y - mean) * rstd * g1.y + b1.y;
    h[6] = (v1.z - mean) * rstd * g1.z + b1.z;
    h[7] = (v1.w - mean) * rstd * g1.w + b1.w;

    float acc[VV];
    #pragma unroll
    for (int c = 0; c < VV; c++) acc[c] = 0.0f;
    #pragma unroll
    for (int u = 0; u < 8; u++) {
        int d = (u < 4) ? (lane * 4 + u) : (128 + lane * 4 + (u - 4));
        const float* wr = w + d * VV;
        #pragma unroll
        for (int c = 0; c < VV; c++) acc[c] = fmaf(h[u], wr[c], acc[c]);
    }
    #pragma unroll
    for (int c = 0; c < VV; c++)
        #pragma unroll
        for (int off = 16; off; off >>= 1)
            acc[c] += __shfl_xor_sync(0xffffffffu, acc[c], off);
    if (lane < VV) out[(size_t)row * VV + lane] = acc[lane];
}

// ---------------- launch ----------------
extern "C" void kernel_launch(void* const* d_in, const int* in_sizes, int n_in,
                              void* d_out, int out_size) {
    const int*   byte_ids = (const int*)  d_in[0];
    const float* embed    = (const float*)d_in[1];
    const float* wq   = (const float*)d_in[2];
    const float* bq   = (const float*)d_in[3];
    const float* wk   = (const float*)d_in[4];
    const float* bk   = (const float*)d_in[5];
    const float* wv   = (const float*)d_in[6];
    const float* bv   = (const float*)d_in[7];
    const float* wo   = (const float*)d_in[8];
    const float* bo   = (const float*)d_in[9];
    const float* ln1g = (const float*)d_in[10];
    const float* ln1b = (const float*)d_in[11];
    const float* ln2g = (const float*)d_in[12];
    const float* ln2b = (const float*)d_in[13];
    const float* w1   = (const float*)d_in[14];
    const float* b1   = (const float*)d_in[15];
    const float* w2   = (const float*)d_in[16];
    const float* b2   = (const float*)d_in[17];
    const float* lnfg = (const float*)d_in[18];
    const float* lnfb = (const float*)d_in[19];
    const float* headw= (const float*)d_in[20];
    float* out = (float*)d_out;

    float *X;
    uint32_t *Hb, *Q, *K, *Vb, *O, *F;
    uint32_t *Wq, *Wk, *Wv, *Wo, *W1, *W2;
    cudaGetSymbolAddress((void**)&X,  g_X);
    cudaGetSymbolAddress((void**)&Hb, g_Hb);
    cudaGetSymbolAddress((void**)&Q,  g_Q);
    cudaGetSymbolAddress((void**)&K,  g_K);
    cudaGetSymbolAddress((void**)&Vb, g_V);
    cudaGetSymbolAddress((void**)&O,  g_O);
    cudaGetSymbolAddress((void**)&F,  g_F);
    cudaGetSymbolAddress((void**)&Wq, g_Wq);
    cudaGetSymbolAddress((void**)&Wk, g_Wk);
    cudaGetSymbolAddress((void**)&Wv, g_Wv);
    cudaGetSymbolAddress((void**)&Wo, g_Wo);
    cudaGetSymbolAddress((void**)&W1, g_W1);
    cudaGetSymbolAddress((void**)&W2, g_W2);

    cudaFuncSetAttribute(attn_kernel, cudaFuncAttributeMaxDynamicSharedMemorySize, ATSM_BYTES);
    cudaFuncSetAttribute(qkv_cp, cudaFuncAttributeMaxDynamicSharedMemorySize, GSM_BYTES);
    cudaFuncSetAttribute(gemm_cp<false,true ,false>, cudaFuncAttributeMaxDynamicSharedMemorySize, GSM_BYTES);
    cudaFuncSetAttribute(gemm_cp<true ,false,true >, cudaFuncAttributeMaxDynamicSharedMemorySize, GSM_BYTES);

    cvtw_t<<<3072, 256>>>(wq, wk, wv, wo, w1, w2);

    embed_kernel<<<BL * 64 / 256, 256>>>(byte_ids, embed, X);

    dim3 gQKV(6, BL / 128);
    dim3 gD(DDIM / 128, BL / 128);
    dim3 gF(FFD / 128,  BL / 128);
    dim3 gA(8, HH, BB * NBLK);
    const size_t SMB = GSM_BYTES;

    for (int l = 0; l < NLAYER; l++) {
        ln_kernel<<<BL / 8, 256>>>(X, ln1g + l * DDIM, ln1b + l * DDIM, Hb);
        qkv_cp<<<gQKV, 256, SMB>>>(Hb,
            Wq + (size_t)l * DDIM * DDIM, Wk + (size_t)l * DDIM * DDIM, Wv + (size_t)l * DDIM * DDIM,
            bq + l * DDIM, bk + l * DDIM, bv + l * DDIM, Q, K, Vb);
        attn_kernel<<<gA, 256, ATSM_BYTES>>>(Q, K, Vb, O);
        gemm_cp<false, true , false><<<gD, 256, SMB>>>(O, Wo + (size_t)l * DDIM * DDIM, bo + l * DDIM, X, X, DDIM, DDIM);
        ln_kernel<<<BL / 8, 256>>>(X, ln2g + l * DDIM, ln2b + l * DDIM, Hb);
        gemm_cp<true , false, true ><<<gF, 256, SMB>>>(Hb, W1 + (size_t)l * DDIM * FFD, b1 + l * FFD, nullptr, F, FFD, DDIM);
        gemm_cp<false, true , false><<<gD, 256, SMB>>>(F, W2 + (size_t)l * FFD * DDIM, b2 + l * DDIM, X, X, DDIM, FFD);
    }
    head_kernel<<<BL / 8, 256>>>(X, lnfg, lnfb, headw, out);
}